// round 4
// baseline (speedup 1.0000x reference)
#include <cuda_runtime.h>
#include <cuda_bf16.h>
#include <stdint.h>
#include <math.h>

#define H_SIZE 2048
#define INTER_SZ 8192
#define NQ 16
#define NKV 8
#define HD 128
#define SEQ 2048
#define BATCH 2
#define NROWS (BATCH*SEQ)
#define WIN 1024

// ---------------- fp32 scratch ----------------
__device__ float g_q[NROWS*H_SIZE];
__device__ float g_k[NROWS*NKV*HD];
__device__ float g_v[NROWS*NKV*HD];
__device__ float g_attnout[NROWS*H_SIZE];
__device__ float g_h2[NROWS*H_SIZE];
__device__ float g_gate[NROWS*INTER_SZ];
__device__ float g_up[NROWS*INTER_SZ];
__device__ float g_ffnout[NROWS*H_SIZE];

// ---------------- bf16 hi/lo planes ----------------
// activations
__device__ __nv_bfloat16 g_h_h[NROWS*H_SIZE],      g_h_l[NROWS*H_SIZE];
__device__ __nv_bfloat16 g_attn_h[NROWS*H_SIZE],   g_attn_l[NROWS*H_SIZE];
__device__ __nv_bfloat16 g_ffnin_h[NROWS*H_SIZE],  g_ffnin_l[NROWS*H_SIZE];
__device__ __nv_bfloat16 g_gact_h[NROWS*INTER_SZ], g_gact_l[NROWS*INTER_SZ];
// weights
__device__ __nv_bfloat16 g_wq_h[H_SIZE*H_SIZE],    g_wq_l[H_SIZE*H_SIZE];
__device__ __nv_bfloat16 g_wk_h[NKV*HD*H_SIZE],    g_wk_l[NKV*HD*H_SIZE];
__device__ __nv_bfloat16 g_wv_h[NKV*HD*H_SIZE],    g_wv_l[NKV*HD*H_SIZE];
__device__ __nv_bfloat16 g_wo_h[H_SIZE*H_SIZE],    g_wo_l[H_SIZE*H_SIZE];
__device__ __nv_bfloat16 g_wg_h[INTER_SZ*H_SIZE],  g_wg_l[INTER_SZ*H_SIZE];
__device__ __nv_bfloat16 g_wu_h[INTER_SZ*H_SIZE],  g_wu_l[INTER_SZ*H_SIZE];
__device__ __nv_bfloat16 g_wd_h[H_SIZE*INTER_SZ],  g_wd_l[H_SIZE*INTER_SZ];

// ---------------- helpers ----------------
__device__ __forceinline__ void split2(float a, float b, __nv_bfloat16* hi, __nv_bfloat16* lo) {
    __nv_bfloat16 ha = __float2bfloat16(a), hb = __float2bfloat16(b);
    __nv_bfloat16 la = __float2bfloat16(a - __bfloat162float(ha));
    __nv_bfloat16 lb = __float2bfloat16(b - __bfloat162float(hb));
    *(__nv_bfloat162*)hi = __halves2bfloat162(ha, hb);
    *(__nv_bfloat162*)lo = __halves2bfloat162(la, lb);
}

// ---------------- weight split: fp32 -> hi/lo planes ----------------
__global__ __launch_bounds__(256) void split_kernel(
    const float* __restrict__ in, __nv_bfloat16* __restrict__ hi,
    __nv_bfloat16* __restrict__ lo, int n4)
{
    int i = blockIdx.x * blockDim.x + threadIdx.x;
    int stride = gridDim.x * blockDim.x;
    for (; i < n4; i += stride) {
        float4 v = ((const float4*)in)[i];
        split2(v.x, v.y, hi + i*4,     lo + i*4);
        split2(v.z, v.w, hi + i*4 + 2, lo + i*4 + 2);
    }
}

// ---------------- RMSNorm fp32 out (mode 1: res+norm; 2: (res+norm)*scalar) -------------
__global__ __launch_bounds__(256) void rmsnorm_kernel(
    const float* __restrict__ in, const float* __restrict__ w,
    const float* __restrict__ res, const float* __restrict__ scal,
    float* __restrict__ out, int mode)
{
    int row = blockIdx.x;
    int t = threadIdx.x;
    const float4* ip = (const float4*)(in + (size_t)row * H_SIZE);
    float4 v0 = ip[t];
    float4 v1 = ip[t + 256];
    float ss = v0.x*v0.x + v0.y*v0.y + v0.z*v0.z + v0.w*v0.w
             + v1.x*v1.x + v1.y*v1.y + v1.z*v1.z + v1.w*v1.w;
    #pragma unroll
    for (int o = 16; o; o >>= 1) ss += __shfl_xor_sync(0xffffffffu, ss, o);
    __shared__ float red[8];
    if ((t & 31) == 0) red[t >> 5] = ss;
    __syncthreads();
    float tot = red[0]+red[1]+red[2]+red[3]+red[4]+red[5]+red[6]+red[7];
    float inv = rsqrtf(tot * (1.0f / H_SIZE) + 1e-6f);

    const float4* w4 = (const float4*)w;
    float4 w0 = w4[t], w1 = w4[t + 256];
    float4 o0, o1;
    o0.x = v0.x*inv*w0.x; o0.y = v0.y*inv*w0.y; o0.z = v0.z*inv*w0.z; o0.w = v0.w*inv*w0.w;
    o1.x = v1.x*inv*w1.x; o1.y = v1.y*inv*w1.y; o1.z = v1.z*inv*w1.z; o1.w = v1.w*inv*w1.w;
    if (mode >= 1) {
        const float4* rp = (const float4*)(res + (size_t)row * H_SIZE);
        float4 r0 = rp[t], r1 = rp[t + 256];
        o0.x += r0.x; o0.y += r0.y; o0.z += r0.z; o0.w += r0.w;
        o1.x += r1.x; o1.y += r1.y; o1.z += r1.z; o1.w += r1.w;
    }
    if (mode == 2) {
        float sc = scal[0];
        o0.x *= sc; o0.y *= sc; o0.z *= sc; o0.w *= sc;
        o1.x *= sc; o1.y *= sc; o1.z *= sc; o1.w *= sc;
    }
    float4* op = (float4*)(out + (size_t)row * H_SIZE);
    op[t] = o0;
    op[t + 256] = o1;
}

// ---------------- RMSNorm -> bf16 hi/lo planes ----------------
__global__ __launch_bounds__(256) void rmsnorm_split_kernel(
    const float* __restrict__ in, const float* __restrict__ w,
    __nv_bfloat16* __restrict__ oh, __nv_bfloat16* __restrict__ ol)
{
    int row = blockIdx.x;
    int t = threadIdx.x;
    const float4* ip = (const float4*)(in + (size_t)row * H_SIZE);
    float4 v0 = ip[t];
    float4 v1 = ip[t + 256];
    float ss = v0.x*v0.x + v0.y*v0.y + v0.z*v0.z + v0.w*v0.w
             + v1.x*v1.x + v1.y*v1.y + v1.z*v1.z + v1.w*v1.w;
    #pragma unroll
    for (int o = 16; o; o >>= 1) ss += __shfl_xor_sync(0xffffffffu, ss, o);
    __shared__ float red[8];
    if ((t & 31) == 0) red[t >> 5] = ss;
    __syncthreads();
    float tot = red[0]+red[1]+red[2]+red[3]+red[4]+red[5]+red[6]+red[7];
    float inv = rsqrtf(tot * (1.0f / H_SIZE) + 1e-6f);

    const float4* w4 = (const float4*)w;
    float4 w0 = w4[t], w1 = w4[t + 256];
    float a0 = v0.x*inv*w0.x, a1 = v0.y*inv*w0.y, a2 = v0.z*inv*w0.z, a3 = v0.w*inv*w0.w;
    float b0 = v1.x*inv*w1.x, b1 = v1.y*inv*w1.y, b2 = v1.z*inv*w1.z, b3 = v1.w*inv*w1.w;
    size_t base = (size_t)row * H_SIZE;
    split2(a0, a1, oh + base + t*4,         ol + base + t*4);
    split2(a2, a3, oh + base + t*4 + 2,     ol + base + t*4 + 2);
    split2(b0, b1, oh + base + 1024 + t*4,     ol + base + 1024 + t*4);
    split2(b2, b3, oh + base + 1024 + t*4 + 2, ol + base + 1024 + t*4 + 2);
}

// ---------------- Tensor-core GEMM on bf16 hi/lo planes, cp.async double buffered --------
// C[M,N] = (Ah+Al)[M,K] * (Bh+Bl)[N,K]^T, 3 passes: AhBh + AhBl + AlBh.
// 128x128 block, BK=32, 256 threads = 8 warps (2m x 4n), warp tile 64x32.

#define LDSK 40
#define PLANE_HALFS (128*LDSK)
#define STAGE_HALFS (4*PLANE_HALFS)

__device__ __forceinline__ void mma_bf16(float* c, const uint32_t* a, const uint32_t* b) {
    asm volatile(
        "mma.sync.aligned.m16n8k16.row.col.f32.bf16.bf16.f32 "
        "{%0,%1,%2,%3}, {%4,%5,%6,%7}, {%8,%9}, {%0,%1,%2,%3};\n"
        : "+f"(c[0]), "+f"(c[1]), "+f"(c[2]), "+f"(c[3])
        : "r"(a[0]), "r"(a[1]), "r"(a[2]), "r"(a[3]), "r"(b[0]), "r"(b[1]));
}

__device__ __forceinline__ void cp16(uint32_t dst_smem, const void* src) {
    asm volatile("cp.async.cg.shared.global [%0], [%1], 16;\n" :: "r"(dst_smem), "l"(src));
}

__global__ __launch_bounds__(256) void gemm_planes(
    const __nv_bfloat16* __restrict__ Ah, const __nv_bfloat16* __restrict__ Al,
    const __nv_bfloat16* __restrict__ Bh, const __nv_bfloat16* __restrict__ Bl,
    float* __restrict__ C, int M, int N, int K)
{
    extern __shared__ __align__(16) __nv_bfloat16 smp[];  // [2][4][128*LDSK]

    const int tid  = threadIdx.x;
    const int warp = tid >> 5, lane = tid & 31;
    const int wm = warp >> 2, wn = warp & 3;
    const int g = lane >> 2, t = lane & 3;

    const __nv_bfloat16* gp0 = Ah + (size_t)blockIdx.y * 128 * K;
    const __nv_bfloat16* gp1 = Al + (size_t)blockIdx.y * 128 * K;
    const __nv_bfloat16* gp2 = Bh + (size_t)blockIdx.x * 128 * K;
    const __nv_bfloat16* gp3 = Bl + (size_t)blockIdx.x * 128 * K;

    uint32_t smbase = (uint32_t)__cvta_generic_to_shared(smp);

    float acc[4][4][4];
    #pragma unroll
    for (int i = 0; i < 4; i++)
        #pragma unroll
        for (int j = 0; j < 4; j++)
            #pragma unroll
            for (int q = 0; q < 4; q++) acc[i][j][q] = 0.f;

    // per-thread: 8 chunks of 16B per stage. cidx: plane = >>9, row = (c>>2), chunk = c&3.
    #define ISSUE_STAGE(s, k0)                                                      \
    {                                                                               \
        _Pragma("unroll")                                                           \
        for (int i = 0; i < 8; i++) {                                               \
            int cidx = tid + 256 * i;                                               \
            int plane = cidx >> 9;                                                  \
            int cc = cidx & 511;                                                    \
            int row = cc >> 2;                                                      \
            int ch = cc & 3;                                                        \
            const __nv_bfloat16* src =                                              \
                (plane == 0 ? gp0 : plane == 1 ? gp1 : plane == 2 ? gp2 : gp3)      \
                + (size_t)row * K + (k0) + ch * 8;                                  \
            uint32_t dst = smbase +                                                 \
                (((s)*4 + plane) * PLANE_HALFS + row * LDSK + ch * 8) * 2;          \
            cp16(dst, src);                                                         \
        }                                                                           \
        asm volatile("cp.async.commit_group;\n");                                   \
    }

    ISSUE_STAGE(0, 0);
    int s = 0;
    for (int k0 = 0; k0 < K; k0 += 32) {
        if (k0 + 32 < K) {
            ISSUE_STAGE(s ^ 1, k0 + 32);
            asm volatile("cp.async.wait_group 1;\n");
        } else {
            asm volatile("cp.async.wait_group 0;\n");
        }
        __syncthreads();

        const __nv_bfloat16* Ahs = smp + (s*4 + 0) * PLANE_HALFS;
        const __nv_bfloat16* Als = smp + (s*4 + 1) * PLANE_HALFS;
        const __nv_bfloat16* Bhs = smp + (s*4 + 2) * PLANE_HALFS;
        const __nv_bfloat16* Bls = smp + (s*4 + 3) * PLANE_HALFS;

        #pragma unroll
        for (int kk = 0; kk < 32; kk += 16) {
            uint32_t fa[4][4], fb[4][2];
            #pragma unroll
            for (int tm = 0; tm < 4; tm++) {
                int r0 = (wm*64 + tm*16 + g) * LDSK + kk + 2*t;
                int r1 = r0 + 8*LDSK;
                fa[tm][0] = *(const uint32_t*)(Ahs + r0);
                fa[tm][1] = *(const uint32_t*)(Ahs + r1);
                fa[tm][2] = *(const uint32_t*)(Ahs + r0 + 8);
                fa[tm][3] = *(const uint32_t*)(Ahs + r1 + 8);
            }
            #pragma unroll
            for (int tn = 0; tn < 4; tn++) {
                int r = (wn*32 + tn*8 + g) * LDSK + kk + 2*t;
                fb[tn][0] = *(const uint32_t*)(Bhs + r);
                fb[tn][1] = *(const uint32_t*)(Bhs + r + 8);
            }
            #pragma unroll
            for (int tm = 0; tm < 4; tm++)
                #pragma unroll
                for (int tn = 0; tn < 4; tn++)
                    mma_bf16(acc[tm][tn], fa[tm], fb[tn]);
            {
                uint32_t fbl[4][2];
                #pragma unroll
                for (int tn = 0; tn < 4; tn++) {
                    int r = (wn*32 + tn*8 + g) * LDSK + kk + 2*t;
                    fbl[tn][0] = *(const uint32_t*)(Bls + r);
                    fbl[tn][1] = *(const uint32_t*)(Bls + r + 8);
                }
                #pragma unroll
                for (int tm = 0; tm < 4; tm++)
                    #pragma unroll
                    for (int tn = 0; tn < 4; tn++)
                        mma_bf16(acc[tm][tn], fa[tm], fbl[tn]);
            }
            {
                uint32_t fal[4][4];
                #pragma unroll
                for (int tm = 0; tm < 4; tm++) {
                    int r0 = (wm*64 + tm*16 + g) * LDSK + kk + 2*t;
                    int r1 = r0 + 8*LDSK;
                    fal[tm][0] = *(const uint32_t*)(Als + r0);
                    fal[tm][1] = *(const uint32_t*)(Als + r1);
                    fal[tm][2] = *(const uint32_t*)(Als + r0 + 8);
                    fal[tm][3] = *(const uint32_t*)(Als + r1 + 8);
                }
                #pragma unroll
                for (int tm = 0; tm < 4; tm++)
                    #pragma unroll
                    for (int tn = 0; tn < 4; tn++)
                        mma_bf16(acc[tm][tn], fal[tm], fb[tn]);
            }
        }
        __syncthreads();
        s ^= 1;
    }

    #pragma unroll
    for (int tm = 0; tm < 4; tm++) {
        #pragma unroll
        for (int tn = 0; tn < 4; tn++) {
            int row = blockIdx.y*128 + wm*64 + tm*16 + g;
            int col = blockIdx.x*128 + wn*32 + tn*8 + 2*t;
            float2 c0 = {acc[tm][tn][0], acc[tm][tn][1]};
            float2 c1 = {acc[tm][tn][2], acc[tm][tn][3]};
            *(float2*)(C + (size_t)row * N + col)       = c0;
            *(float2*)(C + (size_t)(row + 8) * N + col) = c1;
        }
    }
}

// ---------------- RoPE (in-place on [NROWS, nheads*128]) --------------------------------
__global__ __launch_bounds__(256) void rope_kernel(float* __restrict__ buf, int nheads)
{
    int row = blockIdx.x;
    int s = row & (SEQ - 1);
    float* base = buf + (size_t)row * nheads * HD;
    for (int idx = threadIdx.x; idx < nheads * 64; idx += blockDim.x) {
        int hh = idx >> 6;
        int d = idx & 63;
        float inv = expf(-((float)d * (1.0f / 64.0f)) * 9.210340371976184f);
        float fr = (float)s * inv;
        float sn = sinf(fr), cs = cosf(fr);
        float* p = base + hh * HD + d;
        float x1 = p[0], x2 = p[64];
        p[0]  = x1 * cs - x2 * sn;
        p[64] = x2 * cs + x1 * sn;
    }
}

// ---------------- Sliding-window GQA flash attention (out: bf16 hi/lo planes) ------------
#define QSTR 132
#define PSTR 36
#define ATTN_SMEM_FLOATS (64*QSTR + 32*QSTR + 32*QSTR + 64*PSTR)

__global__ __launch_bounds__(256) void attn_kernel(
    const float* __restrict__ Q, const float* __restrict__ K,
    const float* __restrict__ V, __nv_bfloat16* __restrict__ Oh,
    __nv_bfloat16* __restrict__ Ol)
{
    extern __shared__ float sm[];
    float* Qs = sm;
    float* Ks = sm + 64 * QSTR;
    float* Vs = Ks + 32 * QSTR;
    float* Ps = Vs + 32 * QSTR;

    const int i0 = blockIdx.x * 64;
    const int h  = blockIdx.y;
    const int b  = blockIdx.z;
    const int hk = h >> 1;
    const int tid = threadIdx.x;
    const int r = tid >> 2, c = tid & 3;
    const float scale = 0.08838834764831845f;

    #pragma unroll
    for (int it = 0; it < 8; it++) {
        int idx = tid + 256 * it;
        int rr = idx >> 5, d4 = idx & 31;
        float4 qv = *(const float4*)(Q + ((size_t)(b * SEQ + i0 + rr) * H_SIZE + h * HD + d4 * 4));
        float4 qs = {qv.x * scale, qv.y * scale, qv.z * scale, qv.w * scale};
        *(float4*)&Qs[rr * QSTR + d4 * 4] = qs;
    }

    float m = -1e30f, l = 0.f;
    float4 o[8];
    #pragma unroll
    for (int t8 = 0; t8 < 8; t8++) o[t8] = make_float4(0.f, 0.f, 0.f, 0.f);

    int jstart = i0 - (WIN - 1);
    if (jstart < 0) jstart = 0;
    jstart &= ~31;
    const int iq = i0 + r;
    const float* qrow = Qs + r * QSTR;

    for (int j0 = jstart; j0 < i0 + 64; j0 += 32) {
        __syncthreads();
        #pragma unroll
        for (int it = 0; it < 4; it++) {
            int idx = tid + 256 * it;
            int rr = idx >> 5, d4 = idx & 31;
            size_t goff = (size_t)(b * SEQ + j0 + rr) * (NKV * HD) + hk * HD + d4 * 4;
            *(float4*)&Ks[rr * QSTR + d4 * 4] = *(const float4*)(K + goff);
            *(float4*)&Vs[rr * QSTR + d4 * 4] = *(const float4*)(V + goff);
        }
        __syncthreads();

        float s[8];
        #pragma unroll
        for (int u = 0; u < 8; u++) s[u] = 0.f;
        #pragma unroll 4
        for (int d4 = 0; d4 < 32; d4++) {
            float4 qv = *(const float4*)(qrow + d4 * 4);
            #pragma unroll
            for (int u = 0; u < 8; u++) {
                float4 kv = *(const float4*)&Ks[(c + 4 * u) * QSTR + d4 * 4];
                s[u] += qv.x * kv.x + qv.y * kv.y + qv.z * kv.z + qv.w * kv.w;
            }
        }

        float mt = m;
        #pragma unroll
        for (int u = 0; u < 8; u++) {
            int j = j0 + c + 4 * u;
            bool ok = (j <= iq) && (iq - j < WIN);
            s[u] = ok ? s[u] : -1e30f;
            mt = fmaxf(mt, s[u]);
        }
        mt = fmaxf(mt, __shfl_xor_sync(0xffffffffu, mt, 1));
        mt = fmaxf(mt, __shfl_xor_sync(0xffffffffu, mt, 2));
        float alpha = __expf(m - mt);
        m = mt;
        float psum = 0.f;
        #pragma unroll
        for (int u = 0; u < 8; u++) {
            float p = __expf(s[u] - mt);
            psum += p;
            Ps[r * PSTR + c + 4 * u] = p;
        }
        l = l * alpha + psum;
        #pragma unroll
        for (int t8 = 0; t8 < 8; t8++) {
            o[t8].x *= alpha; o[t8].y *= alpha; o[t8].z *= alpha; o[t8].w *= alpha;
        }
        __syncwarp();
        #pragma unroll 4
        for (int jj = 0; jj < 32; jj++) {
            float pj = Ps[r * PSTR + jj];
            #pragma unroll
            for (int t8 = 0; t8 < 8; t8++) {
                float4 vv = *(const float4*)&Vs[jj * QSTR + (c + 4 * t8) * 4];
                o[t8].x += pj * vv.x; o[t8].y += pj * vv.y;
                o[t8].z += pj * vv.z; o[t8].w += pj * vv.w;
            }
        }
        __syncwarp();
    }

    l += __shfl_xor_sync(0xffffffffu, l, 1);
    l += __shfl_xor_sync(0xffffffffu, l, 2);
    float linv = 1.0f / l;
    size_t obase = (size_t)(b * SEQ + i0 + r) * H_SIZE + h * HD;
    #pragma unroll
    for (int t8 = 0; t8 < 8; t8++) {
        float v0 = o[t8].x * linv, v1 = o[t8].y * linv;
        float v2 = o[t8].z * linv, v3 = o[t8].w * linv;
        size_t off = obase + (c + 4 * t8) * 4;
        split2(v0, v1, Oh + off,     Ol + off);
        split2(v2, v3, Oh + off + 2, Ol + off + 2);
    }
}

// ---------------- GeGLU: planes out -------------------------------------------------------
__device__ __forceinline__ float gelu_exact(float x) {
    return 0.5f * x * (1.0f + erff(x * 0.7071067811865476f));
}
__global__ __launch_bounds__(256) void geglu_kernel(
    const float* __restrict__ g, const float* __restrict__ u,
    __nv_bfloat16* __restrict__ oh, __nv_bfloat16* __restrict__ ol, int n4)
{
    int i = blockIdx.x * blockDim.x + threadIdx.x;
    int stride = gridDim.x * blockDim.x;
    for (; i < n4; i += stride) {
        float4 gv = ((const float4*)g)[i];
        float4 uv = ((const float4*)u)[i];
        float r0 = gelu_exact(gv.x) * uv.x;
        float r1 = gelu_exact(gv.y) * uv.y;
        float r2 = gelu_exact(gv.z) * uv.z;
        float r3 = gelu_exact(gv.w) * uv.w;
        split2(r0, r1, oh + i*4,     ol + i*4);
        split2(r2, r3, oh + i*4 + 2, ol + i*4 + 2);
    }
}

// ---------------- launch ----------------------------------------------------------------
extern "C" void kernel_launch(void* const* d_in, const int* in_sizes, int n_in,
                              void* d_out, int out_size)
{
    const float* x    = (const float*)d_in[0];
    const float* wq   = (const float*)d_in[1];
    const float* wk   = (const float*)d_in[2];
    const float* wv   = (const float*)d_in[3];
    const float* wo   = (const float*)d_in[4];
    const float* w_in = (const float*)d_in[5];
    const float* w_pa = (const float*)d_in[6];
    const float* w_pf = (const float*)d_in[7];
    const float* w_pff= (const float*)d_in[8];
    const float* wg   = (const float*)d_in[9];
    const float* wu   = (const float*)d_in[10];
    const float* wd   = (const float*)d_in[11];
    const float* lsc  = (const float*)d_in[12];
    float* out = (float*)d_out;

    float *q, *k, *v, *attnout, *h2, *gate, *up, *ffnout;
    cudaGetSymbolAddress((void**)&q,       g_q);
    cudaGetSymbolAddress((void**)&k,       g_k);
    cudaGetSymbolAddress((void**)&v,       g_v);
    cudaGetSymbolAddress((void**)&attnout, g_attnout);
    cudaGetSymbolAddress((void**)&h2,      g_h2);
    cudaGetSymbolAddress((void**)&gate,    g_gate);
    cudaGetSymbolAddress((void**)&up,      g_up);
    cudaGetSymbolAddress((void**)&ffnout,  g_ffnout);

    __nv_bfloat16 *h_h, *h_l, *attn_h, *attn_l, *ffnin_h, *ffnin_l, *gact_h, *gact_l;
    __nv_bfloat16 *wq_h, *wq_l, *wk_h, *wk_l, *wv_h, *wv_l, *wo_h, *wo_l;
    __nv_bfloat16 *wg_h, *wg_l, *wu_h, *wu_l, *wd_h, *wd_l;
    cudaGetSymbolAddress((void**)&h_h, g_h_h);       cudaGetSymbolAddress((void**)&h_l, g_h_l);
    cudaGetSymbolAddress((void**)&attn_h, g_attn_h); cudaGetSymbolAddress((void**)&attn_l, g_attn_l);
    cudaGetSymbolAddress((void**)&ffnin_h, g_ffnin_h); cudaGetSymbolAddress((void**)&ffnin_l, g_ffnin_l);
    cudaGetSymbolAddress((void**)&gact_h, g_gact_h); cudaGetSymbolAddress((void**)&gact_l, g_gact_l);
    cudaGetSymbolAddress((void**)&wq_h, g_wq_h);     cudaGetSymbolAddress((void**)&wq_l, g_wq_l);
    cudaGetSymbolAddress((void**)&wk_h, g_wk_h);     cudaGetSymbolAddress((void**)&wk_l, g_wk_l);
    cudaGetSymbolAddress((void**)&wv_h, g_wv_h);     cudaGetSymbolAddress((void**)&wv_l, g_wv_l);
    cudaGetSymbolAddress((void**)&wo_h, g_wo_h);     cudaGetSymbolAddress((void**)&wo_l, g_wo_l);
    cudaGetSymbolAddress((void**)&wg_h, g_wg_h);     cudaGetSymbolAddress((void**)&wg_l, g_wg_l);
    cudaGetSymbolAddress((void**)&wu_h, g_wu_h);     cudaGetSymbolAddress((void**)&wu_l, g_wu_l);
    cudaGetSymbolAddress((void**)&wd_h, g_wd_h);     cudaGetSymbolAddress((void**)&wd_l, g_wd_l);

    const int attn_smem = ATTN_SMEM_FLOATS * (int)sizeof(float);
    cudaFuncSetAttribute(attn_kernel, cudaFuncAttributeMaxDynamicSharedMemorySize, attn_smem);
    const int gemm_smem = 2 * STAGE_HALFS * (int)sizeof(__nv_bfloat16);
    cudaFuncSetAttribute(gemm_planes, cudaFuncAttributeMaxDynamicSharedMemorySize, gemm_smem);

    // weight splits
    split_kernel<<<2048, 256>>>(wq, wq_h, wq_l, H_SIZE*H_SIZE/4);
    split_kernel<<<1024, 256>>>(wk, wk_h, wk_l, NKV*HD*H_SIZE/4);
    split_kernel<<<1024, 256>>>(wv, wv_h, wv_l, NKV*HD*H_SIZE/4);
    split_kernel<<<2048, 256>>>(wo, wo_h, wo_l, H_SIZE*H_SIZE/4);
    split_kernel<<<4096, 256>>>(wg, wg_h, wg_l, INTER_SZ*H_SIZE/4);
    split_kernel<<<4096, 256>>>(wu, wu_h, wu_l, INTER_SZ*H_SIZE/4);
    split_kernel<<<4096, 256>>>(wd, wd_h, wd_l, H_SIZE*INTER_SZ/4);

    // h = rmsnorm(x, w_in) -> planes
    rmsnorm_split_kernel<<<NROWS, 256>>>(x, w_in, h_h, h_l);
    // QKV
    gemm_planes<<<dim3(H_SIZE/128, NROWS/128), 256, gemm_smem>>>(h_h, h_l, wq_h, wq_l, q, NROWS, H_SIZE, H_SIZE);
    gemm_planes<<<dim3((NKV*HD)/128, NROWS/128), 256, gemm_smem>>>(h_h, h_l, wk_h, wk_l, k, NROWS, NKV*HD, H_SIZE);
    gemm_planes<<<dim3((NKV*HD)/128, NROWS/128), 256, gemm_smem>>>(h_h, h_l, wv_h, wv_l, v, NROWS, NKV*HD, H_SIZE);
    // RoPE
    rope_kernel<<<NROWS, 256>>>(q, NQ);
    rope_kernel<<<NROWS, 256>>>(k, NKV);
    // attention -> planes
    attn_kernel<<<dim3(SEQ/64, NQ, BATCH), 256, attn_smem>>>(q, k, v, attn_h, attn_l);
    // WO
    gemm_planes<<<dim3(H_SIZE/128, NROWS/128), 256, gemm_smem>>>(attn_h, attn_l, wo_h, wo_l, attnout, NROWS, H_SIZE, H_SIZE);
    // h2 = x + rmsnorm(attnout, w_pa)
    rmsnorm_kernel<<<NROWS, 256>>>(attnout, w_pa, x, nullptr, h2, 1);
    // ffn_in = rmsnorm(h2, w_pf) -> planes
    rmsnorm_split_kernel<<<NROWS, 256>>>(h2, w_pf, ffnin_h, ffnin_l);
    // gate/up GEMMs
    gemm_planes<<<dim3(INTER_SZ/128, NROWS/128), 256, gemm_smem>>>(ffnin_h, ffnin_l, wg_h, wg_l, gate, NROWS, INTER_SZ, H_SIZE);
    gemm_planes<<<dim3(INTER_SZ/128, NROWS/128), 256, gemm_smem>>>(ffnin_h, ffnin_l, wu_h, wu_l, up, NROWS, INTER_SZ, H_SIZE);
    // act = gelu(gate) * up -> planes
    geglu_kernel<<<8192, 256>>>(gate, up, gact_h, gact_l, (NROWS * INTER_SZ) / 4);
    // down projection
    gemm_planes<<<dim3(H_SIZE/128, NROWS/128), 256, gemm_smem>>>(gact_h, gact_l, wd_h, wd_l, ffnout, NROWS, H_SIZE, INTER_SZ);
    // out = (h2 + rmsnorm(ffnout, w_pff)) * layer_scalar
    rmsnorm_kernel<<<NROWS, 256>>>(ffnout, w_pff, h2, lsc, out, 2);
}

// round 7
// speedup vs baseline: 1.0904x; 1.0904x over previous
#include <cuda_runtime.h>
#include <cuda_bf16.h>
#include <stdint.h>
#include <math.h>

#define H_SIZE 2048
#define INTER_SZ 8192
#define NQ 16
#define NKV 8
#define HD 128
#define SEQ 2048
#define BATCH 2
#define NROWS (BATCH*SEQ)
#define WIN 1024

// ---------------- scratch (module-scope device globals; no runtime alloc) ----------------
__device__ float g_h[NROWS*H_SIZE];
__device__ float g_q[NROWS*H_SIZE];
__device__ float g_k[NROWS*NKV*HD];
__device__ float g_v[NROWS*NKV*HD];
__device__ float g_attn[NROWS*H_SIZE];
__device__ float g_attnout[NROWS*H_SIZE];
__device__ float g_h2[NROWS*H_SIZE];
__device__ float g_ffnin[NROWS*H_SIZE];
__device__ float g_gate[NROWS*INTER_SZ];
__device__ float g_up[NROWS*INTER_SZ];
__device__ float g_ffnout[NROWS*H_SIZE];

// ---------------- RMSNorm (mode 0: norm; 1: res + norm; 2: (res + norm)*scalar) ----------
__global__ __launch_bounds__(256) void rmsnorm_kernel(
    const float* __restrict__ in, const float* __restrict__ w,
    const float* __restrict__ res, const float* __restrict__ scal,
    float* __restrict__ out, int mode)
{
    int row = blockIdx.x;
    int t = threadIdx.x;
    const float4* ip = (const float4*)(in + (size_t)row * H_SIZE);
    float4 v0 = ip[t];
    float4 v1 = ip[t + 256];
    float ss = v0.x*v0.x + v0.y*v0.y + v0.z*v0.z + v0.w*v0.w
             + v1.x*v1.x + v1.y*v1.y + v1.z*v1.z + v1.w*v1.w;
    #pragma unroll
    for (int o = 16; o; o >>= 1) ss += __shfl_xor_sync(0xffffffffu, ss, o);
    __shared__ float red[8];
    if ((t & 31) == 0) red[t >> 5] = ss;
    __syncthreads();
    float tot = red[0]+red[1]+red[2]+red[3]+red[4]+red[5]+red[6]+red[7];
    float inv = rsqrtf(tot * (1.0f / H_SIZE) + 1e-6f);

    const float4* w4 = (const float4*)w;
    float4 w0 = w4[t], w1 = w4[t + 256];
    float4 o0, o1;
    o0.x = v0.x*inv*w0.x; o0.y = v0.y*inv*w0.y; o0.z = v0.z*inv*w0.z; o0.w = v0.w*inv*w0.w;
    o1.x = v1.x*inv*w1.x; o1.y = v1.y*inv*w1.y; o1.z = v1.z*inv*w1.z; o1.w = v1.w*inv*w1.w;
    if (mode >= 1) {
        const float4* rp = (const float4*)(res + (size_t)row * H_SIZE);
        float4 r0 = rp[t], r1 = rp[t + 256];
        o0.x += r0.x; o0.y += r0.y; o0.z += r0.z; o0.w += r0.w;
        o1.x += r1.x; o1.y += r1.y; o1.z += r1.z; o1.w += r1.w;
    }
    if (mode == 2) {
        float sc = scal[0];
        o0.x *= sc; o0.y *= sc; o0.z *= sc; o0.w *= sc;
        o1.x *= sc; o1.y *= sc; o1.z *= sc; o1.w *= sc;
    }
    float4* op = (float4*)(out + (size_t)row * H_SIZE);
    op[t] = o0;
    op[t + 256] = o1;
}

// ---------------- Tensor-core GEMM: C[M,N] = A[M,K] * B[N,K]^T  (bf16x3 split) -----------
// 128x128 block, BK=32, 256 threads = 8 warps in 2(m) x 4(n), warp tile 64x32.
// Fragments loaded via ldmatrix.x4 (LDSM) — 4x fewer shared-pipe instructions than LDS.32.

#define LDSK 40   // padded row stride in halfs (80B: 8-row LDSM matrices are conflict-free)

__device__ __forceinline__ void mma_bf16(float* c, const uint32_t* a, const uint32_t* b) {
    asm volatile(
        "mma.sync.aligned.m16n8k16.row.col.f32.bf16.bf16.f32 "
        "{%0,%1,%2,%3}, {%4,%5,%6,%7}, {%8,%9}, {%0,%1,%2,%3};\n"
        : "+f"(c[0]), "+f"(c[1]), "+f"(c[2]), "+f"(c[3])
        : "r"(a[0]), "r"(a[1]), "r"(a[2]), "r"(a[3]), "r"(b[0]), "r"(b[1]));
}

__device__ __forceinline__ void ldsm_x4(uint32_t* r, uint32_t addr) {
    asm volatile("ldmatrix.sync.aligned.m8n8.x4.shared.b16 {%0,%1,%2,%3}, [%4];"
        : "=r"(r[0]), "=r"(r[1]), "=r"(r[2]), "=r"(r[3]) : "r"(addr));
}

__device__ __forceinline__ void cvt_store(__nv_bfloat16* sh, __nv_bfloat16* sl, float4 v) {
    __nv_bfloat16 hx = __float2bfloat16(v.x);
    __nv_bfloat16 hy = __float2bfloat16(v.y);
    __nv_bfloat16 hz = __float2bfloat16(v.z);
    __nv_bfloat16 hw = __float2bfloat16(v.w);
    __nv_bfloat16 lx = __float2bfloat16(v.x - __bfloat162float(hx));
    __nv_bfloat16 ly = __float2bfloat16(v.y - __bfloat162float(hy));
    __nv_bfloat16 lz = __float2bfloat16(v.z - __bfloat162float(hz));
    __nv_bfloat16 lw = __float2bfloat16(v.w - __bfloat162float(hw));
    *(__nv_bfloat162*)(sh)     = __halves2bfloat162(hx, hy);
    *(__nv_bfloat162*)(sh + 2) = __halves2bfloat162(hz, hw);
    *(__nv_bfloat162*)(sl)     = __halves2bfloat162(lx, ly);
    *(__nv_bfloat162*)(sl + 2) = __halves2bfloat162(lz, lw);
}

__global__ __launch_bounds__(256) void gemm_mma(
    const float* __restrict__ A, const float* __restrict__ B,
    float* __restrict__ C, int M, int N, int K)
{
    __shared__ __align__(16) __nv_bfloat16 Ahs[128*LDSK];
    __shared__ __align__(16) __nv_bfloat16 Als[128*LDSK];
    __shared__ __align__(16) __nv_bfloat16 Bhs[128*LDSK];
    __shared__ __align__(16) __nv_bfloat16 Bls[128*LDSK];

    const int tid  = threadIdx.x;
    const int warp = tid >> 5, lane = tid & 31;
    const int wm = warp >> 2, wn = warp & 3;   // 2 x 4 warp grid

    const float* Ab = A + (size_t)blockIdx.y * 128 * K;
    const float* Bb = B + (size_t)blockIdx.x * 128 * K;

    const int lrow = tid >> 3;        // 0..31
    const int lcol = (tid & 7) * 4;   // 0..28

    // ldmatrix base addresses (byte offsets into shared space)
    const uint32_t ah_b = (uint32_t)__cvta_generic_to_shared(Ahs);
    const uint32_t al_b = (uint32_t)__cvta_generic_to_shared(Als);
    const uint32_t bh_b = (uint32_t)__cvta_generic_to_shared(Bhs);
    const uint32_t bl_b = (uint32_t)__cvta_generic_to_shared(Bls);
    // A tile: lanes 0-15 -> rows, lanes 16-31 -> k+8 half
    const uint32_t a_off = (uint32_t)(((wm*64 + (lane & 15)) * LDSK + ((lane >> 4) * 8)) * 2);
    // B tiles (two n8 tiles per x4): lanes>>4 -> tile, (lane>>3)&1 -> k half
    const uint32_t b_off = (uint32_t)(((wn*32 + ((lane >> 4) * 8) + (lane & 7)) * LDSK
                                       + (((lane >> 3) & 1) * 8)) * 2);

    float acc[4][4][4];
    #pragma unroll
    for (int i = 0; i < 4; i++)
        #pragma unroll
        for (int j = 0; j < 4; j++)
            #pragma unroll
            for (int q = 0; q < 4; q++) acc[i][j][q] = 0.f;

    float4 pa[4], pb[4];
    #pragma unroll
    for (int i = 0; i < 4; i++) {
        pa[i] = *(const float4*)(Ab + (size_t)(lrow + 32*i) * K + lcol);
        pb[i] = *(const float4*)(Bb + (size_t)(lrow + 32*i) * K + lcol);
    }

    for (int k0 = 0; k0 < K; k0 += 32) {
        #pragma unroll
        for (int i = 0; i < 4; i++) {
            int off = (lrow + 32*i) * LDSK + lcol;
            cvt_store(Ahs + off, Als + off, pa[i]);
            cvt_store(Bhs + off, Bls + off, pb[i]);
        }
        __syncthreads();
        if (k0 + 32 < K) {
            #pragma unroll
            for (int i = 0; i < 4; i++) {
                pa[i] = *(const float4*)(Ab + (size_t)(lrow + 32*i) * K + (k0 + 32) + lcol);
                pb[i] = *(const float4*)(Bb + (size_t)(lrow + 32*i) * K + (k0 + 32) + lcol);
            }
        }
        #pragma unroll
        for (int kk = 0; kk < 32; kk += 16) {
            const uint32_t kko = kk * 2;
            uint32_t fa[4][4], fal[4][4];
            uint32_t fb[2][4], fbl[2][4];   // [pair][tn0k0,tn0k8,tn1k0,tn1k8]
            #pragma unroll
            for (int tm = 0; tm < 4; tm++) {
                ldsm_x4(fa[tm],  ah_b + a_off + (uint32_t)(tm * 16 * LDSK * 2) + kko);
                ldsm_x4(fal[tm], al_b + a_off + (uint32_t)(tm * 16 * LDSK * 2) + kko);
            }
            #pragma unroll
            for (int p = 0; p < 2; p++) {
                ldsm_x4(fb[p],  bh_b + b_off + (uint32_t)(p * 16 * LDSK * 2) + kko);
                ldsm_x4(fbl[p], bl_b + b_off + (uint32_t)(p * 16 * LDSK * 2) + kko);
            }
            // pass 1: Ah * Bh
            #pragma unroll
            for (int tm = 0; tm < 4; tm++)
                #pragma unroll
                for (int tn = 0; tn < 4; tn++)
                    mma_bf16(acc[tm][tn], fa[tm], &fb[tn >> 1][(tn & 1) * 2]);
            // pass 2: Ah * Bl
            #pragma unroll
            for (int tm = 0; tm < 4; tm++)
                #pragma unroll
                for (int tn = 0; tn < 4; tn++)
                    mma_bf16(acc[tm][tn], fa[tm], &fbl[tn >> 1][(tn & 1) * 2]);
            // pass 3: Al * Bh
            #pragma unroll
            for (int tm = 0; tm < 4; tm++)
                #pragma unroll
                for (int tn = 0; tn < 4; tn++)
                    mma_bf16(acc[tm][tn], fal[tm], &fb[tn >> 1][(tn & 1) * 2]);
        }
        __syncthreads();
    }

    const int g = lane >> 2, t4 = lane & 3;
    #pragma unroll
    for (int tm = 0; tm < 4; tm++) {
        #pragma unroll
        for (int tn = 0; tn < 4; tn++) {
            int row = blockIdx.y*128 + wm*64 + tm*16 + g;
            int col = blockIdx.x*128 + wn*32 + tn*8 + 2*t4;
            float2 c0 = {acc[tm][tn][0], acc[tm][tn][1]};
            float2 c1 = {acc[tm][tn][2], acc[tm][tn][3]};
            *(float2*)(C + (size_t)row * N + col)       = c0;
            *(float2*)(C + (size_t)(row + 8) * N + col) = c1;
        }
    }
}

// ---------------- RoPE (in-place on [NROWS, nheads*128]) --------------------------------
__global__ __launch_bounds__(256) void rope_kernel(float* __restrict__ buf, int nheads)
{
    int row = blockIdx.x;
    int s = row & (SEQ - 1);
    float* base = buf + (size_t)row * nheads * HD;
    for (int idx = threadIdx.x; idx < nheads * 64; idx += blockDim.x) {
        int hh = idx >> 6;
        int d = idx & 63;
        float inv = expf(-((float)d * (1.0f / 64.0f)) * 9.210340371976184f); // ln(10000)
        float fr = (float)s * inv;
        float sn = sinf(fr), cs = cosf(fr);
        float* p = base + hh * HD + d;
        float x1 = p[0], x2 = p[64];
        p[0]  = x1 * cs - x2 * sn;
        p[64] = x2 * cs + x1 * sn;
    }
}

// ---------------- Sliding-window GQA flash attention ------------------------------------
#define QSTR 132
#define PSTR 36
#define ATTN_SMEM_FLOATS (64*QSTR + 32*QSTR + 32*QSTR + 64*PSTR)

__global__ __launch_bounds__(256) void attn_kernel(
    const float* __restrict__ Q, const float* __restrict__ K,
    const float* __restrict__ V, float* __restrict__ O)
{
    extern __shared__ float sm[];
    float* Qs = sm;
    float* Ks = sm + 64 * QSTR;
    float* Vs = Ks + 32 * QSTR;
    float* Ps = Vs + 32 * QSTR;

    const int i0 = blockIdx.x * 64;
    const int h  = blockIdx.y;
    const int b  = blockIdx.z;
    const int hk = h >> 1;
    const int tid = threadIdx.x;
    const int r = tid >> 2, c = tid & 3;
    const float scale = 0.08838834764831845f; // 1/sqrt(128)

    #pragma unroll
    for (int it = 0; it < 8; it++) {
        int idx = tid + 256 * it;
        int rr = idx >> 5, d4 = idx & 31;
        float4 qv = *(const float4*)(Q + ((size_t)(b * SEQ + i0 + rr) * H_SIZE + h * HD + d4 * 4));
        float4 qs = {qv.x * scale, qv.y * scale, qv.z * scale, qv.w * scale};
        *(float4*)&Qs[rr * QSTR + d4 * 4] = qs;
    }

    float m = -1e30f, l = 0.f;
    float4 o[8];
    #pragma unroll
    for (int t8 = 0; t8 < 8; t8++) o[t8] = make_float4(0.f, 0.f, 0.f, 0.f);

    int jstart = i0 - (WIN - 1);
    if (jstart < 0) jstart = 0;
    jstart &= ~31;
    const int iq = i0 + r;
    const float* qrow = Qs + r * QSTR;

    for (int j0 = jstart; j0 < i0 + 64; j0 += 32) {
        __syncthreads();
        #pragma unroll
        for (int it = 0; it < 4; it++) {
            int idx = tid + 256 * it;
            int rr = idx >> 5, d4 = idx & 31;
            size_t goff = (size_t)(b * SEQ + j0 + rr) * (NKV * HD) + hk * HD + d4 * 4;
            *(float4*)&Ks[rr * QSTR + d4 * 4] = *(const float4*)(K + goff);
            *(float4*)&Vs[rr * QSTR + d4 * 4] = *(const float4*)(V + goff);
        }
        __syncthreads();

        float s[8];
        #pragma unroll
        for (int u = 0; u < 8; u++) s[u] = 0.f;
        #pragma unroll 4
        for (int d4 = 0; d4 < 32; d4++) {
            float4 qv = *(const float4*)(qrow + d4 * 4);
            #pragma unroll
            for (int u = 0; u < 8; u++) {
                float4 kv = *(const float4*)&Ks[(c + 4 * u) * QSTR + d4 * 4];
                s[u] += qv.x * kv.x + qv.y * kv.y + qv.z * kv.z + qv.w * kv.w;
            }
        }

        float mt = m;
        #pragma unroll
        for (int u = 0; u < 8; u++) {
            int j = j0 + c + 4 * u;
            bool ok = (j <= iq) && (iq - j < WIN);
            s[u] = ok ? s[u] : -1e30f;
            mt = fmaxf(mt, s[u]);
        }
        mt = fmaxf(mt, __shfl_xor_sync(0xffffffffu, mt, 1));
        mt = fmaxf(mt, __shfl_xor_sync(0xffffffffu, mt, 2));
        float alpha = __expf(m - mt);
        m = mt;
        float psum = 0.f;
        #pragma unroll
        for (int u = 0; u < 8; u++) {
            float p = __expf(s[u] - mt);
            psum += p;
            Ps[r * PSTR + c + 4 * u] = p;
        }
        l = l * alpha + psum;
        #pragma unroll
        for (int t8 = 0; t8 < 8; t8++) {
            o[t8].x *= alpha; o[t8].y *= alpha; o[t8].z *= alpha; o[t8].w *= alpha;
        }
        __syncwarp();
        #pragma unroll 4
        for (int jj = 0; jj < 32; jj++) {
            float pj = Ps[r * PSTR + jj];
            #pragma unroll
            for (int t8 = 0; t8 < 8; t8++) {
                float4 vv = *(const float4*)&Vs[jj * QSTR + (c + 4 * t8) * 4];
                o[t8].x += pj * vv.x; o[t8].y += pj * vv.y;
                o[t8].z += pj * vv.z; o[t8].w += pj * vv.w;
            }
        }
        __syncwarp();
    }

    l += __shfl_xor_sync(0xffffffffu, l, 1);
    l += __shfl_xor_sync(0xffffffffu, l, 2);
    float linv = 1.0f / l;
    float* orow = O + (size_t)(b * SEQ + i0 + r) * H_SIZE + h * HD;
    #pragma unroll
    for (int t8 = 0; t8 < 8; t8++) {
        float4 ov = {o[t8].x * linv, o[t8].y * linv, o[t8].z * linv, o[t8].w * linv};
        *(float4*)(orow + (c + 4 * t8) * 4) = ov;
    }
}

// ---------------- GeGLU elementwise: o = gelu_exact(g) * u -------------------------------
__device__ __forceinline__ float gelu_exact(float x) {
    return 0.5f * x * (1.0f + erff(x * 0.7071067811865476f));
}
__global__ __launch_bounds__(256) void geglu_kernel(
    const float* __restrict__ g, const float* __restrict__ u,
    float* __restrict__ o, int n4)
{
    int i = blockIdx.x * blockDim.x + threadIdx.x;
    int stride = gridDim.x * blockDim.x;
    for (; i < n4; i += stride) {
        float4 gv = ((const float4*)g)[i];
        float4 uv = ((const float4*)u)[i];
        float4 r;
        r.x = gelu_exact(gv.x) * uv.x;
        r.y = gelu_exact(gv.y) * uv.y;
        r.z = gelu_exact(gv.z) * uv.z;
        r.w = gelu_exact(gv.w) * uv.w;
        ((float4*)o)[i] = r;
    }
}

// ---------------- launch ----------------------------------------------------------------
extern "C" void kernel_launch(void* const* d_in, const int* in_sizes, int n_in,
                              void* d_out, int out_size)
{
    const float* x    = (const float*)d_in[0];
    const float* wq   = (const float*)d_in[1];
    const float* wk   = (const float*)d_in[2];
    const float* wv   = (const float*)d_in[3];
    const float* wo   = (const float*)d_in[4];
    const float* w_in = (const float*)d_in[5];
    const float* w_pa = (const float*)d_in[6];
    const float* w_pf = (const float*)d_in[7];
    const float* w_pff= (const float*)d_in[8];
    const float* wg   = (const float*)d_in[9];
    const float* wu   = (const float*)d_in[10];
    const float* wd   = (const float*)d_in[11];
    const float* lsc  = (const float*)d_in[12];
    float* out = (float*)d_out;

    float *h, *q, *k, *v, *attn, *attnout, *h2, *ffnin, *gate, *up, *ffnout;
    cudaGetSymbolAddress((void**)&h,       g_h);
    cudaGetSymbolAddress((void**)&q,       g_q);
    cudaGetSymbolAddress((void**)&k,       g_k);
    cudaGetSymbolAddress((void**)&v,       g_v);
    cudaGetSymbolAddress((void**)&attn,    g_attn);
    cudaGetSymbolAddress((void**)&attnout, g_attnout);
    cudaGetSymbolAddress((void**)&h2,      g_h2);
    cudaGetSymbolAddress((void**)&ffnin,   g_ffnin);
    cudaGetSymbolAddress((void**)&gate,    g_gate);
    cudaGetSymbolAddress((void**)&up,      g_up);
    cudaGetSymbolAddress((void**)&ffnout,  g_ffnout);

    const int attn_smem = ATTN_SMEM_FLOATS * (int)sizeof(float);
    cudaFuncSetAttribute(attn_kernel, cudaFuncAttributeMaxDynamicSharedMemorySize, attn_smem);

    // h = rmsnorm(x, w_in)
    rmsnorm_kernel<<<NROWS, 256>>>(x, w_in, nullptr, nullptr, h, 0);
    // QKV
    gemm_mma<<<dim3(H_SIZE/128, NROWS/128), 256>>>(h, wq, q, NROWS, H_SIZE, H_SIZE);
    gemm_mma<<<dim3((NKV*HD)/128, NROWS/128), 256>>>(h, wk, k, NROWS, NKV*HD, H_SIZE);
    gemm_mma<<<dim3((NKV*HD)/128, NROWS/128), 256>>>(h, wv, v, NROWS, NKV*HD, H_SIZE);
    // RoPE
    rope_kernel<<<NROWS, 256>>>(q, NQ);
    rope_kernel<<<NROWS, 256>>>(k, NKV);
    // attention
    attn_kernel<<<dim3(SEQ/64, NQ, BATCH), 256, attn_smem>>>(q, k, v, attn);
    // WO
    gemm_mma<<<dim3(H_SIZE/128, NROWS/128), 256>>>(attn, wo, attnout, NROWS, H_SIZE, H_SIZE);
    // h2 = x + rmsnorm(attnout, w_pa)
    rmsnorm_kernel<<<NROWS, 256>>>(attnout, w_pa, x, nullptr, h2, 1);
    // ffn_in = rmsnorm(h2, w_pf)
    rmsnorm_kernel<<<NROWS, 256>>>(h2, w_pf, nullptr, nullptr, ffnin, 0);
    // gate/up GEMMs
    gemm_mma<<<dim3(INTER_SZ/128, NROWS/128), 256>>>(ffnin, wg, gate, NROWS, INTER_SZ, H_SIZE);
    gemm_mma<<<dim3(INTER_SZ/128, NROWS/128), 256>>>(ffnin, wu, up, NROWS, INTER_SZ, H_SIZE);
    // act = gelu(gate) * up   (into gate)
    geglu_kernel<<<8192, 256>>>(gate, up, gate, (NROWS * INTER_SZ) / 4);
    // down projection
    gemm_mma<<<dim3(H_SIZE/128, NROWS/128), 256>>>(gate, wd, ffnout, NROWS, H_SIZE, INTER_SZ);
    // out = (h2 + rmsnorm(ffnout, w_pff)) * layer_scalar
    rmsnorm_kernel<<<NROWS, 256>>>(ffnout, w_pff, h2, lsc, out, 2);
}

// round 8
// speedup vs baseline: 1.1167x; 1.0242x over previous
#include <cuda_runtime.h>
#include <cuda_bf16.h>
#include <stdint.h>
#include <math.h>

#define H_SIZE 2048
#define INTER_SZ 8192
#define NQ 16
#define NKV 8
#define HD 128
#define SEQ 2048
#define BATCH 2
#define NROWS (BATCH*SEQ)
#define WIN 1024

// ---------------- scratch (module-scope device globals; no runtime alloc) ----------------
__device__ float g_h[NROWS*H_SIZE];
__device__ float g_q[NROWS*H_SIZE];
__device__ float g_k[NROWS*NKV*HD];
__device__ float g_v[NROWS*NKV*HD];
__device__ float g_attn[NROWS*H_SIZE];
__device__ float g_attnout[NROWS*H_SIZE];
__device__ float g_h2[NROWS*H_SIZE];
__device__ float g_ffnin[NROWS*H_SIZE];
__device__ float g_gate[NROWS*INTER_SZ];
__device__ float g_up[NROWS*INTER_SZ];
__device__ float g_ffnout[NROWS*H_SIZE];

// ---------------- RMSNorm (mode 0: norm; 1: res + norm; 2: (res + norm)*scalar) ----------
__global__ __launch_bounds__(256) void rmsnorm_kernel(
    const float* __restrict__ in, const float* __restrict__ w,
    const float* __restrict__ res, const float* __restrict__ scal,
    float* __restrict__ out, int mode)
{
    int row = blockIdx.x;
    int t = threadIdx.x;
    const float4* ip = (const float4*)(in + (size_t)row * H_SIZE);
    float4 v0 = ip[t];
    float4 v1 = ip[t + 256];
    float ss = v0.x*v0.x + v0.y*v0.y + v0.z*v0.z + v0.w*v0.w
             + v1.x*v1.x + v1.y*v1.y + v1.z*v1.z + v1.w*v1.w;
    #pragma unroll
    for (int o = 16; o; o >>= 1) ss += __shfl_xor_sync(0xffffffffu, ss, o);
    __shared__ float red[8];
    if ((t & 31) == 0) red[t >> 5] = ss;
    __syncthreads();
    float tot = red[0]+red[1]+red[2]+red[3]+red[4]+red[5]+red[6]+red[7];
    float inv = rsqrtf(tot * (1.0f / H_SIZE) + 1e-6f);

    const float4* w4 = (const float4*)w;
    float4 w0 = w4[t], w1 = w4[t + 256];
    float4 o0, o1;
    o0.x = v0.x*inv*w0.x; o0.y = v0.y*inv*w0.y; o0.z = v0.z*inv*w0.z; o0.w = v0.w*inv*w0.w;
    o1.x = v1.x*inv*w1.x; o1.y = v1.y*inv*w1.y; o1.z = v1.z*inv*w1.z; o1.w = v1.w*inv*w1.w;
    if (mode >= 1) {
        const float4* rp = (const float4*)(res + (size_t)row * H_SIZE);
        float4 r0 = rp[t], r1 = rp[t + 256];
        o0.x += r0.x; o0.y += r0.y; o0.z += r0.z; o0.w += r0.w;
        o1.x += r1.x; o1.y += r1.y; o1.z += r1.z; o1.w += r1.w;
    }
    if (mode == 2) {
        float sc = scal[0];
        o0.x *= sc; o0.y *= sc; o0.z *= sc; o0.w *= sc;
        o1.x *= sc; o1.y *= sc; o1.z *= sc; o1.w *= sc;
    }
    float4* op = (float4*)(out + (size_t)row * H_SIZE);
    op[t] = o0;
    op[t + 256] = o1;
}

// ---------------- Tensor-core GEMM: C[M,N] = A[M,K] * B[N,K]^T  (bf16x3 split) -----------
// Block 128x64, BK=32, 256 threads = 8 warps in 4(m) x 2(n), warp tile 32x32.
// 2 CTAs/SM (launch_bounds 256,2) so sync/latency bubbles are covered by the co-resident CTA.

#define LDSK 40   // padded row stride in halfs

__device__ __forceinline__ void mma_bf16(float* c, const uint32_t* a, const uint32_t* b) {
    asm volatile(
        "mma.sync.aligned.m16n8k16.row.col.f32.bf16.bf16.f32 "
        "{%0,%1,%2,%3}, {%4,%5,%6,%7}, {%8,%9}, {%0,%1,%2,%3};\n"
        : "+f"(c[0]), "+f"(c[1]), "+f"(c[2]), "+f"(c[3])
        : "r"(a[0]), "r"(a[1]), "r"(a[2]), "r"(a[3]), "r"(b[0]), "r"(b[1]));
}

__device__ __forceinline__ void ldsm_x4(uint32_t* r, uint32_t addr) {
    asm volatile("ldmatrix.sync.aligned.m8n8.x4.shared.b16 {%0,%1,%2,%3}, [%4];"
        : "=r"(r[0]), "=r"(r[1]), "=r"(r[2]), "=r"(r[3]) : "r"(addr));
}

__device__ __forceinline__ void cvt_store(__nv_bfloat16* sh, __nv_bfloat16* sl, float4 v) {
    __nv_bfloat16 hx = __float2bfloat16(v.x);
    __nv_bfloat16 hy = __float2bfloat16(v.y);
    __nv_bfloat16 hz = __float2bfloat16(v.z);
    __nv_bfloat16 hw = __float2bfloat16(v.w);
    __nv_bfloat16 lx = __float2bfloat16(v.x - __bfloat162float(hx));
    __nv_bfloat16 ly = __float2bfloat16(v.y - __bfloat162float(hy));
    __nv_bfloat16 lz = __float2bfloat16(v.z - __bfloat162float(hz));
    __nv_bfloat16 lw = __float2bfloat16(v.w - __bfloat162float(hw));
    *(__nv_bfloat162*)(sh)     = __halves2bfloat162(hx, hy);
    *(__nv_bfloat162*)(sh + 2) = __halves2bfloat162(hz, hw);
    *(__nv_bfloat162*)(sl)     = __halves2bfloat162(lx, ly);
    *(__nv_bfloat162*)(sl + 2) = __halves2bfloat162(lz, lw);
}

__global__ __launch_bounds__(256, 2) void gemm_mma(
    const float* __restrict__ A, const float* __restrict__ B,
    float* __restrict__ C, int M, int N, int K)
{
    __shared__ __align__(16) __nv_bfloat16 Ahs[128*LDSK];
    __shared__ __align__(16) __nv_bfloat16 Als[128*LDSK];
    __shared__ __align__(16) __nv_bfloat16 Bhs[64*LDSK];
    __shared__ __align__(16) __nv_bfloat16 Bls[64*LDSK];

    const int tid  = threadIdx.x;
    const int warp = tid >> 5, lane = tid & 31;
    const int wm = warp >> 1, wn = warp & 1;   // 4 x 2 warp grid, warp tile 32x32

    const float* Ab = A + (size_t)blockIdx.y * 128 * K;
    const float* Bb = B + (size_t)blockIdx.x * 64 * K;

    const int lrow = tid >> 3;        // 0..31
    const int lcol = (tid & 7) * 4;   // 0..28

    const uint32_t ah_b = (uint32_t)__cvta_generic_to_shared(Ahs);
    const uint32_t al_b = (uint32_t)__cvta_generic_to_shared(Als);
    const uint32_t bh_b = (uint32_t)__cvta_generic_to_shared(Bhs);
    const uint32_t bl_b = (uint32_t)__cvta_generic_to_shared(Bls);
    // A tile: lanes 0-15 -> rows, lanes 16-31 -> k+8 half
    const uint32_t a_off = (uint32_t)(((wm*32 + (lane & 15)) * LDSK + ((lane >> 4) * 8)) * 2);
    // B tiles (two n8 tiles per x4): lane>>4 -> tile, (lane>>3)&1 -> k half
    const uint32_t b_off = (uint32_t)(((wn*32 + ((lane >> 4) * 8) + (lane & 7)) * LDSK
                                       + (((lane >> 3) & 1) * 8)) * 2);

    float acc[2][4][4];
    #pragma unroll
    for (int i = 0; i < 2; i++)
        #pragma unroll
        for (int j = 0; j < 4; j++)
            #pragma unroll
            for (int q = 0; q < 4; q++) acc[i][j][q] = 0.f;

    float4 pa[4], pb[2];
    #pragma unroll
    for (int i = 0; i < 4; i++)
        pa[i] = *(const float4*)(Ab + (size_t)(lrow + 32*i) * K + lcol);
    #pragma unroll
    for (int i = 0; i < 2; i++)
        pb[i] = *(const float4*)(Bb + (size_t)(lrow + 32*i) * K + lcol);

    for (int k0 = 0; k0 < K; k0 += 32) {
        #pragma unroll
        for (int i = 0; i < 4; i++) {
            int off = (lrow + 32*i) * LDSK + lcol;
            cvt_store(Ahs + off, Als + off, pa[i]);
        }
        #pragma unroll
        for (int i = 0; i < 2; i++) {
            int off = (lrow + 32*i) * LDSK + lcol;
            cvt_store(Bhs + off, Bls + off, pb[i]);
        }
        __syncthreads();
        if (k0 + 32 < K) {
            #pragma unroll
            for (int i = 0; i < 4; i++)
                pa[i] = *(const float4*)(Ab + (size_t)(lrow + 32*i) * K + (k0 + 32) + lcol);
            #pragma unroll
            for (int i = 0; i < 2; i++)
                pb[i] = *(const float4*)(Bb + (size_t)(lrow + 32*i) * K + (k0 + 32) + lcol);
        }
        #pragma unroll
        for (int kk = 0; kk < 32; kk += 16) {
            const uint32_t kko = kk * 2;
            uint32_t fa[2][4], fal[2][4];
            uint32_t fb[2][4], fbl[2][4];   // [pair][tn0k0,tn0k8,tn1k0,tn1k8]
            #pragma unroll
            for (int tm = 0; tm < 2; tm++) {
                ldsm_x4(fa[tm],  ah_b + a_off + (uint32_t)(tm * 16 * LDSK * 2) + kko);
                ldsm_x4(fal[tm], al_b + a_off + (uint32_t)(tm * 16 * LDSK * 2) + kko);
            }
            #pragma unroll
            for (int p = 0; p < 2; p++) {
                ldsm_x4(fb[p],  bh_b + b_off + (uint32_t)(p * 16 * LDSK * 2) + kko);
                ldsm_x4(fbl[p], bl_b + b_off + (uint32_t)(p * 16 * LDSK * 2) + kko);
            }
            // pass 1: Ah * Bh
            #pragma unroll
            for (int tm = 0; tm < 2; tm++)
                #pragma unroll
                for (int tn = 0; tn < 4; tn++)
                    mma_bf16(acc[tm][tn], fa[tm], &fb[tn >> 1][(tn & 1) * 2]);
            // pass 2: Ah * Bl
            #pragma unroll
            for (int tm = 0; tm < 2; tm++)
                #pragma unroll
                for (int tn = 0; tn < 4; tn++)
                    mma_bf16(acc[tm][tn], fa[tm], &fbl[tn >> 1][(tn & 1) * 2]);
            // pass 3: Al * Bh
            #pragma unroll
            for (int tm = 0; tm < 2; tm++)
                #pragma unroll
                for (int tn = 0; tn < 4; tn++)
                    mma_bf16(acc[tm][tn], fal[tm], &fb[tn >> 1][(tn & 1) * 2]);
        }
        __syncthreads();
    }

    const int g = lane >> 2, t4 = lane & 3;
    #pragma unroll
    for (int tm = 0; tm < 2; tm++) {
        #pragma unroll
        for (int tn = 0; tn < 4; tn++) {
            int row = blockIdx.y*128 + wm*32 + tm*16 + g;
            int col = blockIdx.x*64 + wn*32 + tn*8 + 2*t4;
            float2 c0 = {acc[tm][tn][0], acc[tm][tn][1]};
            float2 c1 = {acc[tm][tn][2], acc[tm][tn][3]};
            *(float2*)(C + (size_t)row * N + col)       = c0;
            *(float2*)(C + (size_t)(row + 8) * N + col) = c1;
        }
    }
}

// ---------------- RoPE (in-place on [NROWS, nheads*128]) --------------------------------
__global__ __launch_bounds__(256) void rope_kernel(float* __restrict__ buf, int nheads)
{
    int row = blockIdx.x;
    int s = row & (SEQ - 1);
    float* base = buf + (size_t)row * nheads * HD;
    for (int idx = threadIdx.x; idx < nheads * 64; idx += blockDim.x) {
        int hh = idx >> 6;
        int d = idx & 63;
        float inv = expf(-((float)d * (1.0f / 64.0f)) * 9.210340371976184f); // ln(10000)
        float fr = (float)s * inv;
        float sn = sinf(fr), cs = cosf(fr);
        float* p = base + hh * HD + d;
        float x1 = p[0], x2 = p[64];
        p[0]  = x1 * cs - x2 * sn;
        p[64] = x2 * cs + x1 * sn;
    }
}

// ---------------- Sliding-window GQA flash attention ------------------------------------
#define QSTR 132
#define PSTR 36
#define ATTN_SMEM_FLOATS (64*QSTR + 32*QSTR + 32*QSTR + 64*PSTR)

__global__ __launch_bounds__(256) void attn_kernel(
    const float* __restrict__ Q, const float* __restrict__ K,
    const float* __restrict__ V, float* __restrict__ O)
{
    extern __shared__ float sm[];
    float* Qs = sm;
    float* Ks = sm + 64 * QSTR;
    float* Vs = Ks + 32 * QSTR;
    float* Ps = Vs + 32 * QSTR;

    const int i0 = blockIdx.x * 64;
    const int h  = blockIdx.y;
    const int b  = blockIdx.z;
    const int hk = h >> 1;
    const int tid = threadIdx.x;
    const int r = tid >> 2, c = tid & 3;
    const float scale = 0.08838834764831845f; // 1/sqrt(128)

    #pragma unroll
    for (int it = 0; it < 8; it++) {
        int idx = tid + 256 * it;
        int rr = idx >> 5, d4 = idx & 31;
        float4 qv = *(const float4*)(Q + ((size_t)(b * SEQ + i0 + rr) * H_SIZE + h * HD + d4 * 4));
        float4 qs = {qv.x * scale, qv.y * scale, qv.z * scale, qv.w * scale};
        *(float4*)&Qs[rr * QSTR + d4 * 4] = qs;
    }

    float m = -1e30f, l = 0.f;
    float4 o[8];
    #pragma unroll
    for (int t8 = 0; t8 < 8; t8++) o[t8] = make_float4(0.f, 0.f, 0.f, 0.f);

    int jstart = i0 - (WIN - 1);
    if (jstart < 0) jstart = 0;
    jstart &= ~31;
    const int iq = i0 + r;
    const float* qrow = Qs + r * QSTR;

    for (int j0 = jstart; j0 < i0 + 64; j0 += 32) {
        __syncthreads();
        #pragma unroll
        for (int it = 0; it < 4; it++) {
            int idx = tid + 256 * it;
            int rr = idx >> 5, d4 = idx & 31;
            size_t goff = (size_t)(b * SEQ + j0 + rr) * (NKV * HD) + hk * HD + d4 * 4;
            *(float4*)&Ks[rr * QSTR + d4 * 4] = *(const float4*)(K + goff);
            *(float4*)&Vs[rr * QSTR + d4 * 4] = *(const float4*)(V + goff);
        }
        __syncthreads();

        float s[8];
        #pragma unroll
        for (int u = 0; u < 8; u++) s[u] = 0.f;
        #pragma unroll 4
        for (int d4 = 0; d4 < 32; d4++) {
            float4 qv = *(const float4*)(qrow + d4 * 4);
            #pragma unroll
            for (int u = 0; u < 8; u++) {
                float4 kv = *(const float4*)&Ks[(c + 4 * u) * QSTR + d4 * 4];
                s[u] += qv.x * kv.x + qv.y * kv.y + qv.z * kv.z + qv.w * kv.w;
            }
        }

        float mt = m;
        #pragma unroll
        for (int u = 0; u < 8; u++) {
            int j = j0 + c + 4 * u;
            bool ok = (j <= iq) && (iq - j < WIN);
            s[u] = ok ? s[u] : -1e30f;
            mt = fmaxf(mt, s[u]);
        }
        mt = fmaxf(mt, __shfl_xor_sync(0xffffffffu, mt, 1));
        mt = fmaxf(mt, __shfl_xor_sync(0xffffffffu, mt, 2));
        float alpha = __expf(m - mt);
        m = mt;
        float psum = 0.f;
        #pragma unroll
        for (int u = 0; u < 8; u++) {
            float p = __expf(s[u] - mt);
            psum += p;
            Ps[r * PSTR + c + 4 * u] = p;
        }
        l = l * alpha + psum;
        #pragma unroll
        for (int t8 = 0; t8 < 8; t8++) {
            o[t8].x *= alpha; o[t8].y *= alpha; o[t8].z *= alpha; o[t8].w *= alpha;
        }
        __syncwarp();
        #pragma unroll 4
        for (int jj = 0; jj < 32; jj++) {
            float pj = Ps[r * PSTR + jj];
            #pragma unroll
            for (int t8 = 0; t8 < 8; t8++) {
                float4 vv = *(const float4*)&Vs[jj * QSTR + (c + 4 * t8) * 4];
                o[t8].x += pj * vv.x; o[t8].y += pj * vv.y;
                o[t8].z += pj * vv.z; o[t8].w += pj * vv.w;
            }
        }
        __syncwarp();
    }

    l += __shfl_xor_sync(0xffffffffu, l, 1);
    l += __shfl_xor_sync(0xffffffffu, l, 2);
    float linv = 1.0f / l;
    float* orow = O + (size_t)(b * SEQ + i0 + r) * H_SIZE + h * HD;
    #pragma unroll
    for (int t8 = 0; t8 < 8; t8++) {
        float4 ov = {o[t8].x * linv, o[t8].y * linv, o[t8].z * linv, o[t8].w * linv};
        *(float4*)(orow + (c + 4 * t8) * 4) = ov;
    }
}

// ---------------- GeGLU elementwise: o = gelu_exact(g) * u -------------------------------
__device__ __forceinline__ float gelu_exact(float x) {
    return 0.5f * x * (1.0f + erff(x * 0.7071067811865476f));
}
__global__ __launch_bounds__(256) void geglu_kernel(
    const float* __restrict__ g, const float* __restrict__ u,
    float* __restrict__ o, int n4)
{
    int i = blockIdx.x * blockDim.x + threadIdx.x;
    int stride = gridDim.x * blockDim.x;
    for (; i < n4; i += stride) {
        float4 gv = ((const float4*)g)[i];
        float4 uv = ((const float4*)u)[i];
        float4 r;
        r.x = gelu_exact(gv.x) * uv.x;
        r.y = gelu_exact(gv.y) * uv.y;
        r.z = gelu_exact(gv.z) * uv.z;
        r.w = gelu_exact(gv.w) * uv.w;
        ((float4*)o)[i] = r;
    }
}

// ---------------- launch ----------------------------------------------------------------
extern "C" void kernel_launch(void* const* d_in, const int* in_sizes, int n_in,
                              void* d_out, int out_size)
{
    const float* x    = (const float*)d_in[0];
    const float* wq   = (const float*)d_in[1];
    const float* wk   = (const float*)d_in[2];
    const float* wv   = (const float*)d_in[3];
    const float* wo   = (const float*)d_in[4];
    const float* w_in = (const float*)d_in[5];
    const float* w_pa = (const float*)d_in[6];
    const float* w_pf = (const float*)d_in[7];
    const float* w_pff= (const float*)d_in[8];
    const float* wg   = (const float*)d_in[9];
    const float* wu   = (const float*)d_in[10];
    const float* wd   = (const float*)d_in[11];
    const float* lsc  = (const float*)d_in[12];
    float* out = (float*)d_out;

    float *h, *q, *k, *v, *attn, *attnout, *h2, *ffnin, *gate, *up, *ffnout;
    cudaGetSymbolAddress((void**)&h,       g_h);
    cudaGetSymbolAddress((void**)&q,       g_q);
    cudaGetSymbolAddress((void**)&k,       g_k);
    cudaGetSymbolAddress((void**)&v,       g_v);
    cudaGetSymbolAddress((void**)&attn,    g_attn);
    cudaGetSymbolAddress((void**)&attnout, g_attnout);
    cudaGetSymbolAddress((void**)&h2,      g_h2);
    cudaGetSymbolAddress((void**)&ffnin,   g_ffnin);
    cudaGetSymbolAddress((void**)&gate,    g_gate);
    cudaGetSymbolAddress((void**)&up,      g_up);
    cudaGetSymbolAddress((void**)&ffnout,  g_ffnout);

    const int attn_smem = ATTN_SMEM_FLOATS * (int)sizeof(float);
    cudaFuncSetAttribute(attn_kernel, cudaFuncAttributeMaxDynamicSharedMemorySize, attn_smem);

    // h = rmsnorm(x, w_in)
    rmsnorm_kernel<<<NROWS, 256>>>(x, w_in, nullptr, nullptr, h, 0);
    // QKV
    gemm_mma<<<dim3(H_SIZE/64, NROWS/128), 256>>>(h, wq, q, NROWS, H_SIZE, H_SIZE);
    gemm_mma<<<dim3((NKV*HD)/64, NROWS/128), 256>>>(h, wk, k, NROWS, NKV*HD, H_SIZE);
    gemm_mma<<<dim3((NKV*HD)/64, NROWS/128), 256>>>(h, wv, v, NROWS, NKV*HD, H_SIZE);
    // RoPE
    rope_kernel<<<NROWS, 256>>>(q, NQ);
    rope_kernel<<<NROWS, 256>>>(k, NKV);
    // attention
    attn_kernel<<<dim3(SEQ/64, NQ, BATCH), 256, attn_smem>>>(q, k, v, attn);
    // WO
    gemm_mma<<<dim3(H_SIZE/64, NROWS/128), 256>>>(attn, wo, attnout, NROWS, H_SIZE, H_SIZE);
    // h2 = x + rmsnorm(attnout, w_pa)
    rmsnorm_kernel<<<NROWS, 256>>>(attnout, w_pa, x, nullptr, h2, 1);
    // ffn_in = rmsnorm(h2, w_pf)
    rmsnorm_kernel<<<NROWS, 256>>>(h2, w_pf, nullptr, nullptr, ffnin, 0);
    // gate/up GEMMs
    gemm_mma<<<dim3(INTER_SZ/64, NROWS/128), 256>>>(ffnin, wg, gate, NROWS, INTER_SZ, H_SIZE);
    gemm_mma<<<dim3(INTER_SZ/64, NROWS/128), 256>>>(ffnin, wu, up, NROWS, INTER_SZ, H_SIZE);
    // act = gelu(gate) * up   (into gate)
    geglu_kernel<<<8192, 256>>>(gate, up, gate, (NROWS * INTER_SZ) / 4);
    // down projection
    gemm_mma<<<dim3(H_SIZE/64, NROWS/128), 256>>>(gate, wd, ffnout, NROWS, H_SIZE, INTER_SZ);
    // out = (h2 + rmsnorm(ffnout, w_pff)) * layer_scalar
    rmsnorm_kernel<<<NROWS, 256>>>(ffnout, w_pff, h2, lsc, out, 2);
}

// round 9
// speedup vs baseline: 1.3096x; 1.1727x over previous
#include <cuda_runtime.h>
#include <cuda_fp16.h>
#include <stdint.h>
#include <math.h>

#define H_SIZE 2048
#define INTER_SZ 8192
#define NQ 16
#define NKV 8
#define HD 128
#define SEQ 2048
#define BATCH 2
#define NROWS (BATCH*SEQ)
#define WIN 1024

// ---------------- scratch (module-scope device globals; no runtime alloc) ----------------
__device__ float g_h[NROWS*H_SIZE];
__device__ float g_q[NROWS*H_SIZE];
__device__ float g_k[NROWS*NKV*HD];
__device__ float g_v[NROWS*NKV*HD];
__device__ float g_attn[NROWS*H_SIZE];
__device__ float g_attnout[NROWS*H_SIZE];
__device__ float g_h2[NROWS*H_SIZE];
__device__ float g_ffnin[NROWS*H_SIZE];
__device__ float g_gate[NROWS*INTER_SZ];
__device__ float g_up[NROWS*INTER_SZ];
__device__ float g_ffnout[NROWS*H_SIZE];

// ---------------- RMSNorm (mode 0: norm; 1: res + norm; 2: (res + norm)*scalar) ----------
__global__ __launch_bounds__(256) void rmsnorm_kernel(
    const float* __restrict__ in, const float* __restrict__ w,
    const float* __restrict__ res, const float* __restrict__ scal,
    float* __restrict__ out, int mode)
{
    int row = blockIdx.x;
    int t = threadIdx.x;
    const float4* ip = (const float4*)(in + (size_t)row * H_SIZE);
    float4 v0 = ip[t];
    float4 v1 = ip[t + 256];
    float ss = v0.x*v0.x + v0.y*v0.y + v0.z*v0.z + v0.w*v0.w
             + v1.x*v1.x + v1.y*v1.y + v1.z*v1.z + v1.w*v1.w;
    #pragma unroll
    for (int o = 16; o; o >>= 1) ss += __shfl_xor_sync(0xffffffffu, ss, o);
    __shared__ float red[8];
    if ((t & 31) == 0) red[t >> 5] = ss;
    __syncthreads();
    float tot = red[0]+red[1]+red[2]+red[3]+red[4]+red[5]+red[6]+red[7];
    float inv = rsqrtf(tot * (1.0f / H_SIZE) + 1e-6f);

    const float4* w4 = (const float4*)w;
    float4 w0 = w4[t], w1 = w4[t + 256];
    float4 o0, o1;
    o0.x = v0.x*inv*w0.x; o0.y = v0.y*inv*w0.y; o0.z = v0.z*inv*w0.z; o0.w = v0.w*inv*w0.w;
    o1.x = v1.x*inv*w1.x; o1.y = v1.y*inv*w1.y; o1.z = v1.z*inv*w1.z; o1.w = v1.w*inv*w1.w;
    if (mode >= 1) {
        const float4* rp = (const float4*)(res + (size_t)row * H_SIZE);
        float4 r0 = rp[t], r1 = rp[t + 256];
        o0.x += r0.x; o0.y += r0.y; o0.z += r0.z; o0.w += r0.w;
        o1.x += r1.x; o1.y += r1.y; o1.z += r1.z; o1.w += r1.w;
    }
    if (mode == 2) {
        float sc = scal[0];
        o0.x *= sc; o0.y *= sc; o0.z *= sc; o0.w *= sc;
        o1.x *= sc; o1.y *= sc; o1.z *= sc; o1.w *= sc;
    }
    float4* op = (float4*)(out + (size_t)row * H_SIZE);
    op[t] = o0;
    op[t + 256] = o1;
}

// ---------------- Tensor-core GEMM: C[M,N] = A[M,K] * B[N,K]^T  (fp16 split-A, 2 pass) ---
// A = Ah + Al (fp16 each, ~22-bit combined mantissa); B = fp16 single plane.
// D = Ah*Bh + Al*Bh; error ~ a*(b - fp16(b)) ~ 2^-12, incoherent over K.
// Block 128x64, BK=32, 256 threads = 8 warps in 4(m) x 2(n), warp tile 32x32. 2 CTAs/SM.

#define LDSK 40   // padded row stride in halfs

__device__ __forceinline__ void mma_fp16(float* c, const uint32_t* a, const uint32_t* b) {
    asm volatile(
        "mma.sync.aligned.m16n8k16.row.col.f32.f16.f16.f32 "
        "{%0,%1,%2,%3}, {%4,%5,%6,%7}, {%8,%9}, {%0,%1,%2,%3};\n"
        : "+f"(c[0]), "+f"(c[1]), "+f"(c[2]), "+f"(c[3])
        : "r"(a[0]), "r"(a[1]), "r"(a[2]), "r"(a[3]), "r"(b[0]), "r"(b[1]));
}

__device__ __forceinline__ void ldsm_x4(uint32_t* r, uint32_t addr) {
    asm volatile("ldmatrix.sync.aligned.m8n8.x4.shared.b16 {%0,%1,%2,%3}, [%4];"
        : "=r"(r[0]), "=r"(r[1]), "=r"(r[2]), "=r"(r[3]) : "r"(addr));
}

// fp32 -> (hi, lo) fp16 planes
__device__ __forceinline__ void cvt_store_a(__half* sh, __half* sl, float4 v) {
    __half hx = __float2half(v.x), hy = __float2half(v.y);
    __half hz = __float2half(v.z), hw = __float2half(v.w);
    __half lx = __float2half(v.x - __half2float(hx));
    __half ly = __float2half(v.y - __half2float(hy));
    __half lz = __float2half(v.z - __half2float(hz));
    __half lw = __float2half(v.w - __half2float(hw));
    *(__half2*)(sh)     = __halves2half2(hx, hy);
    *(__half2*)(sh + 2) = __halves2half2(hz, hw);
    *(__half2*)(sl)     = __halves2half2(lx, ly);
    *(__half2*)(sl + 2) = __halves2half2(lz, lw);
}
// fp32 -> single fp16 plane
__device__ __forceinline__ void cvt_store_b(__half* sh, float4 v) {
    *(__half2*)(sh)     = __halves2half2(__float2half(v.x), __float2half(v.y));
    *(__half2*)(sh + 2) = __halves2half2(__float2half(v.z), __float2half(v.w));
}

__global__ __launch_bounds__(256, 2) void gemm_mma(
    const float* __restrict__ A, const float* __restrict__ B,
    float* __restrict__ C, int M, int N, int K)
{
    __shared__ __align__(16) __half Ahs[128*LDSK];
    __shared__ __align__(16) __half Als[128*LDSK];
    __shared__ __align__(16) __half Bhs[64*LDSK];

    const int tid  = threadIdx.x;
    const int warp = tid >> 5, lane = tid & 31;
    const int wm = warp >> 1, wn = warp & 1;   // 4 x 2 warp grid, warp tile 32x32

    const float* Ab = A + (size_t)blockIdx.y * 128 * K;
    const float* Bb = B + (size_t)blockIdx.x * 64 * K;

    const int lrow = tid >> 3;        // 0..31
    const int lcol = (tid & 7) * 4;   // 0..28

    const uint32_t ah_b = (uint32_t)__cvta_generic_to_shared(Ahs);
    const uint32_t al_b = (uint32_t)__cvta_generic_to_shared(Als);
    const uint32_t bh_b = (uint32_t)__cvta_generic_to_shared(Bhs);
    // A tile: lanes 0-15 -> rows, lanes 16-31 -> k+8 half
    const uint32_t a_off = (uint32_t)(((wm*32 + (lane & 15)) * LDSK + ((lane >> 4) * 8)) * 2);
    // B tiles (two n8 tiles per x4): lane>>4 -> tile, (lane>>3)&1 -> k half
    const uint32_t b_off = (uint32_t)(((wn*32 + ((lane >> 4) * 8) + (lane & 7)) * LDSK
                                       + (((lane >> 3) & 1) * 8)) * 2);

    float acc[2][4][4];
    #pragma unroll
    for (int i = 0; i < 2; i++)
        #pragma unroll
        for (int j = 0; j < 4; j++)
            #pragma unroll
            for (int q = 0; q < 4; q++) acc[i][j][q] = 0.f;

    float4 pa[4], pb[2];
    #pragma unroll
    for (int i = 0; i < 4; i++)
        pa[i] = *(const float4*)(Ab + (size_t)(lrow + 32*i) * K + lcol);
    #pragma unroll
    for (int i = 0; i < 2; i++)
        pb[i] = *(const float4*)(Bb + (size_t)(lrow + 32*i) * K + lcol);

    for (int k0 = 0; k0 < K; k0 += 32) {
        #pragma unroll
        for (int i = 0; i < 4; i++) {
            int off = (lrow + 32*i) * LDSK + lcol;
            cvt_store_a(Ahs + off, Als + off, pa[i]);
        }
        #pragma unroll
        for (int i = 0; i < 2; i++) {
            int off = (lrow + 32*i) * LDSK + lcol;
            cvt_store_b(Bhs + off, pb[i]);
        }
        __syncthreads();
        if (k0 + 32 < K) {
            #pragma unroll
            for (int i = 0; i < 4; i++)
                pa[i] = *(const float4*)(Ab + (size_t)(lrow + 32*i) * K + (k0 + 32) + lcol);
            #pragma unroll
            for (int i = 0; i < 2; i++)
                pb[i] = *(const float4*)(Bb + (size_t)(lrow + 32*i) * K + (k0 + 32) + lcol);
        }
        #pragma unroll
        for (int kk = 0; kk < 32; kk += 16) {
            const uint32_t kko = kk * 2;
            uint32_t fa[2][4], fal[2][4];
            uint32_t fb[2][4];   // [pair][tn0k0,tn0k8,tn1k0,tn1k8]
            #pragma unroll
            for (int tm = 0; tm < 2; tm++) {
                ldsm_x4(fa[tm],  ah_b + a_off + (uint32_t)(tm * 16 * LDSK * 2) + kko);
                ldsm_x4(fal[tm], al_b + a_off + (uint32_t)(tm * 16 * LDSK * 2) + kko);
            }
            #pragma unroll
            for (int p = 0; p < 2; p++)
                ldsm_x4(fb[p],  bh_b + b_off + (uint32_t)(p * 16 * LDSK * 2) + kko);
            // pass 1: Ah * Bh
            #pragma unroll
            for (int tm = 0; tm < 2; tm++)
                #pragma unroll
                for (int tn = 0; tn < 4; tn++)
                    mma_fp16(acc[tm][tn], fa[tm], &fb[tn >> 1][(tn & 1) * 2]);
            // pass 2: Al * Bh
            #pragma unroll
            for (int tm = 0; tm < 2; tm++)
                #pragma unroll
                for (int tn = 0; tn < 4; tn++)
                    mma_fp16(acc[tm][tn], fal[tm], &fb[tn >> 1][(tn & 1) * 2]);
        }
        __syncthreads();
    }

    const int g = lane >> 2, t4 = lane & 3;
    #pragma unroll
    for (int tm = 0; tm < 2; tm++) {
        #pragma unroll
        for (int tn = 0; tn < 4; tn++) {
            int row = blockIdx.y*128 + wm*32 + tm*16 + g;
            int col = blockIdx.x*64 + wn*32 + tn*8 + 2*t4;
            float2 c0 = {acc[tm][tn][0], acc[tm][tn][1]};
            float2 c1 = {acc[tm][tn][2], acc[tm][tn][3]};
            *(float2*)(C + (size_t)row * N + col)       = c0;
            *(float2*)(C + (size_t)(row + 8) * N + col) = c1;
        }
    }
}

// ---------------- RoPE (in-place on [NROWS, nheads*128]) --------------------------------
__global__ __launch_bounds__(256) void rope_kernel(float* __restrict__ buf, int nheads)
{
    int row = blockIdx.x;
    int s = row & (SEQ - 1);
    float* base = buf + (size_t)row * nheads * HD;
    for (int idx = threadIdx.x; idx < nheads * 64; idx += blockDim.x) {
        int hh = idx >> 6;
        int d = idx & 63;
        float inv = expf(-((float)d * (1.0f / 64.0f)) * 9.210340371976184f); // ln(10000)
        float fr = (float)s * inv;
        float sn = sinf(fr), cs = cosf(fr);
        float* p = base + hh * HD + d;
        float x1 = p[0], x2 = p[64];
        p[0]  = x1 * cs - x2 * sn;
        p[64] = x2 * cs + x1 * sn;
    }
}

// ---------------- Sliding-window GQA flash attention ------------------------------------
#define QSTR 132
#define PSTR 36
#define ATTN_SMEM_FLOATS (64*QSTR + 32*QSTR + 32*QSTR + 64*PSTR)

__global__ __launch_bounds__(256) void attn_kernel(
    const float* __restrict__ Q, const float* __restrict__ K,
    const float* __restrict__ V, float* __restrict__ O)
{
    extern __shared__ float sm[];
    float* Qs = sm;
    float* Ks = sm + 64 * QSTR;
    float* Vs = Ks + 32 * QSTR;
    float* Ps = Vs + 32 * QSTR;

    const int i0 = blockIdx.x * 64;
    const int h  = blockIdx.y;
    const int b  = blockIdx.z;
    const int hk = h >> 1;
    const int tid = threadIdx.x;
    const int r = tid >> 2, c = tid & 3;
    const float scale = 0.08838834764831845f; // 1/sqrt(128)

    #pragma unroll
    for (int it = 0; it < 8; it++) {
        int idx = tid + 256 * it;
        int rr = idx >> 5, d4 = idx & 31;
        float4 qv = *(const float4*)(Q + ((size_t)(b * SEQ + i0 + rr) * H_SIZE + h * HD + d4 * 4));
        float4 qs = {qv.x * scale, qv.y * scale, qv.z * scale, qv.w * scale};
        *(float4*)&Qs[rr * QSTR + d4 * 4] = qs;
    }

    float m = -1e30f, l = 0.f;
    float4 o[8];
    #pragma unroll
    for (int t8 = 0; t8 < 8; t8++) o[t8] = make_float4(0.f, 0.f, 0.f, 0.f);

    int jstart = i0 - (WIN - 1);
    if (jstart < 0) jstart = 0;
    jstart &= ~31;
    const int iq = i0 + r;
    const float* qrow = Qs + r * QSTR;

    for (int j0 = jstart; j0 < i0 + 64; j0 += 32) {
        __syncthreads();
        #pragma unroll
        for (int it = 0; it < 4; it++) {
            int idx = tid + 256 * it;
            int rr = idx >> 5, d4 = idx & 31;
            size_t goff = (size_t)(b * SEQ + j0 + rr) * (NKV * HD) + hk * HD + d4 * 4;
            *(float4*)&Ks[rr * QSTR + d4 * 4] = *(const float4*)(K + goff);
            *(float4*)&Vs[rr * QSTR + d4 * 4] = *(const float4*)(V + goff);
        }
        __syncthreads();

        float s[8];
        #pragma unroll
        for (int u = 0; u < 8; u++) s[u] = 0.f;
        #pragma unroll 4
        for (int d4 = 0; d4 < 32; d4++) {
            float4 qv = *(const float4*)(qrow + d4 * 4);
            #pragma unroll
            for (int u = 0; u < 8; u++) {
                float4 kv = *(const float4*)&Ks[(c + 4 * u) * QSTR + d4 * 4];
                s[u] += qv.x * kv.x + qv.y * kv.y + qv.z * kv.z + qv.w * kv.w;
            }
        }

        float mt = m;
        #pragma unroll
        for (int u = 0; u < 8; u++) {
            int j = j0 + c + 4 * u;
            bool ok = (j <= iq) && (iq - j < WIN);
            s[u] = ok ? s[u] : -1e30f;
            mt = fmaxf(mt, s[u]);
        }
        mt = fmaxf(mt, __shfl_xor_sync(0xffffffffu, mt, 1));
        mt = fmaxf(mt, __shfl_xor_sync(0xffffffffu, mt, 2));
        float alpha = __expf(m - mt);
        m = mt;
        float psum = 0.f;
        #pragma unroll
        for (int u = 0; u < 8; u++) {
            float p = __expf(s[u] - mt);
            psum += p;
            Ps[r * PSTR + c + 4 * u] = p;
        }
        l = l * alpha + psum;
        #pragma unroll
        for (int t8 = 0; t8 < 8; t8++) {
            o[t8].x *= alpha; o[t8].y *= alpha; o[t8].z *= alpha; o[t8].w *= alpha;
        }
        __syncwarp();
        #pragma unroll 4
        for (int jj = 0; jj < 32; jj++) {
            float pj = Ps[r * PSTR + jj];
            #pragma unroll
            for (int t8 = 0; t8 < 8; t8++) {
                float4 vv = *(const float4*)&Vs[jj * QSTR + (c + 4 * t8) * 4];
                o[t8].x += pj * vv.x; o[t8].y += pj * vv.y;
                o[t8].z += pj * vv.z; o[t8].w += pj * vv.w;
            }
        }
        __syncwarp();
    }

    l += __shfl_xor_sync(0xffffffffu, l, 1);
    l += __shfl_xor_sync(0xffffffffu, l, 2);
    float linv = 1.0f / l;
    float* orow = O + (size_t)(b * SEQ + i0 + r) * H_SIZE + h * HD;
    #pragma unroll
    for (int t8 = 0; t8 < 8; t8++) {
        float4 ov = {o[t8].x * linv, o[t8].y * linv, o[t8].z * linv, o[t8].w * linv};
        *(float4*)(orow + (c + 4 * t8) * 4) = ov;
    }
}

// ---------------- GeGLU elementwise: o = gelu_exact(g) * u -------------------------------
__device__ __forceinline__ float gelu_exact(float x) {
    return 0.5f * x * (1.0f + erff(x * 0.7071067811865476f));
}
__global__ __launch_bounds__(256) void geglu_kernel(
    const float* __restrict__ g, const float* __restrict__ u,
    float* __restrict__ o, int n4)
{
    int i = blockIdx.x * blockDim.x + threadIdx.x;
    int stride = gridDim.x * blockDim.x;
    for (; i < n4; i += stride) {
        float4 gv = ((const float4*)g)[i];
        float4 uv = ((const float4*)u)[i];
        float4 r;
        r.x = gelu_exact(gv.x) * uv.x;
        r.y = gelu_exact(gv.y) * uv.y;
        r.z = gelu_exact(gv.z) * uv.z;
        r.w = gelu_exact(gv.w) * uv.w;
        ((float4*)o)[i] = r;
    }
}

// ---------------- launch ----------------------------------------------------------------
extern "C" void kernel_launch(void* const* d_in, const int* in_sizes, int n_in,
                              void* d_out, int out_size)
{
    const float* x    = (const float*)d_in[0];
    const float* wq   = (const float*)d_in[1];
    const float* wk   = (const float*)d_in[2];
    const float* wv   = (const float*)d_in[3];
    const float* wo   = (const float*)d_in[4];
    const float* w_in = (const float*)d_in[5];
    const float* w_pa = (const float*)d_in[6];
    const float* w_pf = (const float*)d_in[7];
    const float* w_pff= (const float*)d_in[8];
    const float* wg   = (const float*)d_in[9];
    const float* wu   = (const float*)d_in[10];
    const float* wd   = (const float*)d_in[11];
    const float* lsc  = (const float*)d_in[12];
    float* out = (float*)d_out;

    float *h, *q, *k, *v, *attn, *attnout, *h2, *ffnin, *gate, *up, *ffnout;
    cudaGetSymbolAddress((void**)&h,       g_h);
    cudaGetSymbolAddress((void**)&q,       g_q);
    cudaGetSymbolAddress((void**)&k,       g_k);
    cudaGetSymbolAddress((void**)&v,       g_v);
    cudaGetSymbolAddress((void**)&attn,    g_attn);
    cudaGetSymbolAddress((void**)&attnout, g_attnout);
    cudaGetSymbolAddress((void**)&h2,      g_h2);
    cudaGetSymbolAddress((void**)&ffnin,   g_ffnin);
    cudaGetSymbolAddress((void**)&gate,    g_gate);
    cudaGetSymbolAddress((void**)&up,      g_up);
    cudaGetSymbolAddress((void**)&ffnout,  g_ffnout);

    const int attn_smem = ATTN_SMEM_FLOATS * (int)sizeof(float);
    cudaFuncSetAttribute(attn_kernel, cudaFuncAttributeMaxDynamicSharedMemorySize, attn_smem);

    // h = rmsnorm(x, w_in)
    rmsnorm_kernel<<<NROWS, 256>>>(x, w_in, nullptr, nullptr, h, 0);
    // QKV
    gemm_mma<<<dim3(H_SIZE/64, NROWS/128), 256>>>(h, wq, q, NROWS, H_SIZE, H_SIZE);
    gemm_mma<<<dim3((NKV*HD)/64, NROWS/128), 256>>>(h, wk, k, NROWS, NKV*HD, H_SIZE);
    gemm_mma<<<dim3((NKV*HD)/64, NROWS/128), 256>>>(h, wv, v, NROWS, NKV*HD, H_SIZE);
    // RoPE
    rope_kernel<<<NROWS, 256>>>(q, NQ);
    rope_kernel<<<NROWS, 256>>>(k, NKV);
    // attention
    attn_kernel<<<dim3(SEQ/64, NQ, BATCH), 256, attn_smem>>>(q, k, v, attn);
    // WO
    gemm_mma<<<dim3(H_SIZE/64, NROWS/128), 256>>>(attn, wo, attnout, NROWS, H_SIZE, H_SIZE);
    // h2 = x + rmsnorm(attnout, w_pa)
    rmsnorm_kernel<<<NROWS, 256>>>(attnout, w_pa, x, nullptr, h2, 1);
    // ffn_in = rmsnorm(h2, w_pf)
    rmsnorm_kernel<<<NROWS, 256>>>(h2, w_pf, nullptr, nullptr, ffnin, 0);
    // gate/up GEMMs
    gemm_mma<<<dim3(INTER_SZ/64, NROWS/128), 256>>>(ffnin, wg, gate, NROWS, INTER_SZ, H_SIZE);
    gemm_mma<<<dim3(INTER_SZ/64, NROWS/128), 256>>>(ffnin, wu, up, NROWS, INTER_SZ, H_SIZE);
    // act = gelu(gate) * up   (into gate)
    geglu_kernel<<<8192, 256>>>(gate, up, gate, (NROWS * INTER_SZ) / 4);
    // down projection
    gemm_mma<<<dim3(H_SIZE/64, NROWS/128), 256>>>(gate, wd, ffnout, NROWS, H_SIZE, INTER_SZ);
    // out = (h2 + rmsnorm(ffnout, w_pff)) * layer_scalar
    rmsnorm_kernel<<<NROWS, 256>>>(ffnout, w_pff, h2, lsc, out, 2);
}

// round 10
// speedup vs baseline: 1.3986x; 1.0680x over previous
#include <cuda_runtime.h>
#include <cuda_fp16.h>
#include <stdint.h>
#include <math.h>

#define H_SIZE 2048
#define INTER_SZ 8192
#define NQ 16
#define NKV 8
#define HD 128
#define SEQ 2048
#define BATCH 2
#define NROWS (BATCH*SEQ)
#define WIN 1024

// ---------------- scratch (module-scope device globals; no runtime alloc) ----------------
__device__ float g_h[NROWS*H_SIZE];
__device__ float g_q[NROWS*H_SIZE];
__device__ float g_k[NROWS*NKV*HD];
__device__ float g_v[NROWS*NKV*HD];
__device__ float g_attn[NROWS*H_SIZE];
__device__ float g_attnout[NROWS*H_SIZE];
__device__ float g_h2[NROWS*H_SIZE];
__device__ float g_ffnin[NROWS*H_SIZE];
__device__ float g_gate[NROWS*INTER_SZ];
__device__ float g_up[NROWS*INTER_SZ];
__device__ float g_ffnout[NROWS*H_SIZE];

// ---------------- RMSNorm (mode 0: norm; 1: res + norm; 2: (res + norm)*scalar) ----------
__global__ __launch_bounds__(256) void rmsnorm_kernel(
    const float* __restrict__ in, const float* __restrict__ w,
    const float* __restrict__ res, const float* __restrict__ scal,
    float* __restrict__ out, int mode)
{
    int row = blockIdx.x;
    int t = threadIdx.x;
    const float4* ip = (const float4*)(in + (size_t)row * H_SIZE);
    float4 v0 = ip[t];
    float4 v1 = ip[t + 256];
    float ss = v0.x*v0.x + v0.y*v0.y + v0.z*v0.z + v0.w*v0.w
             + v1.x*v1.x + v1.y*v1.y + v1.z*v1.z + v1.w*v1.w;
    #pragma unroll
    for (int o = 16; o; o >>= 1) ss += __shfl_xor_sync(0xffffffffu, ss, o);
    __shared__ float red[8];
    if ((t & 31) == 0) red[t >> 5] = ss;
    __syncthreads();
    float tot = red[0]+red[1]+red[2]+red[3]+red[4]+red[5]+red[6]+red[7];
    float inv = rsqrtf(tot * (1.0f / H_SIZE) + 1e-6f);

    const float4* w4 = (const float4*)w;
    float4 w0 = w4[t], w1 = w4[t + 256];
    float4 o0, o1;
    o0.x = v0.x*inv*w0.x; o0.y = v0.y*inv*w0.y; o0.z = v0.z*inv*w0.z; o0.w = v0.w*inv*w0.w;
    o1.x = v1.x*inv*w1.x; o1.y = v1.y*inv*w1.y; o1.z = v1.z*inv*w1.z; o1.w = v1.w*inv*w1.w;
    if (mode >= 1) {
        const float4* rp = (const float4*)(res + (size_t)row * H_SIZE);
        float4 r0 = rp[t], r1 = rp[t + 256];
        o0.x += r0.x; o0.y += r0.y; o0.z += r0.z; o0.w += r0.w;
        o1.x += r1.x; o1.y += r1.y; o1.z += r1.z; o1.w += r1.w;
    }
    if (mode == 2) {
        float sc = scal[0];
        o0.x *= sc; o0.y *= sc; o0.z *= sc; o0.w *= sc;
        o1.x *= sc; o1.y *= sc; o1.z *= sc; o1.w *= sc;
    }
    float4* op = (float4*)(out + (size_t)row * H_SIZE);
    op[t] = o0;
    op[t + 256] = o1;
}

// ---------------- Tensor-core GEMM: C[M,N] = A[M,K] * B[N,K]^T  (fp16 split-A, 2 pass) ---
// Block 128x128, BK=32, 256 threads = 8 warps in 4(m) x 2(n), warp tile 32x64.
// bytes/MMA from smem: 512/tn + 128/tm = 128 (vs 192 at 32x32). 2 CTAs/SM.
// No gmem prefetch registers: direct LDG per k0; co-resident CTA covers latency.

#define LDSK 40   // padded row stride in halfs

__device__ __forceinline__ void mma_fp16(float* c, const uint32_t* a, const uint32_t* b) {
    asm volatile(
        "mma.sync.aligned.m16n8k16.row.col.f32.f16.f16.f32 "
        "{%0,%1,%2,%3}, {%4,%5,%6,%7}, {%8,%9}, {%0,%1,%2,%3};\n"
        : "+f"(c[0]), "+f"(c[1]), "+f"(c[2]), "+f"(c[3])
        : "r"(a[0]), "r"(a[1]), "r"(a[2]), "r"(a[3]), "r"(b[0]), "r"(b[1]));
}

__device__ __forceinline__ void ldsm_x4(uint32_t* r, uint32_t addr) {
    asm volatile("ldmatrix.sync.aligned.m8n8.x4.shared.b16 {%0,%1,%2,%3}, [%4];"
        : "=r"(r[0]), "=r"(r[1]), "=r"(r[2]), "=r"(r[3]) : "r"(addr));
}

// fp32 -> (hi, lo) fp16 planes
__device__ __forceinline__ void cvt_store_a(__half* sh, __half* sl, float4 v) {
    __half hx = __float2half(v.x), hy = __float2half(v.y);
    __half hz = __float2half(v.z), hw = __float2half(v.w);
    __half lx = __float2half(v.x - __half2float(hx));
    __half ly = __float2half(v.y - __half2float(hy));
    __half lz = __float2half(v.z - __half2float(hz));
    __half lw = __float2half(v.w - __half2float(hw));
    *(__half2*)(sh)     = __halves2half2(hx, hy);
    *(__half2*)(sh + 2) = __halves2half2(hz, hw);
    *(__half2*)(sl)     = __halves2half2(lx, ly);
    *(__half2*)(sl + 2) = __halves2half2(lz, lw);
}
// fp32 -> single fp16 plane
__device__ __forceinline__ void cvt_store_b(__half* sh, float4 v) {
    *(__half2*)(sh)     = __halves2half2(__float2half(v.x), __float2half(v.y));
    *(__half2*)(sh + 2) = __halves2half2(__float2half(v.z), __float2half(v.w));
}

__global__ __launch_bounds__(256, 2) void gemm_mma(
    const float* __restrict__ A, const float* __restrict__ B,
    float* __restrict__ C, int M, int N, int K)
{
    __shared__ __align__(16) __half Ahs[128*LDSK];
    __shared__ __align__(16) __half Als[128*LDSK];
    __shared__ __align__(16) __half Bhs[128*LDSK];

    const int tid  = threadIdx.x;
    const int warp = tid >> 5, lane = tid & 31;
    const int wm = warp >> 1, wn = warp & 1;   // 4 x 2 warp grid, warp tile 32x64

    const float* Ab = A + (size_t)blockIdx.y * 128 * K;
    const float* Bb = B + (size_t)blockIdx.x * 128 * K;

    const int lrow = tid >> 3;        // 0..31
    const int lcol = (tid & 7) * 4;   // 0..28

    const uint32_t ah_b = (uint32_t)__cvta_generic_to_shared(Ahs);
    const uint32_t al_b = (uint32_t)__cvta_generic_to_shared(Als);
    const uint32_t bh_b = (uint32_t)__cvta_generic_to_shared(Bhs);
    // A tile: lanes 0-15 -> rows, lanes 16-31 -> k+8 half
    const uint32_t a_off = (uint32_t)(((wm*32 + (lane & 15)) * LDSK + ((lane >> 4) * 8)) * 2);
    // B tiles (two n8 tiles per x4): lane>>4 -> tile, (lane>>3)&1 -> k half
    const uint32_t b_off = (uint32_t)(((wn*64 + ((lane >> 4) * 8) + (lane & 7)) * LDSK
                                       + (((lane >> 3) & 1) * 8)) * 2);

    float acc[2][8][4];
    #pragma unroll
    for (int i = 0; i < 2; i++)
        #pragma unroll
        for (int j = 0; j < 8; j++)
            #pragma unroll
            for (int q = 0; q < 4; q++) acc[i][j][q] = 0.f;

    for (int k0 = 0; k0 < K; k0 += 32) {
        // stage fp32 -> fp16 planes (A hi/lo, B hi), no prefetch registers
        #pragma unroll
        for (int i = 0; i < 4; i++) {
            float4 v = *(const float4*)(Ab + (size_t)(lrow + 32*i) * K + k0 + lcol);
            int off = (lrow + 32*i) * LDSK + lcol;
            cvt_store_a(Ahs + off, Als + off, v);
        }
        #pragma unroll
        for (int i = 0; i < 4; i++) {
            float4 v = *(const float4*)(Bb + (size_t)(lrow + 32*i) * K + k0 + lcol);
            int off = (lrow + 32*i) * LDSK + lcol;
            cvt_store_b(Bhs + off, v);
        }
        __syncthreads();

        #pragma unroll
        for (int kk = 0; kk < 32; kk += 16) {
            const uint32_t kko = kk * 2;
            uint32_t fa[2][4], fal[2][4];
            uint32_t fb[4][4];   // [pair][tn0k0,tn0k8,tn1k0,tn1k8]
            #pragma unroll
            for (int tm = 0; tm < 2; tm++) {
                ldsm_x4(fa[tm],  ah_b + a_off + (uint32_t)(tm * 16 * LDSK * 2) + kko);
                ldsm_x4(fal[tm], al_b + a_off + (uint32_t)(tm * 16 * LDSK * 2) + kko);
            }
            #pragma unroll
            for (int p = 0; p < 4; p++)
                ldsm_x4(fb[p],  bh_b + b_off + (uint32_t)(p * 16 * LDSK * 2) + kko);
            // pass 1: Ah * Bh
            #pragma unroll
            for (int tm = 0; tm < 2; tm++)
                #pragma unroll
                for (int tn = 0; tn < 8; tn++)
                    mma_fp16(acc[tm][tn], fa[tm], &fb[tn >> 1][(tn & 1) * 2]);
            // pass 2: Al * Bh
            #pragma unroll
            for (int tm = 0; tm < 2; tm++)
                #pragma unroll
                for (int tn = 0; tn < 8; tn++)
                    mma_fp16(acc[tm][tn], fal[tm], &fb[tn >> 1][(tn & 1) * 2]);
        }
        __syncthreads();
    }

    const int g = lane >> 2, t4 = lane & 3;
    #pragma unroll
    for (int tm = 0; tm < 2; tm++) {
        #pragma unroll
        for (int tn = 0; tn < 8; tn++) {
            int row = blockIdx.y*128 + wm*32 + tm*16 + g;
            int col = blockIdx.x*128 + wn*64 + tn*8 + 2*t4;
            float2 c0 = {acc[tm][tn][0], acc[tm][tn][1]};
            float2 c1 = {acc[tm][tn][2], acc[tm][tn][3]};
            *(float2*)(C + (size_t)row * N + col)       = c0;
            *(float2*)(C + (size_t)(row + 8) * N + col) = c1;
        }
    }
}

// ---------------- RoPE (in-place on [NROWS, nheads*128]) --------------------------------
__global__ __launch_bounds__(256) void rope_kernel(float* __restrict__ buf, int nheads)
{
    int row = blockIdx.x;
    int s = row & (SEQ - 1);
    float* base = buf + (size_t)row * nheads * HD;
    for (int idx = threadIdx.x; idx < nheads * 64; idx += blockDim.x) {
        int hh = idx >> 6;
        int d = idx & 63;
        float inv = expf(-((float)d * (1.0f / 64.0f)) * 9.210340371976184f); // ln(10000)
        float fr = (float)s * inv;
        float sn = sinf(fr), cs = cosf(fr);
        float* p = base + hh * HD + d;
        float x1 = p[0], x2 = p[64];
        p[0]  = x1 * cs - x2 * sn;
        p[64] = x2 * cs + x1 * sn;
    }
}

// ---------------- Sliding-window GQA flash attention ------------------------------------
#define QSTR 132
#define PSTR 36
#define ATTN_SMEM_FLOATS (64*QSTR + 32*QSTR + 32*QSTR + 64*PSTR)

__global__ __launch_bounds__(256) void attn_kernel(
    const float* __restrict__ Q, const float* __restrict__ K,
    const float* __restrict__ V, float* __restrict__ O)
{
    extern __shared__ float sm[];
    float* Qs = sm;
    float* Ks = sm + 64 * QSTR;
    float* Vs = Ks + 32 * QSTR;
    float* Ps = Vs + 32 * QSTR;

    const int i0 = blockIdx.x * 64;
    const int h  = blockIdx.y;
    const int b  = blockIdx.z;
    const int hk = h >> 1;
    const int tid = threadIdx.x;
    const int r = tid >> 2, c = tid & 3;
    const float scale = 0.08838834764831845f; // 1/sqrt(128)

    #pragma unroll
    for (int it = 0; it < 8; it++) {
        int idx = tid + 256 * it;
        int rr = idx >> 5, d4 = idx & 31;
        float4 qv = *(const float4*)(Q + ((size_t)(b * SEQ + i0 + rr) * H_SIZE + h * HD + d4 * 4));
        float4 qs = {qv.x * scale, qv.y * scale, qv.z * scale, qv.w * scale};
        *(float4*)&Qs[rr * QSTR + d4 * 4] = qs;
    }

    float m = -1e30f, l = 0.f;
    float4 o[8];
    #pragma unroll
    for (int t8 = 0; t8 < 8; t8++) o[t8] = make_float4(0.f, 0.f, 0.f, 0.f);

    int jstart = i0 - (WIN - 1);
    if (jstart < 0) jstart = 0;
    jstart &= ~31;
    const int iq = i0 + r;
    const float* qrow = Qs + r * QSTR;

    for (int j0 = jstart; j0 < i0 + 64; j0 += 32) {
        __syncthreads();
        #pragma unroll
        for (int it = 0; it < 4; it++) {
            int idx = tid + 256 * it;
            int rr = idx >> 5, d4 = idx & 31;
            size_t goff = (size_t)(b * SEQ + j0 + rr) * (NKV * HD) + hk * HD + d4 * 4;
            *(float4*)&Ks[rr * QSTR + d4 * 4] = *(const float4*)(K + goff);
            *(float4*)&Vs[rr * QSTR + d4 * 4] = *(const float4*)(V + goff);
        }
        __syncthreads();

        float s[8];
        #pragma unroll
        for (int u = 0; u < 8; u++) s[u] = 0.f;
        #pragma unroll 4
        for (int d4 = 0; d4 < 32; d4++) {
            float4 qv = *(const float4*)(qrow + d4 * 4);
            #pragma unroll
            for (int u = 0; u < 8; u++) {
                float4 kv = *(const float4*)&Ks[(c + 4 * u) * QSTR + d4 * 4];
                s[u] += qv.x * kv.x + qv.y * kv.y + qv.z * kv.z + qv.w * kv.w;
            }
        }

        float mt = m;
        #pragma unroll
        for (int u = 0; u < 8; u++) {
            int j = j0 + c + 4 * u;
            bool ok = (j <= iq) && (iq - j < WIN);
            s[u] = ok ? s[u] : -1e30f;
            mt = fmaxf(mt, s[u]);
        }
        mt = fmaxf(mt, __shfl_xor_sync(0xffffffffu, mt, 1));
        mt = fmaxf(mt, __shfl_xor_sync(0xffffffffu, mt, 2));
        float alpha = __expf(m - mt);
        m = mt;
        float psum = 0.f;
        #pragma unroll
        for (int u = 0; u < 8; u++) {
            float p = __expf(s[u] - mt);
            psum += p;
            Ps[r * PSTR + c + 4 * u] = p;
        }
        l = l * alpha + psum;
        #pragma unroll
        for (int t8 = 0; t8 < 8; t8++) {
            o[t8].x *= alpha; o[t8].y *= alpha; o[t8].z *= alpha; o[t8].w *= alpha;
        }
        __syncwarp();
        #pragma unroll 4
        for (int jj = 0; jj < 32; jj++) {
            float pj = Ps[r * PSTR + jj];
            #pragma unroll
            for (int t8 = 0; t8 < 8; t8++) {
                float4 vv = *(const float4*)&Vs[jj * QSTR + (c + 4 * t8) * 4];
                o[t8].x += pj * vv.x; o[t8].y += pj * vv.y;
                o[t8].z += pj * vv.z; o[t8].w += pj * vv.w;
            }
        }
        __syncwarp();
    }

    l += __shfl_xor_sync(0xffffffffu, l, 1);
    l += __shfl_xor_sync(0xffffffffu, l, 2);
    float linv = 1.0f / l;
    float* orow = O + (size_t)(b * SEQ + i0 + r) * H_SIZE + h * HD;
    #pragma unroll
    for (int t8 = 0; t8 < 8; t8++) {
        float4 ov = {o[t8].x * linv, o[t8].y * linv, o[t8].z * linv, o[t8].w * linv};
        *(float4*)(orow + (c + 4 * t8) * 4) = ov;
    }
}

// ---------------- GeGLU elementwise: o = gelu_exact(g) * u -------------------------------
__device__ __forceinline__ float gelu_exact(float x) {
    return 0.5f * x * (1.0f + erff(x * 0.7071067811865476f));
}
__global__ __launch_bounds__(256) void geglu_kernel(
    const float* __restrict__ g, const float* __restrict__ u,
    float* __restrict__ o, int n4)
{
    int i = blockIdx.x * blockDim.x + threadIdx.x;
    int stride = gridDim.x * blockDim.x;
    for (; i < n4; i += stride) {
        float4 gv = ((const float4*)g)[i];
        float4 uv = ((const float4*)u)[i];
        float4 r;
        r.x = gelu_exact(gv.x) * uv.x;
        r.y = gelu_exact(gv.y) * uv.y;
        r.z = gelu_exact(gv.z) * uv.z;
        r.w = gelu_exact(gv.w) * uv.w;
        ((float4*)o)[i] = r;
    }
}

// ---------------- launch ----------------------------------------------------------------
extern "C" void kernel_launch(void* const* d_in, const int* in_sizes, int n_in,
                              void* d_out, int out_size)
{
    const float* x    = (const float*)d_in[0];
    const float* wq   = (const float*)d_in[1];
    const float* wk   = (const float*)d_in[2];
    const float* wv   = (const float*)d_in[3];
    const float* wo   = (const float*)d_in[4];
    const float* w_in = (const float*)d_in[5];
    const float* w_pa = (const float*)d_in[6];
    const float* w_pf = (const float*)d_in[7];
    const float* w_pff= (const float*)d_in[8];
    const float* wg   = (const float*)d_in[9];
    const float* wu   = (const float*)d_in[10];
    const float* wd   = (const float*)d_in[11];
    const float* lsc  = (const float*)d_in[12];
    float* out = (float*)d_out;

    float *h, *q, *k, *v, *attn, *attnout, *h2, *ffnin, *gate, *up, *ffnout;
    cudaGetSymbolAddress((void**)&h,       g_h);
    cudaGetSymbolAddress((void**)&q,       g_q);
    cudaGetSymbolAddress((void**)&k,       g_k);
    cudaGetSymbolAddress((void**)&v,       g_v);
    cudaGetSymbolAddress((void**)&attn,    g_attn);
    cudaGetSymbolAddress((void**)&attnout, g_attnout);
    cudaGetSymbolAddress((void**)&h2,      g_h2);
    cudaGetSymbolAddress((void**)&ffnin,   g_ffnin);
    cudaGetSymbolAddress((void**)&gate,    g_gate);
    cudaGetSymbolAddress((void**)&up,      g_up);
    cudaGetSymbolAddress((void**)&ffnout,  g_ffnout);

    const int attn_smem = ATTN_SMEM_FLOATS * (int)sizeof(float);
    cudaFuncSetAttribute(attn_kernel, cudaFuncAttributeMaxDynamicSharedMemorySize, attn_smem);

    // h = rmsnorm(x, w_in)
    rmsnorm_kernel<<<NROWS, 256>>>(x, w_in, nullptr, nullptr, h, 0);
    // QKV
    gemm_mma<<<dim3(H_SIZE/128, NROWS/128), 256>>>(h, wq, q, NROWS, H_SIZE, H_SIZE);
    gemm_mma<<<dim3((NKV*HD)/128, NROWS/128), 256>>>(h, wk, k, NROWS, NKV*HD, H_SIZE);
    gemm_mma<<<dim3((NKV*HD)/128, NROWS/128), 256>>>(h, wv, v, NROWS, NKV*HD, H_SIZE);
    // RoPE
    rope_kernel<<<NROWS, 256>>>(q, NQ);
    rope_kernel<<<NROWS, 256>>>(k, NKV);
    // attention
    attn_kernel<<<dim3(SEQ/64, NQ, BATCH), 256, attn_smem>>>(q, k, v, attn);
    // WO
    gemm_mma<<<dim3(H_SIZE/128, NROWS/128), 256>>>(attn, wo, attnout, NROWS, H_SIZE, H_SIZE);
    // h2 = x + rmsnorm(attnout, w_pa)
    rmsnorm_kernel<<<NROWS, 256>>>(attnout, w_pa, x, nullptr, h2, 1);
    // ffn_in = rmsnorm(h2, w_pf)
    rmsnorm_kernel<<<NROWS, 256>>>(h2, w_pf, nullptr, nullptr, ffnin, 0);
    // gate/up GEMMs
    gemm_mma<<<dim3(INTER_SZ/128, NROWS/128), 256>>>(ffnin, wg, gate, NROWS, INTER_SZ, H_SIZE);
    gemm_mma<<<dim3(INTER_SZ/128, NROWS/128), 256>>>(ffnin, wu, up, NROWS, INTER_SZ, H_SIZE);
    // act = gelu(gate) * up   (into gate)
    geglu_kernel<<<8192, 256>>>(gate, up, gate, (NROWS * INTER_SZ) / 4);
    // down projection
    gemm_mma<<<dim3(H_SIZE/128, NROWS/128), 256>>>(gate, wd, ffnout, NROWS, H_SIZE, INTER_SZ);
    // out = (h2 + rmsnorm(ffnout, w_pff)) * layer_scalar
    rmsnorm_kernel<<<NROWS, 256>>>(ffnout, w_pff, h2, lsc, out, 2);
}

// round 11
// speedup vs baseline: 1.4688x; 1.0502x over previous
#include <cuda_runtime.h>
#include <cuda_fp16.h>
#include <stdint.h>
#include <math.h>

#define H_SIZE 2048
#define INTER_SZ 8192
#define NQ 16
#define NKV 8
#define HD 128
#define SEQ 2048
#define BATCH 2
#define NROWS (BATCH*SEQ)
#define WIN 1024

// ---------------- fp32 scratch ----------------
__device__ float g_q[NROWS*H_SIZE];
__device__ float g_k[NROWS*NKV*HD];
__device__ float g_v[NROWS*NKV*HD];
__device__ float g_attnout[NROWS*H_SIZE];
__device__ float g_h2[NROWS*H_SIZE];
__device__ float g_gate[NROWS*INTER_SZ];
__device__ float g_up[NROWS*INTER_SZ];
__device__ float g_ffnout[NROWS*H_SIZE];

// ---------------- fp16 planes ----------------
// activations: hi/lo (A operand, 2-pass)
__device__ __half g_h_h[NROWS*H_SIZE],      g_h_l[NROWS*H_SIZE];
__device__ __half g_attn_h[NROWS*H_SIZE],   g_attn_l[NROWS*H_SIZE];
__device__ __half g_ffnin_h[NROWS*H_SIZE],  g_ffnin_l[NROWS*H_SIZE];
__device__ __half g_gact_h[NROWS*INTER_SZ], g_gact_l[NROWS*INTER_SZ];
// weights: single fp16 plane (B operand)
__device__ __half g_wq[H_SIZE*H_SIZE];
__device__ __half g_wk[NKV*HD*H_SIZE];
__device__ __half g_wv[NKV*HD*H_SIZE];
__device__ __half g_wo[H_SIZE*H_SIZE];
__device__ __half g_wg[INTER_SZ*H_SIZE];
__device__ __half g_wu[INTER_SZ*H_SIZE];
__device__ __half g_wd[H_SIZE*INTER_SZ];

// ---------------- helpers ----------------
__device__ __forceinline__ void split2h(float a, float b, __half* hi, __half* lo) {
    __half ha = __float2half(a), hb = __float2half(b);
    __half la = __float2half(a - __half2float(ha));
    __half lb = __float2half(b - __half2float(hb));
    *(__half2*)hi = __halves2half2(ha, hb);
    *(__half2*)lo = __halves2half2(la, lb);
}

// weights: fp32 -> fp16 single plane
__global__ __launch_bounds__(256) void wsplit_kernel(
    const float* __restrict__ in, __half* __restrict__ out, int n4)
{
    int i = blockIdx.x * blockDim.x + threadIdx.x;
    int stride = gridDim.x * blockDim.x;
    for (; i < n4; i += stride) {
        float4 v = ((const float4*)in)[i];
        *(__half2*)(out + i*4)     = __halves2half2(__float2half(v.x), __float2half(v.y));
        *(__half2*)(out + i*4 + 2) = __halves2half2(__float2half(v.z), __float2half(v.w));
    }
}

// ---------------- RMSNorm fp32 out (mode 1: res+norm; 2: (res+norm)*scalar) -------------
__global__ __launch_bounds__(256) void rmsnorm_kernel(
    const float* __restrict__ in, const float* __restrict__ w,
    const float* __restrict__ res, const float* __restrict__ scal,
    float* __restrict__ out, int mode)
{
    int row = blockIdx.x;
    int t = threadIdx.x;
    const float4* ip = (const float4*)(in + (size_t)row * H_SIZE);
    float4 v0 = ip[t];
    float4 v1 = ip[t + 256];
    float ss = v0.x*v0.x + v0.y*v0.y + v0.z*v0.z + v0.w*v0.w
             + v1.x*v1.x + v1.y*v1.y + v1.z*v1.z + v1.w*v1.w;
    #pragma unroll
    for (int o = 16; o; o >>= 1) ss += __shfl_xor_sync(0xffffffffu, ss, o);
    __shared__ float red[8];
    if ((t & 31) == 0) red[t >> 5] = ss;
    __syncthreads();
    float tot = red[0]+red[1]+red[2]+red[3]+red[4]+red[5]+red[6]+red[7];
    float inv = rsqrtf(tot * (1.0f / H_SIZE) + 1e-6f);

    const float4* w4 = (const float4*)w;
    float4 w0 = w4[t], w1 = w4[t + 256];
    float4 o0, o1;
    o0.x = v0.x*inv*w0.x; o0.y = v0.y*inv*w0.y; o0.z = v0.z*inv*w0.z; o0.w = v0.w*inv*w0.w;
    o1.x = v1.x*inv*w1.x; o1.y = v1.y*inv*w1.y; o1.z = v1.z*inv*w1.z; o1.w = v1.w*inv*w1.w;
    if (mode >= 1) {
        const float4* rp = (const float4*)(res + (size_t)row * H_SIZE);
        float4 r0 = rp[t], r1 = rp[t + 256];
        o0.x += r0.x; o0.y += r0.y; o0.z += r0.z; o0.w += r0.w;
        o1.x += r1.x; o1.y += r1.y; o1.z += r1.z; o1.w += r1.w;
    }
    if (mode == 2) {
        float sc = scal[0];
        o0.x *= sc; o0.y *= sc; o0.z *= sc; o0.w *= sc;
        o1.x *= sc; o1.y *= sc; o1.z *= sc; o1.w *= sc;
    }
    float4* op = (float4*)(out + (size_t)row * H_SIZE);
    op[t] = o0;
    op[t + 256] = o1;
}

// ---------------- RMSNorm -> fp16 hi/lo planes ----------------
__global__ __launch_bounds__(256) void rmsnorm_split_kernel(
    const float* __restrict__ in, const float* __restrict__ w,
    __half* __restrict__ oh, __half* __restrict__ ol)
{
    int row = blockIdx.x;
    int t = threadIdx.x;
    const float4* ip = (const float4*)(in + (size_t)row * H_SIZE);
    float4 v0 = ip[t];
    float4 v1 = ip[t + 256];
    float ss = v0.x*v0.x + v0.y*v0.y + v0.z*v0.z + v0.w*v0.w
             + v1.x*v1.x + v1.y*v1.y + v1.z*v1.z + v1.w*v1.w;
    #pragma unroll
    for (int o = 16; o; o >>= 1) ss += __shfl_xor_sync(0xffffffffu, ss, o);
    __shared__ float red[8];
    if ((t & 31) == 0) red[t >> 5] = ss;
    __syncthreads();
    float tot = red[0]+red[1]+red[2]+red[3]+red[4]+red[5]+red[6]+red[7];
    float inv = rsqrtf(tot * (1.0f / H_SIZE) + 1e-6f);

    const float4* w4 = (const float4*)w;
    float4 w0 = w4[t], w1 = w4[t + 256];
    size_t base = (size_t)row * H_SIZE;
    split2h(v0.x*inv*w0.x, v0.y*inv*w0.y, oh + base + t*4,     ol + base + t*4);
    split2h(v0.z*inv*w0.z, v0.w*inv*w0.w, oh + base + t*4 + 2, ol + base + t*4 + 2);
    split2h(v1.x*inv*w1.x, v1.y*inv*w1.y, oh + base + 1024 + t*4,     ol + base + 1024 + t*4);
    split2h(v1.z*inv*w1.z, v1.w*inv*w1.w, oh + base + 1024 + t*4 + 2, ol + base + 1024 + t*4 + 2);
}

// ---------------- Tensor-core GEMM on fp16 planes, cp.async double-buffered --------------
// C[M,N] = (Ah+Al)[M,K] * Bh[N,K]^T, 2 passes. Block 128x128, BK=32, warp tile 32x64.
// 2 stages x (Ah|Al|Bh) x 128 rows x LDSK halfs. 2 CTAs/SM.

#define LDSK 40
#define PLANE_H (128*LDSK)
#define STAGE_H (3*PLANE_H)
#define GEMM_SMEM (2*STAGE_H*2)   // bytes

__device__ __forceinline__ void mma_fp16(float* c, const uint32_t* a, const uint32_t* b) {
    asm volatile(
        "mma.sync.aligned.m16n8k16.row.col.f32.f16.f16.f32 "
        "{%0,%1,%2,%3}, {%4,%5,%6,%7}, {%8,%9}, {%0,%1,%2,%3};\n"
        : "+f"(c[0]), "+f"(c[1]), "+f"(c[2]), "+f"(c[3])
        : "r"(a[0]), "r"(a[1]), "r"(a[2]), "r"(a[3]), "r"(b[0]), "r"(b[1]));
}

__device__ __forceinline__ void ldsm_x4(uint32_t* r, uint32_t addr) {
    asm volatile("ldmatrix.sync.aligned.m8n8.x4.shared.b16 {%0,%1,%2,%3}, [%4];"
        : "=r"(r[0]), "=r"(r[1]), "=r"(r[2]), "=r"(r[3]) : "r"(addr));
}

__device__ __forceinline__ void cp16(uint32_t dst, const void* src) {
    asm volatile("cp.async.cg.shared.global [%0], [%1], 16;\n" :: "r"(dst), "l"(src));
}

__global__ __launch_bounds__(256, 2) void gemm_mma(
    const __half* __restrict__ Agh, const __half* __restrict__ Agl,
    const __half* __restrict__ Bgh,
    float* __restrict__ C, int M, int N, int K)
{
    extern __shared__ __align__(16) __half smp[];

    const int tid  = threadIdx.x;
    const int warp = tid >> 5, lane = tid & 31;
    const int wm = warp >> 1, wn = warp & 1;   // 4 x 2 warp grid, warp tile 32x64
    const int rowA = blockIdx.y * 128;
    const int colB = blockIdx.x * 128;

    const uint32_t smb = (uint32_t)__cvta_generic_to_shared(smp);
    // fragment offsets (bytes) within a plane
    const uint32_t a_off = (uint32_t)(((wm*32 + (lane & 15)) * LDSK + ((lane >> 4) * 8)) * 2);
    const uint32_t b_off = (uint32_t)(((wn*64 + ((lane >> 4) * 8) + (lane & 7)) * LDSK
                                       + (((lane >> 3) & 1) * 8)) * 2);

    float acc[2][8][4];
    #pragma unroll
    for (int i = 0; i < 2; i++)
        #pragma unroll
        for (int j = 0; j < 8; j++)
            #pragma unroll
            for (int q = 0; q < 4; q++) acc[i][j][q] = 0.f;

    // 6 x 16B chunks per thread per stage: 3 planes x 128 rows x 4 chunks
    #define CP_STAGE(s, k0)                                                        \
    {                                                                              \
        _Pragma("unroll")                                                          \
        for (int i = 0; i < 6; i++) {                                              \
            int cidx = tid + 256 * i;                                              \
            int plane = cidx >> 9;                                                 \
            int cc = cidx & 511;                                                   \
            int row = cc >> 2;                                                     \
            int ch = cc & 3;                                                       \
            const __half* src =                                                    \
                (plane == 0) ? Agh + (size_t)(rowA + row) * K :                    \
                (plane == 1) ? Agl + (size_t)(rowA + row) * K :                    \
                               Bgh + (size_t)(colB + row) * K;                     \
            uint32_t dst = smb +                                                   \
                (uint32_t)(((s) * STAGE_H + plane * PLANE_H + row * LDSK + ch * 8) * 2); \
            cp16(dst, src + (k0) + ch * 8);                                        \
        }                                                                          \
        asm volatile("cp.async.commit_group;\n" ::: "memory");                     \
    }

    const int NC = K >> 5;
    CP_STAGE(0, 0);
    for (int c = 0; c < NC; c++) {
        int s = c & 1;
        if (c + 1 < NC) {
            CP_STAGE(s ^ 1, (c + 1) * 32);
            asm volatile("cp.async.wait_group 1;\n" ::: "memory");
        } else {
            asm volatile("cp.async.wait_group 0;\n" ::: "memory");
        }
        __syncthreads();

        const uint32_t ah_b = smb + (uint32_t)((s * STAGE_H) * 2);
        const uint32_t al_b = ah_b + (uint32_t)(PLANE_H * 2);
        const uint32_t bh_b = al_b + (uint32_t)(PLANE_H * 2);

        #pragma unroll
        for (int kk = 0; kk < 32; kk += 16) {
            const uint32_t kko = kk * 2;
            uint32_t fa[2][4], fal[2][4];
            uint32_t fb[4][4];
            #pragma unroll
            for (int tm = 0; tm < 2; tm++) {
                ldsm_x4(fa[tm],  ah_b + a_off + (uint32_t)(tm * 16 * LDSK * 2) + kko);
                ldsm_x4(fal[tm], al_b + a_off + (uint32_t)(tm * 16 * LDSK * 2) + kko);
            }
            #pragma unroll
            for (int p = 0; p < 4; p++)
                ldsm_x4(fb[p],  bh_b + b_off + (uint32_t)(p * 16 * LDSK * 2) + kko);
            #pragma unroll
            for (int tm = 0; tm < 2; tm++)
                #pragma unroll
                for (int tn = 0; tn < 8; tn++)
                    mma_fp16(acc[tm][tn], fa[tm], &fb[tn >> 1][(tn & 1) * 2]);
            #pragma unroll
            for (int tm = 0; tm < 2; tm++)
                #pragma unroll
                for (int tn = 0; tn < 8; tn++)
                    mma_fp16(acc[tm][tn], fal[tm], &fb[tn >> 1][(tn & 1) * 2]);
        }
        __syncthreads();
    }

    const int g = lane >> 2, t4 = lane & 3;
    #pragma unroll
    for (int tm = 0; tm < 2; tm++) {
        #pragma unroll
        for (int tn = 0; tn < 8; tn++) {
            int row = blockIdx.y*128 + wm*32 + tm*16 + g;
            int col = blockIdx.x*128 + wn*64 + tn*8 + 2*t4;
            float2 c0 = {acc[tm][tn][0], acc[tm][tn][1]};
            float2 c1 = {acc[tm][tn][2], acc[tm][tn][3]};
            *(float2*)(C + (size_t)row * N + col)       = c0;
            *(float2*)(C + (size_t)(row + 8) * N + col) = c1;
        }
    }
}

// ---------------- RoPE (in-place on [NROWS, nheads*128]) --------------------------------
__global__ __launch_bounds__(256) void rope_kernel(float* __restrict__ buf, int nheads)
{
    int row = blockIdx.x;
    int s = row & (SEQ - 1);
    float* base = buf + (size_t)row * nheads * HD;
    for (int idx = threadIdx.x; idx < nheads * 64; idx += blockDim.x) {
        int hh = idx >> 6;
        int d = idx & 63;
        float inv = expf(-((float)d * (1.0f / 64.0f)) * 9.210340371976184f); // ln(10000)
        float fr = (float)s * inv;
        float sn = sinf(fr), cs = cosf(fr);
        float* p = base + hh * HD + d;
        float x1 = p[0], x2 = p[64];
        p[0]  = x1 * cs - x2 * sn;
        p[64] = x2 * cs + x1 * sn;
    }
}

// ---------------- Sliding-window GQA flash attention (out: fp16 hi/lo planes) ------------
#define QSTR 132
#define PSTR 36
#define ATTN_SMEM_FLOATS (64*QSTR + 32*QSTR + 32*QSTR + 64*PSTR)

__global__ __launch_bounds__(256) void attn_kernel(
    const float* __restrict__ Q, const float* __restrict__ K,
    const float* __restrict__ V, __half* __restrict__ Oh,
    __half* __restrict__ Ol)
{
    extern __shared__ float sm[];
    float* Qs = sm;
    float* Ks = sm + 64 * QSTR;
    float* Vs = Ks + 32 * QSTR;
    float* Ps = Vs + 32 * QSTR;

    const int i0 = blockIdx.x * 64;
    const int h  = blockIdx.y;
    const int b  = blockIdx.z;
    const int hk = h >> 1;
    const int tid = threadIdx.x;
    const int r = tid >> 2, c = tid & 3;
    const float scale = 0.08838834764831845f; // 1/sqrt(128)

    #pragma unroll
    for (int it = 0; it < 8; it++) {
        int idx = tid + 256 * it;
        int rr = idx >> 5, d4 = idx & 31;
        float4 qv = *(const float4*)(Q + ((size_t)(b * SEQ + i0 + rr) * H_SIZE + h * HD + d4 * 4));
        float4 qs = {qv.x * scale, qv.y * scale, qv.z * scale, qv.w * scale};
        *(float4*)&Qs[rr * QSTR + d4 * 4] = qs;
    }

    float m = -1e30f, l = 0.f;
    float4 o[8];
    #pragma unroll
    for (int t8 = 0; t8 < 8; t8++) o[t8] = make_float4(0.f, 0.f, 0.f, 0.f);

    int jstart = i0 - (WIN - 1);
    if (jstart < 0) jstart = 0;
    jstart &= ~31;
    const int iq = i0 + r;
    const float* qrow = Qs + r * QSTR;

    for (int j0 = jstart; j0 < i0 + 64; j0 += 32) {
        __syncthreads();
        #pragma unroll
        for (int it = 0; it < 4; it++) {
            int idx = tid + 256 * it;
            int rr = idx >> 5, d4 = idx & 31;
            size_t goff = (size_t)(b * SEQ + j0 + rr) * (NKV * HD) + hk * HD + d4 * 4;
            *(float4*)&Ks[rr * QSTR + d4 * 4] = *(const float4*)(K + goff);
            *(float4*)&Vs[rr * QSTR + d4 * 4] = *(const float4*)(V + goff);
        }
        __syncthreads();

        float s[8];
        #pragma unroll
        for (int u = 0; u < 8; u++) s[u] = 0.f;
        #pragma unroll 4
        for (int d4 = 0; d4 < 32; d4++) {
            float4 qv = *(const float4*)(qrow + d4 * 4);
            #pragma unroll
            for (int u = 0; u < 8; u++) {
                float4 kv = *(const float4*)&Ks[(c + 4 * u) * QSTR + d4 * 4];
                s[u] += qv.x * kv.x + qv.y * kv.y + qv.z * kv.z + qv.w * kv.w;
            }
        }

        float mt = m;
        #pragma unroll
        for (int u = 0; u < 8; u++) {
            int j = j0 + c + 4 * u;
            bool ok = (j <= iq) && (iq - j < WIN);
            s[u] = ok ? s[u] : -1e30f;
            mt = fmaxf(mt, s[u]);
        }
        mt = fmaxf(mt, __shfl_xor_sync(0xffffffffu, mt, 1));
        mt = fmaxf(mt, __shfl_xor_sync(0xffffffffu, mt, 2));
        float alpha = __expf(m - mt);
        m = mt;
        float psum = 0.f;
        #pragma unroll
        for (int u = 0; u < 8; u++) {
            float p = __expf(s[u] - mt);
            psum += p;
            Ps[r * PSTR + c + 4 * u] = p;
        }
        l = l * alpha + psum;
        #pragma unroll
        for (int t8 = 0; t8 < 8; t8++) {
            o[t8].x *= alpha; o[t8].y *= alpha; o[t8].z *= alpha; o[t8].w *= alpha;
        }
        __syncwarp();
        #pragma unroll 4
        for (int jj = 0; jj < 32; jj++) {
            float pj = Ps[r * PSTR + jj];
            #pragma unroll
            for (int t8 = 0; t8 < 8; t8++) {
                float4 vv = *(const float4*)&Vs[jj * QSTR + (c + 4 * t8) * 4];
                o[t8].x += pj * vv.x; o[t8].y += pj * vv.y;
                o[t8].z += pj * vv.z; o[t8].w += pj * vv.w;
            }
        }
        __syncwarp();
    }

    l += __shfl_xor_sync(0xffffffffu, l, 1);
    l += __shfl_xor_sync(0xffffffffu, l, 2);
    float linv = 1.0f / l;
    size_t obase = (size_t)(b * SEQ + i0 + r) * H_SIZE + h * HD;
    #pragma unroll
    for (int t8 = 0; t8 < 8; t8++) {
        size_t off = obase + (c + 4 * t8) * 4;
        split2h(o[t8].x * linv, o[t8].y * linv, Oh + off,     Ol + off);
        split2h(o[t8].z * linv, o[t8].w * linv, Oh + off + 2, Ol + off + 2);
    }
}

// ---------------- GeGLU: fp16 hi/lo planes out -------------------------------------------
__device__ __forceinline__ float gelu_exact(float x) {
    return 0.5f * x * (1.0f + erff(x * 0.7071067811865476f));
}
__global__ __launch_bounds__(256) void geglu_kernel(
    const float* __restrict__ g, const float* __restrict__ u,
    __half* __restrict__ oh, __half* __restrict__ ol, int n4)
{
    int i = blockIdx.x * blockDim.x + threadIdx.x;
    int stride = gridDim.x * blockDim.x;
    for (; i < n4; i += stride) {
        float4 gv = ((const float4*)g)[i];
        float4 uv = ((const float4*)u)[i];
        float r0 = gelu_exact(gv.x) * uv.x;
        float r1 = gelu_exact(gv.y) * uv.y;
        float r2 = gelu_exact(gv.z) * uv.z;
        float r3 = gelu_exact(gv.w) * uv.w;
        split2h(r0, r1, oh + i*4,     ol + i*4);
        split2h(r2, r3, oh + i*4 + 2, ol + i*4 + 2);
    }
}

// ---------------- launch ----------------------------------------------------------------
extern "C" void kernel_launch(void* const* d_in, const int* in_sizes, int n_in,
                              void* d_out, int out_size)
{
    const float* x    = (const float*)d_in[0];
    const float* wq   = (const float*)d_in[1];
    const float* wk   = (const float*)d_in[2];
    const float* wv   = (const float*)d_in[3];
    const float* wo   = (const float*)d_in[4];
    const float* w_in = (const float*)d_in[5];
    const float* w_pa = (const float*)d_in[6];
    const float* w_pf = (const float*)d_in[7];
    const float* w_pff= (const float*)d_in[8];
    const float* wg   = (const float*)d_in[9];
    const float* wu   = (const float*)d_in[10];
    const float* wd   = (const float*)d_in[11];
    const float* lsc  = (const float*)d_in[12];
    float* out = (float*)d_out;

    float *q, *k, *v, *attnout, *h2, *gate, *up, *ffnout;
    cudaGetSymbolAddress((void**)&q,       g_q);
    cudaGetSymbolAddress((void**)&k,       g_k);
    cudaGetSymbolAddress((void**)&v,       g_v);
    cudaGetSymbolAddress((void**)&attnout, g_attnout);
    cudaGetSymbolAddress((void**)&h2,      g_h2);
    cudaGetSymbolAddress((void**)&gate,    g_gate);
    cudaGetSymbolAddress((void**)&up,      g_up);
    cudaGetSymbolAddress((void**)&ffnout,  g_ffnout);

    __half *h_h, *h_l, *attn_h, *attn_l, *ffnin_h, *ffnin_l, *gact_h, *gact_l;
    __half *pwq, *pwk, *pwv, *pwo, *pwg, *pwu, *pwd;
    cudaGetSymbolAddress((void**)&h_h, g_h_h);         cudaGetSymbolAddress((void**)&h_l, g_h_l);
    cudaGetSymbolAddress((void**)&attn_h, g_attn_h);   cudaGetSymbolAddress((void**)&attn_l, g_attn_l);
    cudaGetSymbolAddress((void**)&ffnin_h, g_ffnin_h); cudaGetSymbolAddress((void**)&ffnin_l, g_ffnin_l);
    cudaGetSymbolAddress((void**)&gact_h, g_gact_h);   cudaGetSymbolAddress((void**)&gact_l, g_gact_l);
    cudaGetSymbolAddress((void**)&pwq, g_wq);
    cudaGetSymbolAddress((void**)&pwk, g_wk);
    cudaGetSymbolAddress((void**)&pwv, g_wv);
    cudaGetSymbolAddress((void**)&pwo, g_wo);
    cudaGetSymbolAddress((void**)&pwg, g_wg);
    cudaGetSymbolAddress((void**)&pwu, g_wu);
    cudaGetSymbolAddress((void**)&pwd, g_wd);

    const int attn_smem = ATTN_SMEM_FLOATS * (int)sizeof(float);
    cudaFuncSetAttribute(attn_kernel, cudaFuncAttributeMaxDynamicSharedMemorySize, attn_smem);
    cudaFuncSetAttribute(gemm_mma, cudaFuncAttributeMaxDynamicSharedMemorySize, GEMM_SMEM);

    // weight planes (fp16)
    wsplit_kernel<<<2048, 256>>>(wq, pwq, H_SIZE*H_SIZE/4);
    wsplit_kernel<<<1024, 256>>>(wk, pwk, NKV*HD*H_SIZE/4);
    wsplit_kernel<<<1024, 256>>>(wv, pwv, NKV*HD*H_SIZE/4);
    wsplit_kernel<<<2048, 256>>>(wo, pwo, H_SIZE*H_SIZE/4);
    wsplit_kernel<<<4096, 256>>>(wg, pwg, INTER_SZ*H_SIZE/4);
    wsplit_kernel<<<4096, 256>>>(wu, pwu, INTER_SZ*H_SIZE/4);
    wsplit_kernel<<<4096, 256>>>(wd, pwd, H_SIZE*INTER_SZ/4);

    // h = rmsnorm(x, w_in) -> fp16 hi/lo planes
    rmsnorm_split_kernel<<<NROWS, 256>>>(x, w_in, h_h, h_l);
    // QKV
    gemm_mma<<<dim3(H_SIZE/128, NROWS/128), 256, GEMM_SMEM>>>(h_h, h_l, pwq, q, NROWS, H_SIZE, H_SIZE);
    gemm_mma<<<dim3((NKV*HD)/128, NROWS/128), 256, GEMM_SMEM>>>(h_h, h_l, pwk, k, NROWS, NKV*HD, H_SIZE);
    gemm_mma<<<dim3((NKV*HD)/128, NROWS/128), 256, GEMM_SMEM>>>(h_h, h_l, pwv, v, NROWS, NKV*HD, H_SIZE);
    // RoPE
    rope_kernel<<<NROWS, 256>>>(q, NQ);
    rope_kernel<<<NROWS, 256>>>(k, NKV);
    // attention -> fp16 planes
    attn_kernel<<<dim3(SEQ/64, NQ, BATCH), 256, attn_smem>>>(q, k, v, attn_h, attn_l);
    // WO
    gemm_mma<<<dim3(H_SIZE/128, NROWS/128), 256, GEMM_SMEM>>>(attn_h, attn_l, pwo, attnout, NROWS, H_SIZE, H_SIZE);
    // h2 = x + rmsnorm(attnout, w_pa)
    rmsnorm_kernel<<<NROWS, 256>>>(attnout, w_pa, x, nullptr, h2, 1);
    // ffn_in = rmsnorm(h2, w_pf) -> fp16 planes
    rmsnorm_split_kernel<<<NROWS, 256>>>(h2, w_pf, ffnin_h, ffnin_l);
    // gate/up GEMMs
    gemm_mma<<<dim3(INTER_SZ/128, NROWS/128), 256, GEMM_SMEM>>>(ffnin_h, ffnin_l, pwg, gate, NROWS, INTER_SZ, H_SIZE);
    gemm_mma<<<dim3(INTER_SZ/128, NROWS/128), 256, GEMM_SMEM>>>(ffnin_h, ffnin_l, pwu, up, NROWS, INTER_SZ, H_SIZE);
    // act = gelu(gate) * up -> fp16 planes
    geglu_kernel<<<8192, 256>>>(gate, up, gact_h, gact_l, (NROWS * INTER_SZ) / 4);
    // down projection (K = INTER)
    gemm_mma<<<dim3(H_SIZE/128, NROWS/128), 256, GEMM_SMEM>>>(gact_h, gact_l, pwd, ffnout, NROWS, H_SIZE, INTER_SZ);
    // out = (h2 + rmsnorm(ffnout, w_pff)) * layer_scalar
    rmsnorm_kernel<<<NROWS, 256>>>(ffnout, w_pff, h2, lsc, out, 2);
}

// round 12
// speedup vs baseline: 1.8022x; 1.2270x over previous
#include <cuda_runtime.h>
#include <cuda_fp16.h>
#include <stdint.h>
#include <math.h>

#define H_SIZE 2048
#define INTER_SZ 8192
#define NQ 16
#define NKV 8
#define HD 128
#define SEQ 2048
#define BATCH 2
#define NROWS (BATCH*SEQ)
#define WIN 1024

// ---------------- fp32 scratch ----------------
__device__ float g_q[NROWS*H_SIZE];
__device__ float g_k[NROWS*NKV*HD];
__device__ float g_v[NROWS*NKV*HD];
__device__ float g_attnout[NROWS*H_SIZE];
__device__ float g_h2[NROWS*H_SIZE];
__device__ float g_gate[NROWS*INTER_SZ];
__device__ float g_up[NROWS*INTER_SZ];
__device__ float g_ffnout[NROWS*H_SIZE];

// ---------------- fp16 planes ----------------
__device__ __half g_h_h[NROWS*H_SIZE],      g_h_l[NROWS*H_SIZE];
__device__ __half g_attn_h[NROWS*H_SIZE],   g_attn_l[NROWS*H_SIZE];
__device__ __half g_ffnin_h[NROWS*H_SIZE],  g_ffnin_l[NROWS*H_SIZE];
__device__ __half g_gact_h[NROWS*INTER_SZ], g_gact_l[NROWS*INTER_SZ];
__device__ __half g_wq[H_SIZE*H_SIZE];
__device__ __half g_wk[NKV*HD*H_SIZE];
__device__ __half g_wv[NKV*HD*H_SIZE];
__device__ __half g_wo[H_SIZE*H_SIZE];
__device__ __half g_wg[INTER_SZ*H_SIZE];
__device__ __half g_wu[INTER_SZ*H_SIZE];
__device__ __half g_wd[H_SIZE*INTER_SZ];

// ---------------- helpers ----------------
__device__ __forceinline__ void split2h(float a, float b, __half* hi, __half* lo) {
    __half ha = __float2half(a), hb = __float2half(b);
    __half la = __float2half(a - __half2float(ha));
    __half lb = __float2half(b - __half2float(hb));
    *(__half2*)hi = __halves2half2(ha, hb);
    *(__half2*)lo = __halves2half2(la, lb);
}

__global__ __launch_bounds__(256) void wsplit_kernel(
    const float* __restrict__ in, __half* __restrict__ out, int n4)
{
    int i = blockIdx.x * blockDim.x + threadIdx.x;
    int stride = gridDim.x * blockDim.x;
    for (; i < n4; i += stride) {
        float4 v = ((const float4*)in)[i];
        *(__half2*)(out + i*4)     = __halves2half2(__float2half(v.x), __float2half(v.y));
        *(__half2*)(out + i*4 + 2) = __halves2half2(__float2half(v.z), __float2half(v.w));
    }
}

// ---------------- RMSNorm fp32 out ----------------
__global__ __launch_bounds__(256) void rmsnorm_kernel(
    const float* __restrict__ in, const float* __restrict__ w,
    const float* __restrict__ res, const float* __restrict__ scal,
    float* __restrict__ out, int mode)
{
    int row = blockIdx.x;
    int t = threadIdx.x;
    const float4* ip = (const float4*)(in + (size_t)row * H_SIZE);
    float4 v0 = ip[t];
    float4 v1 = ip[t + 256];
    float ss = v0.x*v0.x + v0.y*v0.y + v0.z*v0.z + v0.w*v0.w
             + v1.x*v1.x + v1.y*v1.y + v1.z*v1.z + v1.w*v1.w;
    #pragma unroll
    for (int o = 16; o; o >>= 1) ss += __shfl_xor_sync(0xffffffffu, ss, o);
    __shared__ float red[8];
    if ((t & 31) == 0) red[t >> 5] = ss;
    __syncthreads();
    float tot = red[0]+red[1]+red[2]+red[3]+red[4]+red[5]+red[6]+red[7];
    float inv = rsqrtf(tot * (1.0f / H_SIZE) + 1e-6f);

    const float4* w4 = (const float4*)w;
    float4 w0 = w4[t], w1 = w4[t + 256];
    float4 o0, o1;
    o0.x = v0.x*inv*w0.x; o0.y = v0.y*inv*w0.y; o0.z = v0.z*inv*w0.z; o0.w = v0.w*inv*w0.w;
    o1.x = v1.x*inv*w1.x; o1.y = v1.y*inv*w1.y; o1.z = v1.z*inv*w1.z; o1.w = v1.w*inv*w1.w;
    if (mode >= 1) {
        const float4* rp = (const float4*)(res + (size_t)row * H_SIZE);
        float4 r0 = rp[t], r1 = rp[t + 256];
        o0.x += r0.x; o0.y += r0.y; o0.z += r0.z; o0.w += r0.w;
        o1.x += r1.x; o1.y += r1.y; o1.z += r1.z; o1.w += r1.w;
    }
    if (mode == 2) {
        float sc = scal[0];
        o0.x *= sc; o0.y *= sc; o0.z *= sc; o0.w *= sc;
        o1.x *= sc; o1.y *= sc; o1.z *= sc; o1.w *= sc;
    }
    float4* op = (float4*)(out + (size_t)row * H_SIZE);
    op[t] = o0;
    op[t + 256] = o1;
}

// ---------------- RMSNorm -> fp16 hi/lo planes ----------------
__global__ __launch_bounds__(256) void rmsnorm_split_kernel(
    const float* __restrict__ in, const float* __restrict__ w,
    __half* __restrict__ oh, __half* __restrict__ ol)
{
    int row = blockIdx.x;
    int t = threadIdx.x;
    const float4* ip = (const float4*)(in + (size_t)row * H_SIZE);
    float4 v0 = ip[t];
    float4 v1 = ip[t + 256];
    float ss = v0.x*v0.x + v0.y*v0.y + v0.z*v0.z + v0.w*v0.w
             + v1.x*v1.x + v1.y*v1.y + v1.z*v1.z + v1.w*v1.w;
    #pragma unroll
    for (int o = 16; o; o >>= 1) ss += __shfl_xor_sync(0xffffffffu, ss, o);
    __shared__ float red[8];
    if ((t & 31) == 0) red[t >> 5] = ss;
    __syncthreads();
    float tot = red[0]+red[1]+red[2]+red[3]+red[4]+red[5]+red[6]+red[7];
    float inv = rsqrtf(tot * (1.0f / H_SIZE) + 1e-6f);

    const float4* w4 = (const float4*)w;
    float4 w0 = w4[t], w1 = w4[t + 256];
    size_t base = (size_t)row * H_SIZE;
    split2h(v0.x*inv*w0.x, v0.y*inv*w0.y, oh + base + t*4,     ol + base + t*4);
    split2h(v0.z*inv*w0.z, v0.w*inv*w0.w, oh + base + t*4 + 2, ol + base + t*4 + 2);
    split2h(v1.x*inv*w1.x, v1.y*inv*w1.y, oh + base + 1024 + t*4,     ol + base + 1024 + t*4);
    split2h(v1.z*inv*w1.z, v1.w*inv*w1.w, oh + base + 1024 + t*4 + 2, ol + base + 1024 + t*4 + 2);
}

// ---------------- Tensor-core GEMM on fp16 planes, cp.async double-buffered --------------
// TWOPASS: C = (Ah+Al)*Bh^T (2 MMA passes, 3 planes staged)
// !TWOPASS: C = Ah*Bh^T (1 pass, 2 planes staged)
// Block 128x128, BK=32, warp tile 32x64, 2 CTAs/SM.
// plane order in stage: [0]=Ah, [1]=Bh, [2]=Al(TWOPASS only)

#define LDSK 40
#define PLANE_H (128*LDSK)

__device__ __forceinline__ void mma_fp16(float* c, const uint32_t* a, const uint32_t* b) {
    asm volatile(
        "mma.sync.aligned.m16n8k16.row.col.f32.f16.f16.f32 "
        "{%0,%1,%2,%3}, {%4,%5,%6,%7}, {%8,%9}, {%0,%1,%2,%3};\n"
        : "+f"(c[0]), "+f"(c[1]), "+f"(c[2]), "+f"(c[3])
        : "r"(a[0]), "r"(a[1]), "r"(a[2]), "r"(a[3]), "r"(b[0]), "r"(b[1]));
}

__device__ __forceinline__ void ldsm_x4(uint32_t* r, uint32_t addr) {
    asm volatile("ldmatrix.sync.aligned.m8n8.x4.shared.b16 {%0,%1,%2,%3}, [%4];"
        : "=r"(r[0]), "=r"(r[1]), "=r"(r[2]), "=r"(r[3]) : "r"(addr));
}

__device__ __forceinline__ void cp16(uint32_t dst, const void* src) {
    asm volatile("cp.async.cg.shared.global [%0], [%1], 16;\n" :: "r"(dst), "l"(src));
}

template<bool TWOPASS>
__global__ __launch_bounds__(256, 2) void gemm_mma(
    const __half* __restrict__ Agh, const __half* __restrict__ Agl,
    const __half* __restrict__ Bgh,
    float* __restrict__ C, int M, int N, int K)
{
    extern __shared__ __align__(16) __half smp[];
    const int NPL = TWOPASS ? 3 : 2;
    const int STAGE_HH = NPL * PLANE_H;

    const int tid  = threadIdx.x;
    const int warp = tid >> 5, lane = tid & 31;
    const int wm = warp >> 1, wn = warp & 1;   // 4 x 2 warp grid, warp tile 32x64
    const int rowA = blockIdx.y * 128;
    const int colB = blockIdx.x * 128;

    const uint32_t smb = (uint32_t)__cvta_generic_to_shared(smp);
    const uint32_t a_off = (uint32_t)(((wm*32 + (lane & 15)) * LDSK + ((lane >> 4) * 8)) * 2);
    const uint32_t b_off = (uint32_t)(((wn*64 + ((lane >> 4) * 8) + (lane & 7)) * LDSK
                                       + (((lane >> 3) & 1) * 8)) * 2);

    float acc[2][8][4];
    #pragma unroll
    for (int i = 0; i < 2; i++)
        #pragma unroll
        for (int j = 0; j < 8; j++)
            #pragma unroll
            for (int q = 0; q < 4; q++) acc[i][j][q] = 0.f;

    // 2*NPL x 16B chunks per thread per stage: NPL planes x 128 rows x 4 chunks
    #define CP_STAGE(s, k0)                                                        \
    {                                                                              \
        _Pragma("unroll")                                                          \
        for (int i = 0; i < 2*NPL; i++) {                                          \
            int cidx = tid + 256 * i;                                              \
            int plane = cidx >> 9;                                                 \
            int cc = cidx & 511;                                                   \
            int row = cc >> 2;                                                     \
            int ch = cc & 3;                                                       \
            const __half* src =                                                    \
                (plane == 0) ? Agh + (size_t)(rowA + row) * K :                    \
                (plane == 1) ? Bgh + (size_t)(colB + row) * K :                    \
                               Agl + (size_t)(rowA + row) * K;                     \
            uint32_t dst = smb +                                                   \
                (uint32_t)(((s) * STAGE_HH + plane * PLANE_H + row * LDSK + ch * 8) * 2); \
            cp16(dst, src + (k0) + ch * 8);                                        \
        }                                                                          \
        asm volatile("cp.async.commit_group;\n" ::: "memory");                     \
    }

    const int NC = K >> 5;
    CP_STAGE(0, 0);
    for (int c = 0; c < NC; c++) {
        int s = c & 1;
        if (c + 1 < NC) {
            CP_STAGE(s ^ 1, (c + 1) * 32);
            asm volatile("cp.async.wait_group 1;\n" ::: "memory");
        } else {
            asm volatile("cp.async.wait_group 0;\n" ::: "memory");
        }
        __syncthreads();

        const uint32_t ah_b = smb + (uint32_t)((s * STAGE_HH) * 2);
        const uint32_t bh_b = ah_b + (uint32_t)(PLANE_H * 2);
        const uint32_t al_b = bh_b + (uint32_t)(PLANE_H * 2);

        #pragma unroll
        for (int kk = 0; kk < 32; kk += 16) {
            const uint32_t kko = kk * 2;
            uint32_t fa[2][4];
            uint32_t fb[4][4];
            #pragma unroll
            for (int tm = 0; tm < 2; tm++)
                ldsm_x4(fa[tm], ah_b + a_off + (uint32_t)(tm * 16 * LDSK * 2) + kko);
            #pragma unroll
            for (int p = 0; p < 4; p++)
                ldsm_x4(fb[p], bh_b + b_off + (uint32_t)(p * 16 * LDSK * 2) + kko);
            #pragma unroll
            for (int tm = 0; tm < 2; tm++)
                #pragma unroll
                for (int tn = 0; tn < 8; tn++)
                    mma_fp16(acc[tm][tn], fa[tm], &fb[tn >> 1][(tn & 1) * 2]);
            if (TWOPASS) {
                uint32_t fal[2][4];
                #pragma unroll
                for (int tm = 0; tm < 2; tm++)
                    ldsm_x4(fal[tm], al_b + a_off + (uint32_t)(tm * 16 * LDSK * 2) + kko);
                #pragma unroll
                for (int tm = 0; tm < 2; tm++)
                    #pragma unroll
                    for (int tn = 0; tn < 8; tn++)
                        mma_fp16(acc[tm][tn], fal[tm], &fb[tn >> 1][(tn & 1) * 2]);
            }
        }
        __syncthreads();
    }

    const int g = lane >> 2, t4 = lane & 3;
    #pragma unroll
    for (int tm = 0; tm < 2; tm++) {
        #pragma unroll
        for (int tn = 0; tn < 8; tn++) {
            int row = blockIdx.y*128 + wm*32 + tm*16 + g;
            int col = blockIdx.x*128 + wn*64 + tn*8 + 2*t4;
            float2 c0 = {acc[tm][tn][0], acc[tm][tn][1]};
            float2 c1 = {acc[tm][tn][2], acc[tm][tn][3]};
            *(float2*)(C + (size_t)row * N + col)       = c0;
            *(float2*)(C + (size_t)(row + 8) * N + col) = c1;
        }
    }
}

// ---------------- RoPE ----------------
__global__ __launch_bounds__(256) void rope_kernel(float* __restrict__ buf, int nheads)
{
    int row = blockIdx.x;
    int s = row & (SEQ - 1);
    float* base = buf + (size_t)row * nheads * HD;
    for (int idx = threadIdx.x; idx < nheads * 64; idx += blockDim.x) {
        int hh = idx >> 6;
        int d = idx & 63;
        float inv = expf(-((float)d * (1.0f / 64.0f)) * 9.210340371976184f); // ln(10000)
        float fr = (float)s * inv;
        float sn = sinf(fr), cs = cosf(fr);
        float* p = base + hh * HD + d;
        float x1 = p[0], x2 = p[64];
        p[0]  = x1 * cs - x2 * sn;
        p[64] = x2 * cs + x1 * sn;
    }
}

// ---------------- Sliding-window GQA flash attention (out: fp16 hi/lo planes) ------------
#define QSTR 132
#define PSTR 36
#define ATTN_SMEM_FLOATS (64*QSTR + 32*QSTR + 32*QSTR + 64*PSTR)

__global__ __launch_bounds__(256) void attn_kernel(
    const float* __restrict__ Q, const float* __restrict__ K,
    const float* __restrict__ V, __half* __restrict__ Oh,
    __half* __restrict__ Ol)
{
    extern __shared__ float sm[];
    float* Qs = sm;
    float* Ks = sm + 64 * QSTR;
    float* Vs = Ks + 32 * QSTR;
    float* Ps = Vs + 32 * QSTR;

    const int i0 = blockIdx.x * 64;
    const int h  = blockIdx.y;
    const int b  = blockIdx.z;
    const int hk = h >> 1;
    const int tid = threadIdx.x;
    const int r = tid >> 2, c = tid & 3;
    const float scale = 0.08838834764831845f;

    #pragma unroll
    for (int it = 0; it < 8; it++) {
        int idx = tid + 256 * it;
        int rr = idx >> 5, d4 = idx & 31;
        float4 qv = *(const float4*)(Q + ((size_t)(b * SEQ + i0 + rr) * H_SIZE + h * HD + d4 * 4));
        float4 qs = {qv.x * scale, qv.y * scale, qv.z * scale, qv.w * scale};
        *(float4*)&Qs[rr * QSTR + d4 * 4] = qs;
    }

    float m = -1e30f, l = 0.f;
    float4 o[8];
    #pragma unroll
    for (int t8 = 0; t8 < 8; t8++) o[t8] = make_float4(0.f, 0.f, 0.f, 0.f);

    int jstart = i0 - (WIN - 1);
    if (jstart < 0) jstart = 0;
    jstart &= ~31;
    const int iq = i0 + r;
    const float* qrow = Qs + r * QSTR;

    for (int j0 = jstart; j0 < i0 + 64; j0 += 32) {
        __syncthreads();
        #pragma unroll
        for (int it = 0; it < 4; it++) {
            int idx = tid + 256 * it;
            int rr = idx >> 5, d4 = idx & 31;
            size_t goff = (size_t)(b * SEQ + j0 + rr) * (NKV * HD) + hk * HD + d4 * 4;
            *(float4*)&Ks[rr * QSTR + d4 * 4] = *(const float4*)(K + goff);
            *(float4*)&Vs[rr * QSTR + d4 * 4] = *(const float4*)(V + goff);
        }
        __syncthreads();

        float s[8];
        #pragma unroll
        for (int u = 0; u < 8; u++) s[u] = 0.f;
        #pragma unroll 4
        for (int d4 = 0; d4 < 32; d4++) {
            float4 qv = *(const float4*)(qrow + d4 * 4);
            #pragma unroll
            for (int u = 0; u < 8; u++) {
                float4 kv = *(const float4*)&Ks[(c + 4 * u) * QSTR + d4 * 4];
                s[u] += qv.x * kv.x + qv.y * kv.y + qv.z * kv.z + qv.w * kv.w;
            }
        }

        float mt = m;
        #pragma unroll
        for (int u = 0; u < 8; u++) {
            int j = j0 + c + 4 * u;
            bool ok = (j <= iq) && (iq - j < WIN);
            s[u] = ok ? s[u] : -1e30f;
            mt = fmaxf(mt, s[u]);
        }
        mt = fmaxf(mt, __shfl_xor_sync(0xffffffffu, mt, 1));
        mt = fmaxf(mt, __shfl_xor_sync(0xffffffffu, mt, 2));
        float alpha = __expf(m - mt);
        m = mt;
        float psum = 0.f;
        #pragma unroll
        for (int u = 0; u < 8; u++) {
            float p = __expf(s[u] - mt);
            psum += p;
            Ps[r * PSTR + c + 4 * u] = p;
        }
        l = l * alpha + psum;
        #pragma unroll
        for (int t8 = 0; t8 < 8; t8++) {
            o[t8].x *= alpha; o[t8].y *= alpha; o[t8].z *= alpha; o[t8].w *= alpha;
        }
        __syncwarp();
        #pragma unroll 4
        for (int jj = 0; jj < 32; jj++) {
            float pj = Ps[r * PSTR + jj];
            #pragma unroll
            for (int t8 = 0; t8 < 8; t8++) {
                float4 vv = *(const float4*)&Vs[jj * QSTR + (c + 4 * t8) * 4];
                o[t8].x += pj * vv.x; o[t8].y += pj * vv.y;
                o[t8].z += pj * vv.z; o[t8].w += pj * vv.w;
            }
        }
        __syncwarp();
    }

    l += __shfl_xor_sync(0xffffffffu, l, 1);
    l += __shfl_xor_sync(0xffffffffu, l, 2);
    float linv = 1.0f / l;
    size_t obase = (size_t)(b * SEQ + i0 + r) * H_SIZE + h * HD;
    #pragma unroll
    for (int t8 = 0; t8 < 8; t8++) {
        size_t off = obase + (c + 4 * t8) * 4;
        split2h(o[t8].x * linv, o[t8].y * linv, Oh + off,     Ol + off);
        split2h(o[t8].z * linv, o[t8].w * linv, Oh + off + 2, Ol + off + 2);
    }
}

// ---------------- GeGLU: fp16 hi plane out (lo unused by 1-pass down-proj) ---------------
__device__ __forceinline__ float gelu_exact(float x) {
    return 0.5f * x * (1.0f + erff(x * 0.7071067811865476f));
}
__global__ __launch_bounds__(256) void geglu_kernel(
    const float* __restrict__ g, const float* __restrict__ u,
    __half* __restrict__ oh, int n4)
{
    int i = blockIdx.x * blockDim.x + threadIdx.x;
    int stride = gridDim.x * blockDim.x;
    for (; i < n4; i += stride) {
        float4 gv = ((const float4*)g)[i];
        float4 uv = ((const float4*)u)[i];
        float r0 = gelu_exact(gv.x) * uv.x;
        float r1 = gelu_exact(gv.y) * uv.y;
        float r2 = gelu_exact(gv.z) * uv.z;
        float r3 = gelu_exact(gv.w) * uv.w;
        *(__half2*)(oh + i*4)     = __halves2half2(__float2half(r0), __float2half(r1));
        *(__half2*)(oh + i*4 + 2) = __halves2half2(__float2half(r2), __float2half(r3));
    }
}

// ---------------- launch ----------------
extern "C" void kernel_launch(void* const* d_in, const int* in_sizes, int n_in,
                              void* d_out, int out_size)
{
    const float* x    = (const float*)d_in[0];
    const float* wq   = (const float*)d_in[1];
    const float* wk   = (const float*)d_in[2];
    const float* wv   = (const float*)d_in[3];
    const float* wo   = (const float*)d_in[4];
    const float* w_in = (const float*)d_in[5];
    const float* w_pa = (const float*)d_in[6];
    const float* w_pf = (const float*)d_in[7];
    const float* w_pff= (const float*)d_in[8];
    const float* wg   = (const float*)d_in[9];
    const float* wu   = (const float*)d_in[10];
    const float* wd   = (const float*)d_in[11];
    const float* lsc  = (const float*)d_in[12];
    float* out = (float*)d_out;

    float *q, *k, *v, *attnout, *h2, *gate, *up, *ffnout;
    cudaGetSymbolAddress((void**)&q,       g_q);
    cudaGetSymbolAddress((void**)&k,       g_k);
    cudaGetSymbolAddress((void**)&v,       g_v);
    cudaGetSymbolAddress((void**)&attnout, g_attnout);
    cudaGetSymbolAddress((void**)&h2,      g_h2);
    cudaGetSymbolAddress((void**)&gate,    g_gate);
    cudaGetSymbolAddress((void**)&up,      g_up);
    cudaGetSymbolAddress((void**)&ffnout,  g_ffnout);

    __half *h_h, *h_l, *attn_h, *attn_l, *ffnin_h, *ffnin_l, *gact_h;
    __half *pwq, *pwk, *pwv, *pwo, *pwg, *pwu, *pwd;
    cudaGetSymbolAddress((void**)&h_h, g_h_h);         cudaGetSymbolAddress((void**)&h_l, g_h_l);
    cudaGetSymbolAddress((void**)&attn_h, g_attn_h);   cudaGetSymbolAddress((void**)&attn_l, g_attn_l);
    cudaGetSymbolAddress((void**)&ffnin_h, g_ffnin_h); cudaGetSymbolAddress((void**)&ffnin_l, g_ffnin_l);
    cudaGetSymbolAddress((void**)&gact_h, g_gact_h);
    cudaGetSymbolAddress((void**)&pwq, g_wq);
    cudaGetSymbolAddress((void**)&pwk, g_wk);
    cudaGetSymbolAddress((void**)&pwv, g_wv);
    cudaGetSymbolAddress((void**)&pwo, g_wo);
    cudaGetSymbolAddress((void**)&pwg, g_wg);
    cudaGetSymbolAddress((void**)&pwu, g_wu);
    cudaGetSymbolAddress((void**)&pwd, g_wd);

    const int attn_smem = ATTN_SMEM_FLOATS * (int)sizeof(float);
    const int smem2 = 2 * 3 * PLANE_H * 2;   // two-pass: 3 planes
    const int smem1 = 2 * 2 * PLANE_H * 2;   // one-pass: 2 planes
    cudaFuncSetAttribute(attn_kernel, cudaFuncAttributeMaxDynamicSharedMemorySize, attn_smem);
    cudaFuncSetAttribute(gemm_mma<true>,  cudaFuncAttributeMaxDynamicSharedMemorySize, smem2);
    cudaFuncSetAttribute(gemm_mma<false>, cudaFuncAttributeMaxDynamicSharedMemorySize, smem1);

    // weight planes (fp16)
    wsplit_kernel<<<2048, 256>>>(wq, pwq, H_SIZE*H_SIZE/4);
    wsplit_kernel<<<1024, 256>>>(wk, pwk, NKV*HD*H_SIZE/4);
    wsplit_kernel<<<1024, 256>>>(wv, pwv, NKV*HD*H_SIZE/4);
    wsplit_kernel<<<2048, 256>>>(wo, pwo, H_SIZE*H_SIZE/4);
    wsplit_kernel<<<4096, 256>>>(wg, pwg, INTER_SZ*H_SIZE/4);
    wsplit_kernel<<<4096, 256>>>(wu, pwu, INTER_SZ*H_SIZE/4);
    wsplit_kernel<<<4096, 256>>>(wd, pwd, H_SIZE*INTER_SZ/4);

    // h = rmsnorm(x, w_in) -> fp16 hi/lo planes
    rmsnorm_split_kernel<<<NROWS, 256>>>(x, w_in, h_h, h_l);
    // QKV (2-pass)
    gemm_mma<true><<<dim3(H_SIZE/128, NROWS/128), 256, smem2>>>(h_h, h_l, pwq, q, NROWS, H_SIZE, H_SIZE);
    gemm_mma<true><<<dim3((NKV*HD)/128, NROWS/128), 256, smem2>>>(h_h, h_l, pwk, k, NROWS, NKV*HD, H_SIZE);
    gemm_mma<true><<<dim3((NKV*HD)/128, NROWS/128), 256, smem2>>>(h_h, h_l, pwv, v, NROWS, NKV*HD, H_SIZE);
    // RoPE
    rope_kernel<<<NROWS, 256>>>(q, NQ);
    rope_kernel<<<NROWS, 256>>>(k, NKV);
    // attention -> fp16 planes
    attn_kernel<<<dim3(SEQ/64, NQ, BATCH), 256, attn_smem>>>(q, k, v, attn_h, attn_l);
    // WO (2-pass)
    gemm_mma<true><<<dim3(H_SIZE/128, NROWS/128), 256, smem2>>>(attn_h, attn_l, pwo, attnout, NROWS, H_SIZE, H_SIZE);
    // h2 = x + rmsnorm(attnout, w_pa)
    rmsnorm_kernel<<<NROWS, 256>>>(attnout, w_pa, x, nullptr, h2, 1);
    // ffn_in = rmsnorm(h2, w_pf) -> fp16 planes (lo written but unused by 1-pass)
    rmsnorm_split_kernel<<<NROWS, 256>>>(h2, w_pf, ffnin_h, ffnin_l);
    // gate/up GEMMs (1-pass fp16)
    gemm_mma<false><<<dim3(INTER_SZ/128, NROWS/128), 256, smem1>>>(ffnin_h, nullptr, pwg, gate, NROWS, INTER_SZ, H_SIZE);
    gemm_mma<false><<<dim3(INTER_SZ/128, NROWS/128), 256, smem1>>>(ffnin_h, nullptr, pwu, up, NROWS, INTER_SZ, H_SIZE);
    // act = gelu(gate) * up -> fp16 hi plane
    geglu_kernel<<<8192, 256>>>(gate, up, gact_h, (NROWS * INTER_SZ) / 4);
    // down projection (1-pass fp16, K = INTER)
    gemm_mma<false><<<dim3(H_SIZE/128, NROWS/128), 256, smem1>>>(gact_h, nullptr, pwd, ffnout, NROWS, H_SIZE, INTER_SZ);
    // out = (h2 + rmsnorm(ffnout, w_pff)) * layer_scalar
    rmsnorm_kernel<<<NROWS, 256>>>(ffnout, w_pff, h2, lsc, out, 2);
}

// round 13
// speedup vs baseline: 2.8769x; 1.5963x over previous
#include <cuda_runtime.h>
#include <cuda_fp16.h>
#include <stdint.h>
#include <math.h>

#define H_SIZE 2048
#define INTER_SZ 8192
#define NQ 16
#define NKV 8
#define HD 128
#define SEQ 2048
#define BATCH 2
#define NROWS (BATCH*SEQ)
#define WIN 1024

// ---------------- fp32 scratch ----------------
__device__ float g_q[NROWS*H_SIZE];
__device__ float g_k[NROWS*NKV*HD];
__device__ float g_v[NROWS*NKV*HD];
__device__ float g_attnout[NROWS*H_SIZE];
__device__ float g_h2[NROWS*H_SIZE];
__device__ float g_gate[NROWS*INTER_SZ];
__device__ float g_up[NROWS*INTER_SZ];
__device__ float g_ffnout[NROWS*H_SIZE];

// ---------------- fp16 planes ----------------
__device__ __half g_h_h[NROWS*H_SIZE],      g_h_l[NROWS*H_SIZE];
__device__ __half g_attn_h[NROWS*H_SIZE],   g_attn_l[NROWS*H_SIZE];
__device__ __half g_ffnin_h[NROWS*H_SIZE],  g_ffnin_l[NROWS*H_SIZE];
__device__ __half g_gact_h[NROWS*INTER_SZ];
__device__ __half g_wq[H_SIZE*H_SIZE];
__device__ __half g_wk[NKV*HD*H_SIZE];
__device__ __half g_wv[NKV*HD*H_SIZE];
__device__ __half g_wo[H_SIZE*H_SIZE];
__device__ __half g_wg[INTER_SZ*H_SIZE];
__device__ __half g_wu[INTER_SZ*H_SIZE];
__device__ __half g_wd[H_SIZE*INTER_SZ];

// ---------------- helpers ----------------
__device__ __forceinline__ void split2h(float a, float b, __half* hi, __half* lo) {
    __half ha = __float2half(a), hb = __float2half(b);
    __half la = __float2half(a - __half2float(ha));
    __half lb = __float2half(b - __half2float(hb));
    *(__half2*)hi = __halves2half2(ha, hb);
    *(__half2*)lo = __halves2half2(la, lb);
}

__global__ __launch_bounds__(256) void wsplit_kernel(
    const float* __restrict__ in, __half* __restrict__ out, int n4)
{
    int i = blockIdx.x * blockDim.x + threadIdx.x;
    int stride = gridDim.x * blockDim.x;
    for (; i < n4; i += stride) {
        float4 v = ((const float4*)in)[i];
        *(__half2*)(out + i*4)     = __halves2half2(__float2half(v.x), __float2half(v.y));
        *(__half2*)(out + i*4 + 2) = __halves2half2(__float2half(v.z), __float2half(v.w));
    }
}

// ---------------- RMSNorm fp32 out ----------------
__global__ __launch_bounds__(256) void rmsnorm_kernel(
    const float* __restrict__ in, const float* __restrict__ w,
    const float* __restrict__ res, const float* __restrict__ scal,
    float* __restrict__ out, int mode)
{
    int row = blockIdx.x;
    int t = threadIdx.x;
    const float4* ip = (const float4*)(in + (size_t)row * H_SIZE);
    float4 v0 = ip[t];
    float4 v1 = ip[t + 256];
    float ss = v0.x*v0.x + v0.y*v0.y + v0.z*v0.z + v0.w*v0.w
             + v1.x*v1.x + v1.y*v1.y + v1.z*v1.z + v1.w*v1.w;
    #pragma unroll
    for (int o = 16; o; o >>= 1) ss += __shfl_xor_sync(0xffffffffu, ss, o);
    __shared__ float red[8];
    if ((t & 31) == 0) red[t >> 5] = ss;
    __syncthreads();
    float tot = red[0]+red[1]+red[2]+red[3]+red[4]+red[5]+red[6]+red[7];
    float inv = rsqrtf(tot * (1.0f / H_SIZE) + 1e-6f);

    const float4* w4 = (const float4*)w;
    float4 w0 = w4[t], w1 = w4[t + 256];
    float4 o0, o1;
    o0.x = v0.x*inv*w0.x; o0.y = v0.y*inv*w0.y; o0.z = v0.z*inv*w0.z; o0.w = v0.w*inv*w0.w;
    o1.x = v1.x*inv*w1.x; o1.y = v1.y*inv*w1.y; o1.z = v1.z*inv*w1.z; o1.w = v1.w*inv*w1.w;
    if (mode >= 1) {
        const float4* rp = (const float4*)(res + (size_t)row * H_SIZE);
        float4 r0 = rp[t], r1 = rp[t + 256];
        o0.x += r0.x; o0.y += r0.y; o0.z += r0.z; o0.w += r0.w;
        o1.x += r1.x; o1.y += r1.y; o1.z += r1.z; o1.w += r1.w;
    }
    if (mode == 2) {
        float sc = scal[0];
        o0.x *= sc; o0.y *= sc; o0.z *= sc; o0.w *= sc;
        o1.x *= sc; o1.y *= sc; o1.z *= sc; o1.w *= sc;
    }
    float4* op = (float4*)(out + (size_t)row * H_SIZE);
    op[t] = o0;
    op[t + 256] = o1;
}

// ---------------- RMSNorm -> fp16 hi/lo planes ----------------
__global__ __launch_bounds__(256) void rmsnorm_split_kernel(
    const float* __restrict__ in, const float* __restrict__ w,
    __half* __restrict__ oh, __half* __restrict__ ol)
{
    int row = blockIdx.x;
    int t = threadIdx.x;
    const float4* ip = (const float4*)(in + (size_t)row * H_SIZE);
    float4 v0 = ip[t];
    float4 v1 = ip[t + 256];
    float ss = v0.x*v0.x + v0.y*v0.y + v0.z*v0.z + v0.w*v0.w
             + v1.x*v1.x + v1.y*v1.y + v1.z*v1.z + v1.w*v1.w;
    #pragma unroll
    for (int o = 16; o; o >>= 1) ss += __shfl_xor_sync(0xffffffffu, ss, o);
    __shared__ float red[8];
    if ((t & 31) == 0) red[t >> 5] = ss;
    __syncthreads();
    float tot = red[0]+red[1]+red[2]+red[3]+red[4]+red[5]+red[6]+red[7];
    float inv = rsqrtf(tot * (1.0f / H_SIZE) + 1e-6f);

    const float4* w4 = (const float4*)w;
    float4 w0 = w4[t], w1 = w4[t + 256];
    size_t base = (size_t)row * H_SIZE;
    split2h(v0.x*inv*w0.x, v0.y*inv*w0.y, oh + base + t*4,     ol + base + t*4);
    split2h(v0.z*inv*w0.z, v0.w*inv*w0.w, oh + base + t*4 + 2, ol + base + t*4 + 2);
    split2h(v1.x*inv*w1.x, v1.y*inv*w1.y, oh + base + 1024 + t*4,     ol + base + 1024 + t*4);
    split2h(v1.z*inv*w1.z, v1.w*inv*w1.w, oh + base + 1024 + t*4 + 2, ol + base + 1024 + t*4 + 2);
}

// ---------------- MMA helpers ----------------
__device__ __forceinline__ void mma_fp16(float* c, const uint32_t* a, const uint32_t* b) {
    asm volatile(
        "mma.sync.aligned.m16n8k16.row.col.f32.f16.f16.f32 "
        "{%0,%1,%2,%3}, {%4,%5,%6,%7}, {%8,%9}, {%0,%1,%2,%3};\n"
        : "+f"(c[0]), "+f"(c[1]), "+f"(c[2]), "+f"(c[3])
        : "r"(a[0]), "r"(a[1]), "r"(a[2]), "r"(a[3]), "r"(b[0]), "r"(b[1]));
}

__device__ __forceinline__ void ldsm_x4(uint32_t* r, uint32_t addr) {
    asm volatile("ldmatrix.sync.aligned.m8n8.x4.shared.b16 {%0,%1,%2,%3}, [%4];"
        : "=r"(r[0]), "=r"(r[1]), "=r"(r[2]), "=r"(r[3]) : "r"(addr));
}

__device__ __forceinline__ void ldsm_x4_t(uint32_t* r, uint32_t addr) {
    asm volatile("ldmatrix.sync.aligned.m8n8.x4.trans.shared.b16 {%0,%1,%2,%3}, [%4];"
        : "=r"(r[0]), "=r"(r[1]), "=r"(r[2]), "=r"(r[3]) : "r"(addr));
}

__device__ __forceinline__ void cp16(uint32_t dst, const void* src) {
    asm volatile("cp.async.cg.shared.global [%0], [%1], 16;\n" :: "r"(dst), "l"(src));
}

// ---------------- Tensor-core GEMM on fp16 planes (unchanged from R12) -------------------
#define LDSK 40
#define PLANE_H (128*LDSK)

template<bool TWOPASS>
__global__ __launch_bounds__(256, 2) void gemm_mma(
    const __half* __restrict__ Agh, const __half* __restrict__ Agl,
    const __half* __restrict__ Bgh,
    float* __restrict__ C, int M, int N, int K)
{
    extern __shared__ __align__(16) __half smp[];
    const int NPL = TWOPASS ? 3 : 2;
    const int STAGE_HH = NPL * PLANE_H;

    const int tid  = threadIdx.x;
    const int warp = tid >> 5, lane = tid & 31;
    const int wm = warp >> 1, wn = warp & 1;
    const int rowA = blockIdx.y * 128;
    const int colB = blockIdx.x * 128;

    const uint32_t smb = (uint32_t)__cvta_generic_to_shared(smp);
    const uint32_t a_off = (uint32_t)(((wm*32 + (lane & 15)) * LDSK + ((lane >> 4) * 8)) * 2);
    const uint32_t b_off = (uint32_t)(((wn*64 + ((lane >> 4) * 8) + (lane & 7)) * LDSK
                                       + (((lane >> 3) & 1) * 8)) * 2);

    float acc[2][8][4];
    #pragma unroll
    for (int i = 0; i < 2; i++)
        #pragma unroll
        for (int j = 0; j < 8; j++)
            #pragma unroll
            for (int q = 0; q < 4; q++) acc[i][j][q] = 0.f;

    #define CP_STAGE(s, k0)                                                        \
    {                                                                              \
        _Pragma("unroll")                                                          \
        for (int i = 0; i < 2*NPL; i++) {                                          \
            int cidx = tid + 256 * i;                                              \
            int plane = cidx >> 9;                                                 \
            int cc = cidx & 511;                                                   \
            int row = cc >> 2;                                                     \
            int ch = cc & 3;                                                       \
            const __half* src =                                                    \
                (plane == 0) ? Agh + (size_t)(rowA + row) * K :                    \
                (plane == 1) ? Bgh + (size_t)(colB + row) * K :                    \
                               Agl + (size_t)(rowA + row) * K;                     \
            uint32_t dst = smb +                                                   \
                (uint32_t)(((s) * STAGE_HH + plane * PLANE_H + row * LDSK + ch * 8) * 2); \
            cp16(dst, src + (k0) + ch * 8);                                        \
        }                                                                          \
        asm volatile("cp.async.commit_group;\n" ::: "memory");                     \
    }

    const int NC = K >> 5;
    CP_STAGE(0, 0);
    for (int c = 0; c < NC; c++) {
        int s = c & 1;
        if (c + 1 < NC) {
            CP_STAGE(s ^ 1, (c + 1) * 32);
            asm volatile("cp.async.wait_group 1;\n" ::: "memory");
        } else {
            asm volatile("cp.async.wait_group 0;\n" ::: "memory");
        }
        __syncthreads();

        const uint32_t ah_b = smb + (uint32_t)((s * STAGE_HH) * 2);
        const uint32_t bh_b = ah_b + (uint32_t)(PLANE_H * 2);
        const uint32_t al_b = bh_b + (uint32_t)(PLANE_H * 2);

        #pragma unroll
        for (int kk = 0; kk < 32; kk += 16) {
            const uint32_t kko = kk * 2;
            uint32_t fa[2][4];
            uint32_t fb[4][4];
            #pragma unroll
            for (int tm = 0; tm < 2; tm++)
                ldsm_x4(fa[tm], ah_b + a_off + (uint32_t)(tm * 16 * LDSK * 2) + kko);
            #pragma unroll
            for (int p = 0; p < 4; p++)
                ldsm_x4(fb[p], bh_b + b_off + (uint32_t)(p * 16 * LDSK * 2) + kko);
            #pragma unroll
            for (int tm = 0; tm < 2; tm++)
                #pragma unroll
                for (int tn = 0; tn < 8; tn++)
                    mma_fp16(acc[tm][tn], fa[tm], &fb[tn >> 1][(tn & 1) * 2]);
            if (TWOPASS) {
                uint32_t fal[2][4];
                #pragma unroll
                for (int tm = 0; tm < 2; tm++)
                    ldsm_x4(fal[tm], al_b + a_off + (uint32_t)(tm * 16 * LDSK * 2) + kko);
                #pragma unroll
                for (int tm = 0; tm < 2; tm++)
                    #pragma unroll
                    for (int tn = 0; tn < 8; tn++)
                        mma_fp16(acc[tm][tn], fal[tm], &fb[tn >> 1][(tn & 1) * 2]);
            }
        }
        __syncthreads();
    }

    const int g = lane >> 2, t4 = lane & 3;
    #pragma unroll
    for (int tm = 0; tm < 2; tm++) {
        #pragma unroll
        for (int tn = 0; tn < 8; tn++) {
            int row = blockIdx.y*128 + wm*32 + tm*16 + g;
            int col = blockIdx.x*128 + wn*64 + tn*8 + 2*t4;
            float2 c0 = {acc[tm][tn][0], acc[tm][tn][1]};
            float2 c1 = {acc[tm][tn][2], acc[tm][tn][3]};
            *(float2*)(C + (size_t)row * N + col)       = c0;
            *(float2*)(C + (size_t)(row + 8) * N + col) = c1;
        }
    }
}

// ---------------- RoPE ----------------
__global__ __launch_bounds__(256) void rope_kernel(float* __restrict__ buf, int nheads)
{
    int row = blockIdx.x;
    int s = row & (SEQ - 1);
    float* base = buf + (size_t)row * nheads * HD;
    for (int idx = threadIdx.x; idx < nheads * 64; idx += blockDim.x) {
        int hh = idx >> 6;
        int d = idx & 63;
        float inv = expf(-((float)d * (1.0f / 64.0f)) * 9.210340371976184f);
        float fr = (float)s * inv;
        float sn = sinf(fr), cs = cosf(fr);
        float* p = base + hh * HD + d;
        float x1 = p[0], x2 = p[64];
        p[0]  = x1 * cs - x2 * sn;
        p[64] = x2 * cs + x1 * sn;
    }
}

// ---------------- Tensor-core sliding-window GQA flash attention -------------------------
// i-block 128, j-tile 32, 8 warps x 16 rows. QK: 3-pass split fp16; softmax fp32 in
// fragments; PV: 3-pass (Ph+Pl)x(Vh+Vl minus lo*lo), V via ldmatrix.trans.
// Output written directly as fp16 hi/lo planes.

#define ASTR 136   // row stride in halfs for Q/K/V tiles (d=128 + 8 pad)
#define ATTN2_SMEM ((128*ASTR*2 + 32*ASTR*4) * 2)

__global__ __launch_bounds__(256) void attn_mma_kernel(
    const float* __restrict__ Q, const float* __restrict__ K,
    const float* __restrict__ V, __half* __restrict__ Oh,
    __half* __restrict__ Ol)
{
    extern __shared__ __align__(16) __half asmem[];
    __half* Qh = asmem;
    __half* Ql = Qh + 128*ASTR;
    __half* Kh = Ql + 128*ASTR;
    __half* Kl = Kh + 32*ASTR;
    __half* Vh = Kl + 32*ASTR;
    __half* Vl = Vh + 32*ASTR;

    const int i0 = blockIdx.x * 128;
    const int h  = blockIdx.y;
    const int b  = blockIdx.z;
    const int hk = h >> 1;
    const int tid = threadIdx.x;
    const int w = tid >> 5, lane = tid & 31;
    const int g = lane >> 2, t = lane & 3;
    const float scale = 0.08838834764831845f;

    const uint32_t qh_b = (uint32_t)__cvta_generic_to_shared(Qh);
    const uint32_t ql_b = (uint32_t)__cvta_generic_to_shared(Ql);
    const uint32_t kh_b = (uint32_t)__cvta_generic_to_shared(Kh);
    const uint32_t kl_b = (uint32_t)__cvta_generic_to_shared(Kl);
    const uint32_t vh_b = (uint32_t)__cvta_generic_to_shared(Vh);
    const uint32_t vl_b = (uint32_t)__cvta_generic_to_shared(Vl);

    // fragment lane offsets (bytes)
    const uint32_t a_off  = (uint32_t)(((w*16 + (lane & 15)) * ASTR + ((lane >> 4) * 8)) * 2);
    const uint32_t kb_off = (uint32_t)((((lane >> 4) * 8 + (lane & 7)) * ASTR
                                        + ((lane >> 3) & 1) * 8) * 2);
    const uint32_t vt_off = (uint32_t)((((lane & 7) + 8 * ((lane >> 3) & 1)) * ASTR
                                        + 8 * (lane >> 4)) * 2);

    // stage Q (128 x 128), prescaled, split hi/lo
    #pragma unroll
    for (int it = 0; it < 16; it++) {
        int idx = tid + 256 * it;
        int row = idx >> 5, d4 = idx & 31;
        float4 qv = *(const float4*)(Q + (size_t)(b * SEQ + i0 + row) * H_SIZE + h * HD + d4 * 4);
        int off = row * ASTR + d4 * 4;
        split2h(qv.x * scale, qv.y * scale, Qh + off,     Ql + off);
        split2h(qv.z * scale, qv.w * scale, Qh + off + 2, Ql + off + 2);
    }

    float accO[16][4];
    #pragma unroll
    for (int i = 0; i < 16; i++)
        #pragma unroll
        for (int q = 0; q < 4; q++) accO[i][q] = 0.f;
    float m0 = -1e30f, m1 = -1e30f, l0 = 0.f, l1 = 0.f;

    int jstart = i0 - (WIN - 1);
    if (jstart < 0) jstart = 0;
    jstart &= ~31;
    const int r0 = i0 + w*16 + g;
    const int r1 = r0 + 8;

    for (int j0 = jstart; j0 < i0 + 128; j0 += 32) {
        __syncthreads();
        #pragma unroll
        for (int it = 0; it < 4; it++) {
            int idx = tid + 256 * it;
            int row = idx >> 5, d4 = idx & 31;
            size_t goff = (size_t)(b * SEQ + j0 + row) * (NKV * HD) + hk * HD + d4 * 4;
            float4 kv = *(const float4*)(K + goff);
            float4 vv = *(const float4*)(V + goff);
            int off = row * ASTR + d4 * 4;
            split2h(kv.x, kv.y, Kh + off,     Kl + off);
            split2h(kv.z, kv.w, Kh + off + 2, Kl + off + 2);
            split2h(vv.x, vv.y, Vh + off,     Vl + off);
            split2h(vv.z, vv.w, Vh + off + 2, Vl + off + 2);
        }
        __syncthreads();

        // ---- QK^T: S[16 x 32] per warp, 3 passes ----
        float accS[4][4];
        #pragma unroll
        for (int nt = 0; nt < 4; nt++)
            #pragma unroll
            for (int q = 0; q < 4; q++) accS[nt][q] = 0.f;

        #pragma unroll
        for (int ks = 0; ks < 8; ks++) {
            const uint32_t kko = (uint32_t)(ks * 32);
            uint32_t fa[4], fal[4], fb[2][4], fbl[2][4];
            ldsm_x4(fa,  qh_b + a_off + kko);
            ldsm_x4(fal, ql_b + a_off + kko);
            ldsm_x4(fb[0],  kh_b + kb_off + kko);
            ldsm_x4(fb[1],  kh_b + kb_off + (uint32_t)(16 * ASTR * 2) + kko);
            ldsm_x4(fbl[0], kl_b + kb_off + kko);
            ldsm_x4(fbl[1], kl_b + kb_off + (uint32_t)(16 * ASTR * 2) + kko);
            #pragma unroll
            for (int nt = 0; nt < 4; nt++) {
                mma_fp16(accS[nt], fa,  &fb[nt >> 1][(nt & 1) * 2]);
                mma_fp16(accS[nt], fal, &fb[nt >> 1][(nt & 1) * 2]);
                mma_fp16(accS[nt], fa,  &fbl[nt >> 1][(nt & 1) * 2]);
            }
        }

        // ---- mask ----
        #pragma unroll
        for (int nt = 0; nt < 4; nt++) {
            int jc0 = j0 + nt * 8 + 2 * t;
            int jc1 = jc0 + 1;
            accS[nt][0] = (jc0 <= r0 && r0 - jc0 < WIN) ? accS[nt][0] : -1e30f;
            accS[nt][1] = (jc1 <= r0 && r0 - jc1 < WIN) ? accS[nt][1] : -1e30f;
            accS[nt][2] = (jc0 <= r1 && r1 - jc0 < WIN) ? accS[nt][2] : -1e30f;
            accS[nt][3] = (jc1 <= r1 && r1 - jc1 < WIN) ? accS[nt][3] : -1e30f;
        }

        // ---- online softmax stats ----
        float mt0 = m0, mt1 = m1;
        #pragma unroll
        for (int nt = 0; nt < 4; nt++) {
            mt0 = fmaxf(mt0, fmaxf(accS[nt][0], accS[nt][1]));
            mt1 = fmaxf(mt1, fmaxf(accS[nt][2], accS[nt][3]));
        }
        mt0 = fmaxf(mt0, __shfl_xor_sync(0xffffffffu, mt0, 1));
        mt0 = fmaxf(mt0, __shfl_xor_sync(0xffffffffu, mt0, 2));
        mt1 = fmaxf(mt1, __shfl_xor_sync(0xffffffffu, mt1, 1));
        mt1 = fmaxf(mt1, __shfl_xor_sync(0xffffffffu, mt1, 2));
        float alpha0 = __expf(m0 - mt0);
        float alpha1 = __expf(m1 - mt1);
        m0 = mt0; m1 = mt1;

        float p[4][4];
        float ps0 = 0.f, ps1 = 0.f;
        #pragma unroll
        for (int nt = 0; nt < 4; nt++) {
            p[nt][0] = __expf(accS[nt][0] - mt0);
            p[nt][1] = __expf(accS[nt][1] - mt0);
            p[nt][2] = __expf(accS[nt][2] - mt1);
            p[nt][3] = __expf(accS[nt][3] - mt1);
            ps0 += p[nt][0] + p[nt][1];
            ps1 += p[nt][2] + p[nt][3];
        }
        ps0 += __shfl_xor_sync(0xffffffffu, ps0, 1);
        ps0 += __shfl_xor_sync(0xffffffffu, ps0, 2);
        ps1 += __shfl_xor_sync(0xffffffffu, ps1, 1);
        ps1 += __shfl_xor_sync(0xffffffffu, ps1, 2);
        l0 = l0 * alpha0 + ps0;
        l1 = l1 * alpha1 + ps1;

        #pragma unroll
        for (int i = 0; i < 16; i++) {
            accO[i][0] *= alpha0; accO[i][1] *= alpha0;
            accO[i][2] *= alpha1; accO[i][3] *= alpha1;
        }

        // ---- P fragments (register repack, hi/lo split) ----
        uint32_t ph[2][4], pl[2][4];
        #pragma unroll
        for (int kb = 0; kb < 2; kb++) {
            #pragma unroll
            for (int q = 0; q < 4; q++) {
                int nt = 2*kb + (q >> 1);
                int e0 = (q & 1) * 2;      // 0: row g cols; 2: row g+8 cols
                float v0 = p[nt][e0], v1 = p[nt][e0 + 1];
                __half h0 = __float2half(v0), h1 = __float2half(v1);
                __half lo0 = __float2half(v0 - __half2float(h0));
                __half lo1 = __float2half(v1 - __half2float(h1));
                // a-frag order: [0]=(g,k0-7) [1]=(g+8,k0-7) [2]=(g,k8-15) [3]=(g+8,k8-15)
                int ridx = (q >> 1) * 2 + (q & 1);
                __half2 hh = __halves2half2(h0, h1);
                __half2 ll = __halves2half2(lo0, lo1);
                ph[kb][ridx] = *(uint32_t*)&hh;
                pl[kb][ridx] = *(uint32_t*)&ll;
            }
        }

        // ---- PV: O[16 x 128] per warp, 3 passes, V via ldmatrix.trans ----
        #pragma unroll
        for (int kb = 0; kb < 2; kb++) {
            #pragma unroll
            for (int dg = 0; dg < 8; dg++) {
                uint32_t vb[4], vbl[4];
                uint32_t voff = vt_off + (uint32_t)((kb * 16 * ASTR + dg * 16) * 2);
                ldsm_x4_t(vb,  vh_b + voff);
                ldsm_x4_t(vbl, vl_b + voff);
                mma_fp16(accO[2*dg],     ph[kb], &vb[0]);
                mma_fp16(accO[2*dg],     pl[kb], &vb[0]);
                mma_fp16(accO[2*dg],     ph[kb], &vbl[0]);
                mma_fp16(accO[2*dg + 1], ph[kb], &vb[2]);
                mma_fp16(accO[2*dg + 1], pl[kb], &vb[2]);
                mma_fp16(accO[2*dg + 1], ph[kb], &vbl[2]);
            }
        }
    }

    // ---- epilogue: normalize + write fp16 hi/lo planes ----
    float li0 = 1.0f / l0, li1 = 1.0f / l1;
    size_t ob0 = (size_t)(b * SEQ + i0 + w*16 + g) * H_SIZE + h * HD;
    size_t ob1 = ob0 + (size_t)8 * H_SIZE;
    #pragma unroll
    for (int nt = 0; nt < 16; nt++) {
        int dim = nt * 8 + 2 * t;
        split2h(accO[nt][0] * li0, accO[nt][1] * li0, Oh + ob0 + dim, Ol + ob0 + dim);
        split2h(accO[nt][2] * li1, accO[nt][3] * li1, Oh + ob1 + dim, Ol + ob1 + dim);
    }
}

// ---------------- GeGLU: fp16 hi plane out ----------------
__device__ __forceinline__ float gelu_exact(float x) {
    return 0.5f * x * (1.0f + erff(x * 0.7071067811865476f));
}
__global__ __launch_bounds__(256) void geglu_kernel(
    const float* __restrict__ g, const float* __restrict__ u,
    __half* __restrict__ oh, int n4)
{
    int i = blockIdx.x * blockDim.x + threadIdx.x;
    int stride = gridDim.x * blockDim.x;
    for (; i < n4; i += stride) {
        float4 gv = ((const float4*)g)[i];
        float4 uv = ((const float4*)u)[i];
        float r0 = gelu_exact(gv.x) * uv.x;
        float r1 = gelu_exact(gv.y) * uv.y;
        float r2 = gelu_exact(gv.z) * uv.z;
        float r3 = gelu_exact(gv.w) * uv.w;
        *(__half2*)(oh + i*4)     = __halves2half2(__float2half(r0), __float2half(r1));
        *(__half2*)(oh + i*4 + 2) = __halves2half2(__float2half(r2), __float2half(r3));
    }
}

// ---------------- launch ----------------
extern "C" void kernel_launch(void* const* d_in, const int* in_sizes, int n_in,
                              void* d_out, int out_size)
{
    const float* x    = (const float*)d_in[0];
    const float* wq   = (const float*)d_in[1];
    const float* wk   = (const float*)d_in[2];
    const float* wv   = (const float*)d_in[3];
    const float* wo   = (const float*)d_in[4];
    const float* w_in = (const float*)d_in[5];
    const float* w_pa = (const float*)d_in[6];
    const float* w_pf = (const float*)d_in[7];
    const float* w_pff= (const float*)d_in[8];
    const float* wg   = (const float*)d_in[9];
    const float* wu   = (const float*)d_in[10];
    const float* wd   = (const float*)d_in[11];
    const float* lsc  = (const float*)d_in[12];
    float* out = (float*)d_out;

    float *q, *k, *v, *attnout, *h2, *gate, *up, *ffnout;
    cudaGetSymbolAddress((void**)&q,       g_q);
    cudaGetSymbolAddress((void**)&k,       g_k);
    cudaGetSymbolAddress((void**)&v,       g_v);
    cudaGetSymbolAddress((void**)&attnout, g_attnout);
    cudaGetSymbolAddress((void**)&h2,      g_h2);
    cudaGetSymbolAddress((void**)&gate,    g_gate);
    cudaGetSymbolAddress((void**)&up,      g_up);
    cudaGetSymbolAddress((void**)&ffnout,  g_ffnout);

    __half *h_h, *h_l, *attn_h, *attn_l, *ffnin_h, *ffnin_l, *gact_h;
    __half *pwq, *pwk, *pwv, *pwo, *pwg, *pwu, *pwd;
    cudaGetSymbolAddress((void**)&h_h, g_h_h);         cudaGetSymbolAddress((void**)&h_l, g_h_l);
    cudaGetSymbolAddress((void**)&attn_h, g_attn_h);   cudaGetSymbolAddress((void**)&attn_l, g_attn_l);
    cudaGetSymbolAddress((void**)&ffnin_h, g_ffnin_h); cudaGetSymbolAddress((void**)&ffnin_l, g_ffnin_l);
    cudaGetSymbolAddress((void**)&gact_h, g_gact_h);
    cudaGetSymbolAddress((void**)&pwq, g_wq);
    cudaGetSymbolAddress((void**)&pwk, g_wk);
    cudaGetSymbolAddress((void**)&pwv, g_wv);
    cudaGetSymbolAddress((void**)&pwo, g_wo);
    cudaGetSymbolAddress((void**)&pwg, g_wg);
    cudaGetSymbolAddress((void**)&pwu, g_wu);
    cudaGetSymbolAddress((void**)&pwd, g_wd);

    const int smem2 = 2 * 3 * PLANE_H * 2;
    const int smem1 = 2 * 2 * PLANE_H * 2;
    cudaFuncSetAttribute(attn_mma_kernel, cudaFuncAttributeMaxDynamicSharedMemorySize, ATTN2_SMEM);
    cudaFuncSetAttribute(gemm_mma<true>,  cudaFuncAttributeMaxDynamicSharedMemorySize, smem2);
    cudaFuncSetAttribute(gemm_mma<false>, cudaFuncAttributeMaxDynamicSharedMemorySize, smem1);

    // weight planes (fp16)
    wsplit_kernel<<<2048, 256>>>(wq, pwq, H_SIZE*H_SIZE/4);
    wsplit_kernel<<<1024, 256>>>(wk, pwk, NKV*HD*H_SIZE/4);
    wsplit_kernel<<<1024, 256>>>(wv, pwv, NKV*HD*H_SIZE/4);
    wsplit_kernel<<<2048, 256>>>(wo, pwo, H_SIZE*H_SIZE/4);
    wsplit_kernel<<<4096, 256>>>(wg, pwg, INTER_SZ*H_SIZE/4);
    wsplit_kernel<<<4096, 256>>>(wu, pwu, INTER_SZ*H_SIZE/4);
    wsplit_kernel<<<4096, 256>>>(wd, pwd, H_SIZE*INTER_SZ/4);

    // h = rmsnorm(x, w_in) -> fp16 hi/lo planes
    rmsnorm_split_kernel<<<NROWS, 256>>>(x, w_in, h_h, h_l);
    // QKV (2-pass)
    gemm_mma<true><<<dim3(H_SIZE/128, NROWS/128), 256, smem2>>>(h_h, h_l, pwq, q, NROWS, H_SIZE, H_SIZE);
    gemm_mma<true><<<dim3((NKV*HD)/128, NROWS/128), 256, smem2>>>(h_h, h_l, pwk, k, NROWS, NKV*HD, H_SIZE);
    gemm_mma<true><<<dim3((NKV*HD)/128, NROWS/128), 256, smem2>>>(h_h, h_l, pwv, v, NROWS, NKV*HD, H_SIZE);
    // RoPE
    rope_kernel<<<NROWS, 256>>>(q, NQ);
    rope_kernel<<<NROWS, 256>>>(k, NKV);
    // tensor-core attention -> fp16 planes
    attn_mma_kernel<<<dim3(SEQ/128, NQ, BATCH), 256, ATTN2_SMEM>>>(q, k, v, attn_h, attn_l);
    // WO (2-pass)
    gemm_mma<true><<<dim3(H_SIZE/128, NROWS/128), 256, smem2>>>(attn_h, attn_l, pwo, attnout, NROWS, H_SIZE, H_SIZE);
    // h2 = x + rmsnorm(attnout, w_pa)
    rmsnorm_kernel<<<NROWS, 256>>>(attnout, w_pa, x, nullptr, h2, 1);
    // ffn_in = rmsnorm(h2, w_pf) -> fp16 planes
    rmsnorm_split_kernel<<<NROWS, 256>>>(h2, w_pf, ffnin_h, ffnin_l);
    // gate/up GEMMs (1-pass fp16)
    gemm_mma<false><<<dim3(INTER_SZ/128, NROWS/128), 256, smem1>>>(ffnin_h, nullptr, pwg, gate, NROWS, INTER_SZ, H_SIZE);
    gemm_mma<false><<<dim3(INTER_SZ/128, NROWS/128), 256, smem1>>>(ffnin_h, nullptr, pwu, up, NROWS, INTER_SZ, H_SIZE);
    // act = gelu(gate) * up -> fp16 hi plane
    geglu_kernel<<<8192, 256>>>(gate, up, gact_h, (NROWS * INTER_SZ) / 4);
    // down projection (1-pass fp16, K = INTER)
    gemm_mma<false><<<dim3(H_SIZE/128, NROWS/128), 256, smem1>>>(gact_h, nullptr, pwd, ffnout, NROWS, H_SIZE, INTER_SZ);
    // out = (h2 + rmsnorm(ffnout, w_pff)) * layer_scalar
    rmsnorm_kernel<<<NROWS, 256>>>(ffnout, w_pff, h2, lsc, out, 2);
}